// round 6
// baseline (speedup 1.0000x reference)
#include <cuda_runtime.h>
#include <math.h>
#include <stdint.h>

#define TB 8
#define TS 4096
#define TD 512
#define TH 2048
#define TE 8
#define TP 16
#define NTOK (TB*TS)          /* 32768 tokens */

/* ---------------- device state ---------------- */
__device__ int    g_counts[TE];
__device__ int    g_base[TE];
__device__ int    g_tok[TE * NTOK];
__device__ float  g_gate[TE * NTOK];
__device__ double g_zsum;
__device__ double g_psum[TE];
__device__ float  g_H[(size_t)2 * NTOK * TH];     /* tf32-rounded H */
__device__ float  g_xt[(size_t)NTOK * TD];        /* tf32-rounded x */
__device__ float  g_w1t[(size_t)TE * TH * TD];    /* W1^T: [e][h][d] (K-major) */
__device__ float  g_w3t[(size_t)TE * TH * TD];    /* W3^T: [e][h][d] */
__device__ float  g_w2t[(size_t)TE * TD * TH];    /* W2^T: [e][d][h] */

/* ---------------- helpers ---------------- */
__device__ __forceinline__ unsigned tf32_of(float f) {
    unsigned u; asm("cvt.rna.tf32.f32 %0, %1;" : "=r"(u) : "f"(f)); return u;
}
__device__ __forceinline__ float tf32f(float f) { return __uint_as_float(tf32_of(f)); }

__device__ __forceinline__ void mma_tf32(
    float& c0, float& c1, float& c2, float& c3,
    unsigned a0, unsigned a1, unsigned a2, unsigned a3,
    unsigned b0, unsigned b1)
{
    asm volatile(
        "mma.sync.aligned.m16n8k8.row.col.f32.tf32.tf32.f32 "
        "{%0,%1,%2,%3}, {%4,%5,%6,%7}, {%8,%9}, {%0,%1,%2,%3};"
        : "+f"(c0), "+f"(c1), "+f"(c2), "+f"(c3)
        : "r"(a0), "r"(a1), "r"(a2), "r"(a3), "r"(b0), "r"(b1));
}

#define CP16(dst, src) \
    asm volatile("cp.async.cg.shared.global [%0], [%1], 16;" :: "r"(dst), "l"(src))
#define CP_COMMIT() asm volatile("cp.async.commit_group;")
#define CP_WAIT1()  asm volatile("cp.async.wait_group 1;")
#define CP_WAIT0()  asm volatile("cp.async.wait_group 0;")

__device__ __forceinline__ unsigned sptr(const void* p) {
    return (unsigned)__cvta_generic_to_shared(p);
}
__device__ __forceinline__ uint32_t swz128(uint32_t byte_off) {
    return byte_off ^ ((byte_off >> 3) & 0x70);
}

#define HDR 2048
#define F_STG 49152
#define FFN_SMEM (HDR + 3 * F_STG)   /* 149504 B */

/* ---------------- prep: transpose+round weights, round x, zero state ---------------- */
__global__ __launch_bounds__(256) void prep_kernel(
    const float* __restrict__ x, const float* __restrict__ W1,
    const float* __restrict__ W2, const float* __restrict__ W3)
{
    const int m = blockIdx.z;
    const int tx = threadIdx.x, ty = threadIdx.y;
    if (m < 24) {
        const float* src; float* dst; int R, C;
        if (m < 8)       { src = W1 + (size_t)m * TD * TH;        dst = g_w1t + (size_t)m * TH * TD;        R = TD; C = TH; }
        else if (m < 16) { src = W3 + (size_t)(m - 8) * TD * TH;  dst = g_w3t + (size_t)(m - 8) * TH * TD;  R = TD; C = TH; }
        else             { src = W2 + (size_t)(m - 16) * TH * TD; dst = g_w2t + (size_t)(m - 16) * TD * TH; R = TH; C = TD; }
        const int bx = blockIdx.x, by = blockIdx.y;
        if (bx * 32 >= C || by * 32 >= R) return;
        __shared__ float t[32][33];
        #pragma unroll
        for (int i = 0; i < 4; ++i)
            t[ty + 8 * i][tx] = src[(size_t)(by * 32 + ty + 8 * i) * C + bx * 32 + tx];
        __syncthreads();
        #pragma unroll
        for (int i = 0; i < 4; ++i)
            dst[(size_t)(bx * 32 + ty + 8 * i) * R + by * 32 + tx] = tf32f(t[tx][ty + 8 * i]);
    } else {
        const int tid = ty * 32 + tx;
        const size_t nb = (size_t)blockIdx.y * 64 + blockIdx.x;   /* 0..4095 */
        if (nb == 0 && tid < TE) { g_counts[tid] = 0; g_psum[tid] = 0.0; if (tid == 0) g_zsum = 0.0; }
        const size_t NX = (size_t)NTOK * TD / 4;
        const size_t stride = (size_t)4096 * 256;
        for (size_t i = nb * 256 + tid; i < NX; i += stride) {
            float4 v = ((const float4*)x)[i];
            v.x = tf32f(v.x); v.y = tf32f(v.y); v.z = tf32f(v.z); v.w = tf32f(v.w);
            ((float4*)g_xt)[i] = v;
        }
    }
}

/* ---------------- router (unchanged, passing) ---------------- */
__global__ __launch_bounds__(256) void router_kernel(
    const float* __restrict__ x, const int* __restrict__ pid,
    const float* __restrict__ Wr, const float* __restrict__ Wp)
{
    __shared__ float sWrT[TE * TD];
    __shared__ float sPsum[TE];
    __shared__ float sZsum;
    __shared__ int   sCnt[TE];
    __shared__ int   sGbase[TE];
    __shared__ unsigned char sE[256];
    __shared__ short sSlot[256];
    __shared__ float sG[256];

    const int tid = threadIdx.x;
    for (int idx = tid; idx < TD * TE; idx += 256) {
        int d = idx >> 3, e = idx & 7;
        sWrT[e * TD + d] = Wr[idx];
    }
    if (tid < TE) { sPsum[tid] = 0.f; sCnt[tid] = 0; }
    if (tid == 0) sZsum = 0.f;
    __syncthreads();

    const int warp = tid >> 5, lane = tid & 31;
    const int tok0 = blockIdx.x * 128 + warp * 16;

    for (int tt = 0; tt < 16; ++tt) {
        const int t = tok0 + tt;
        float acc[TE];
        #pragma unroll
        for (int e = 0; e < TE; ++e) acc[e] = 0.f;
        const float* xr = x + (size_t)t * TD;
        for (int i = lane; i < TD; i += 32) {
            float xv = xr[i];
            #pragma unroll
            for (int e = 0; e < TE; ++e)
                acc[e] = fmaf(xv, sWrT[e * TD + i], acc[e]);
        }
        #pragma unroll
        for (int off = 16; off >= 1; off >>= 1) {
            #pragma unroll
            for (int e = 0; e < TE; ++e)
                acc[e] += __shfl_down_sync(0xffffffffu, acc[e], off);
        }
        if (lane == 0) {
            const int b = t / TS;
            const int p = pid[b];
            float l[TE];
            float zs = 0.f, mx = -1e30f;
            #pragma unroll
            for (int e = 0; e < TE; ++e) {
                l[e] = acc[e] + Wp[p * TE + e];
                zs += l[e] * l[e];
                mx = fmaxf(mx, l[e]);
            }
            atomicAdd(&sZsum, zs);
            float s = 0.f, pr[TE];
            #pragma unroll
            for (int e = 0; e < TE; ++e) { pr[e] = expf(l[e] - mx); s += pr[e]; }
            const float inv = 1.f / s;
            #pragma unroll
            for (int e = 0; e < TE; ++e) atomicAdd(&sPsum[e], pr[e] * inv);
            int i0 = 0;
            #pragma unroll
            for (int e = 1; e < TE; ++e) if (l[e] > l[i0]) i0 = e;
            int i1 = (i0 == 0) ? 1 : 0;
            #pragma unroll
            for (int e = 0; e < TE; ++e) if (e != i0 && l[e] > l[i1]) i1 = e;
            const float e1 = expf(l[i1] - l[i0]);
            const float g0 = 1.f / (1.f + e1);
            const float g1 = e1 * g0;
            const int s0 = atomicAdd(&sCnt[i0], 1);
            const int s1 = atomicAdd(&sCnt[i1], 1);
            const int loc = (warp * 16 + tt) * 2;
            sE[loc]     = (unsigned char)i0; sSlot[loc]     = (short)s0; sG[loc]     = g0;
            sE[loc + 1] = (unsigned char)i1; sSlot[loc + 1] = (short)s1; sG[loc + 1] = g1;
        }
    }
    __syncthreads();
    if (tid < TE) {
        sGbase[tid] = atomicAdd(&g_counts[tid], sCnt[tid]);
        atomicAdd(&g_psum[tid], (double)sPsum[tid]);
    }
    if (tid == 0) atomicAdd(&g_zsum, (double)sZsum);
    __syncthreads();
    {
        const int e = sE[tid];
        const int pos = sGbase[e] + sSlot[tid];
        const int t = blockIdx.x * 128 + (tid >> 1);
        g_tok[e * NTOK + pos]  = t;
        g_gate[e * NTOK + pos] = sG[tid];
    }
}

__global__ void prefix_kernel() {
    if (threadIdx.x == 0) {
        int s = 0;
        for (int e = 0; e < TE; ++e) { g_base[e] = s; s += g_counts[e]; }
    }
}

/* ================= FFN stage 1: H = (X@W1) * silu(X@W3) =================
   CTA tile 128(M) x 128(N), both gemms. BK=32, 16 iters, 3-stage cp.async.
   8 warps = 2m x 4n; warp tile 64x32 per gemm -> m_frags=4, n_frags=4.
   Stage smem 48KB: A[128][32] @0, B1[128n][32k] @16K, B3 @32K; all SW128 swizzled. */
__global__ __launch_bounds__(256, 1) void ffn1_kernel()
{
    const int e   = blockIdx.z;
    const int cnt = g_counts[e];
    const int m0  = blockIdx.x * 128;
    if (m0 >= cnt) return;
    const int n0   = blockIdx.y * 128;
    const int base = g_base[e];

    extern __shared__ char smc[];
    int* stok = (int*)smc;

    const int tid = threadIdx.x;
    if (tid < 128) {
        const int r = m0 + tid;
        stok[tid] = (r < cnt) ? g_tok[e * NTOK + r] : g_tok[e * NTOK];
    }
    __syncthreads();

    const float* W1e = g_w1t + (size_t)e * TH * TD;
    const float* W3e = g_w3t + (size_t)e * TH * TD;

    const int warp = tid >> 5, lane = tid & 31;
    const int warp_m = warp >> 2;      /* 0..1 -> *64 */
    const int warp_n = warp & 3;       /* 0..3 -> *32 */
    const int lg = lane >> 2, lt = lane & 3;

    auto issue = [&](int it, int stg) {
        const int k0 = it * 32;
        char* S = smc + HDR + stg * F_STG;
        #pragma unroll
        for (int j = 0; j < 4; ++j) {
            const int q = tid + 256 * j;
            const int row = q >> 3, c = q & 7;
            const uint32_t sw = swz128(row * 128 + c * 16);
            CP16(sptr(S + sw),         g_xt + (size_t)stok[row] * TD + k0 + c * 4);
            CP16(sptr(S + 16384 + sw), W1e + (size_t)(n0 + row) * TD + k0 + c * 4);
            CP16(sptr(S + 32768 + sw), W3e + (size_t)(n0 + row) * TD + k0 + c * 4);
        }
        CP_COMMIT();
    };

    float acc1[4][4][4], acc3[4][4][4];
    #pragma unroll
    for (int i = 0; i < 4; ++i)
        #pragma unroll
        for (int j = 0; j < 4; ++j)
            #pragma unroll
            for (int k = 0; k < 4; ++k) { acc1[i][j][k] = 0.f; acc3[i][j][k] = 0.f; }

    issue(0, 0);
    issue(1, 1);
    int sa = 0, sc = 2;
    const int NIT = TD / 32;   /* 16 */

    #pragma unroll 1
    for (int it = 0; it < NIT; ++it) {
        if (it < NIT - 1) { CP_WAIT1(); } else { CP_WAIT0(); }
        __syncthreads();

        const float* A  = (const float*)(smc + HDR + sa * F_STG);
        const float* B1 = A + 4096;
        const float* B3 = A + 8192;

        #pragma unroll
        for (int ks = 0; ks < 4; ++ks) {
            const int c0  = 2 * ks;
            const int xo0 = ((c0 ^ lg) << 2) + lt;
            const int xo1 = (((c0 + 1) ^ lg) << 2) + lt;
            unsigned a[4][4];
            #pragma unroll
            for (int mi = 0; mi < 4; ++mi) {
                const int r0 = (warp_m * 64 + mi * 16 + lg) * 32;
                a[mi][0] = __float_as_uint(A[r0 + xo0]);
                a[mi][1] = __float_as_uint(A[r0 + 256 + xo0]);   /* +8 rows */
                a[mi][2] = __float_as_uint(A[r0 + xo1]);
                a[mi][3] = __float_as_uint(A[r0 + 256 + xo1]);
            }
            unsigned b1f[4][2], b3f[4][2];
            #pragma unroll
            for (int ni = 0; ni < 4; ++ni) {
                const int nr = (warp_n * 32 + ni * 8 + lg) * 32;
                b1f[ni][0] = __float_as_uint(B1[nr + xo0]);
                b1f[ni][1] = __float_as_uint(B1[nr + xo1]);
                b3f[ni][0] = __float_as_uint(B3[nr + xo0]);
                b3f[ni][1] = __float_as_uint(B3[nr + xo1]);
            }
            #pragma unroll
            for (int mi = 0; mi < 4; ++mi)
                #pragma unroll
                for (int ni = 0; ni < 4; ++ni) {
                    mma_tf32(acc1[mi][ni][0], acc1[mi][ni][1], acc1[mi][ni][2], acc1[mi][ni][3],
                             a[mi][0], a[mi][1], a[mi][2], a[mi][3], b1f[ni][0], b1f[ni][1]);
                    mma_tf32(acc3[mi][ni][0], acc3[mi][ni][1], acc3[mi][ni][2], acc3[mi][ni][3],
                             a[mi][0], a[mi][1], a[mi][2], a[mi][3], b3f[ni][0], b3f[ni][1]);
                }
        }

        if (it + 2 < NIT) issue(it + 2, sc);
        if (++sa == 3) sa = 0;
        if (++sc == 3) sc = 0;
    }

    /* epilogue: h = (X@W1) * silu(X@W3), tf32-rounded for ffn2 */
    #pragma unroll
    for (int mi = 0; mi < 4; ++mi) {
        #pragma unroll
        for (int half = 0; half < 2; ++half) {
            const int rl = warp_m * 64 + mi * 16 + half * 8 + lg;
            const int r  = m0 + rl;
            if (r < cnt) {
                float* hrow = g_H + (size_t)(base + r) * TH + n0 + warp_n * 32;
                #pragma unroll
                for (int ni = 0; ni < 4; ++ni) {
                    const float g1v = acc1[mi][ni][half * 2 + 0];
                    const float g1w = acc1[mi][ni][half * 2 + 1];
                    const float g3v = acc3[mi][ni][half * 2 + 0];
                    const float g3w = acc3[mi][ni][half * 2 + 1];
                    float2 h;
                    h.x = tf32f(g1v * (g3v / (1.f + expf(-g3v))));
                    h.y = tf32f(g1w * (g3w / (1.f + expf(-g3w))));
                    *(float2*)(hrow + ni * 8 + 2 * lt) = h;
                }
            }
        }
    }
}

/* ================= FFN stage 2: y += gate * (H @ W2) =================
   CTA tile 128(M) x 256(N). BK=32, 64 iters, 3-stage cp.async.
   8 warps = 2m x 4n; warp tile 64x64 -> m_frags=4, n_frags=8.
   Stage smem 48KB: A(H)[128][32] @0, B(W2)[256n][32k] @16K. */
__global__ __launch_bounds__(256, 1) void ffn2_kernel(float* __restrict__ y)
{
    const int e   = blockIdx.z;
    const int cnt = g_counts[e];
    const int m0  = blockIdx.x * 128;
    if (m0 >= cnt) return;
    const int n0   = blockIdx.y * 256;
    const int base = g_base[e];

    extern __shared__ char smc[];
    int*   sslot = (int*)smc;           /* 128 */
    int*   stokT = (int*)(smc + 512);   /* 128 */
    float* sgate = (float*)(smc + 1024);/* 128 */

    const int tid = threadIdx.x;
    if (tid < 128) {
        const int r = m0 + tid;
        const int rc = (r < cnt) ? r : (cnt - 1);
        sslot[tid] = base + rc;
        stokT[tid] = g_tok[e * NTOK + rc];
        sgate[tid] = (r < cnt) ? g_gate[e * NTOK + r] : 0.f;
    }
    __syncthreads();

    const float* W2e = g_w2t + (size_t)e * TD * TH;

    const int warp = tid >> 5, lane = tid & 31;
    const int warp_m = warp >> 2;      /* 0..1 -> *64 */
    const int warp_n = warp & 3;       /* 0..3 -> *64 */
    const int lg = lane >> 2, lt = lane & 3;

    auto issue = [&](int it, int stg) {
        const int k0 = it * 32;
        char* S = smc + HDR + stg * F_STG;
        #pragma unroll
        for (int j = 0; j < 4; ++j) {      /* H: 1024 chunks */
            const int q = tid + 256 * j;
            const int row = q >> 3, c = q & 7;
            CP16(sptr(S + swz128(row * 128 + c * 16)),
                 g_H + (size_t)sslot[row] * TH + k0 + c * 4);
        }
        #pragma unroll
        for (int j = 0; j < 8; ++j) {      /* W2: 2048 chunks */
            const int q = tid + 256 * j;
            const int row = q >> 3, c = q & 7;
            CP16(sptr(S + 16384 + swz128(row * 128 + c * 16)),
                 W2e + (size_t)(n0 + row) * TH + k0 + c * 4);
        }
        CP_COMMIT();
    };

    float acc[4][8][4];
    #pragma unroll
    for (int i = 0; i < 4; ++i)
        #pragma unroll
        for (int j = 0; j < 8; ++j)
            #pragma unroll
            for (int k = 0; k < 4; ++k) acc[i][j][k] = 0.f;

    issue(0, 0);
    issue(1, 1);
    int sa = 0, sc = 2;
    const int NIT = TH / 32;   /* 64 */

    #pragma unroll 1
    for (int it = 0; it < NIT; ++it) {
        if (it < NIT - 1) { CP_WAIT1(); } else { CP_WAIT0(); }
        __syncthreads();

        const float* A = (const float*)(smc + HDR + sa * F_STG);
        const float* B = A + 4096;

        #pragma unroll
        for (int ks = 0; ks < 4; ++ks) {
            const int c0  = 2 * ks;
            const int xo0 = ((c0 ^ lg) << 2) + lt;
            const int xo1 = (((c0 + 1) ^ lg) << 2) + lt;
            unsigned a[4][4];
            #pragma unroll
            for (int mi = 0; mi < 4; ++mi) {
                const int r0 = (warp_m * 64 + mi * 16 + lg) * 32;
                a[mi][0] = __float_as_uint(A[r0 + xo0]);
                a[mi][1] = __float_as_uint(A[r0 + 256 + xo0]);
                a[mi][2] = __float_as_uint(A[r0 + xo1]);
                a[mi][3] = __float_as_uint(A[r0 + 256 + xo1]);
            }
            unsigned b[8][2];
            #pragma unroll
            for (int ni = 0; ni < 8; ++ni) {
                const int nr = (warp_n * 64 + ni * 8 + lg) * 32;
                b[ni][0] = __float_as_uint(B[nr + xo0]);
                b[ni][1] = __float_as_uint(B[nr + xo1]);
            }
            #pragma unroll
            for (int mi = 0; mi < 4; ++mi)
                #pragma unroll
                for (int ni = 0; ni < 8; ++ni)
                    mma_tf32(acc[mi][ni][0], acc[mi][ni][1], acc[mi][ni][2], acc[mi][ni][3],
                             a[mi][0], a[mi][1], a[mi][2], a[mi][3], b[ni][0], b[ni][1]);
        }

        if (it + 2 < NIT) issue(it + 2, sc);
        if (++sa == 3) sa = 0;
        if (++sc == 3) sc = 0;
    }

    #pragma unroll
    for (int mi = 0; mi < 4; ++mi) {
        #pragma unroll
        for (int half = 0; half < 2; ++half) {
            const int rl = warp_m * 64 + mi * 16 + half * 8 + lg;
            if (m0 + rl < cnt) {
                const int t = stokT[rl];
                const float g = sgate[rl];
                float* yr = y + (size_t)t * TD + n0 + warp_n * 64;
                #pragma unroll
                for (int ni = 0; ni < 8; ++ni) {
                    const int col = ni * 8 + 2 * lt;
                    atomicAdd(&yr[col],     g * acc[mi][ni][half * 2 + 0]);
                    atomicAdd(&yr[col + 1], g * acc[mi][ni][half * 2 + 1]);
                }
            }
        }
    }
}

/* ---------------- losses ---------------- */
__global__ void losses_kernel(const float* __restrict__ Wp, float* __restrict__ out, int sbase)
{
    if (threadIdx.x != 0) return;
    const double z = g_zsum / (double)((size_t)NTOK * TE) * 0.001;
    double sb = 0.0;
    for (int e = 0; e < TE; ++e) {
        const double m = g_psum[e] / (double)NTOK;
        const double d = m - 1.0 / TE;
        sb += d * d;
    }
    sb /= TE;
    float Pn[TP][TE];
    for (int p = 0; p < TP; ++p) {
        float mx = -1e30f;
        for (int e = 0; e < TE; ++e) mx = fmaxf(mx, Wp[p * TE + e]);
        float s = 0.f;
        for (int e = 0; e < TE; ++e) { Pn[p][e] = expf(Wp[p * TE + e] - mx); s += Pn[p][e]; }
        const float inv = 1.f / s;
        for (int e = 0; e < TE; ++e) Pn[p][e] *= inv;
    }
    double acc = 0.0;
    for (int p = 0; p < TP; ++p)
        for (int q = 0; q < TP; ++q)
            if (p != q) {
                float d = 0.f;
                for (int e = 0; e < TE; ++e) d += Pn[p][e] * Pn[q][e];
                acc += (double)d;
            }
    const double spec = acc / (double)(TP * TP) * 0.1;
    out[sbase + 0] = (float)z;
    out[sbase + 1] = (float)sb;
    out[sbase + 2] = (float)spec;
}

/* ---------------- launch ---------------- */
extern "C" void kernel_launch(void* const* d_in, const int* in_sizes, int n_in,
                              void* d_out, int out_size)
{
    const float* x  = (const float*)d_in[0];
    const int*   pid= (const int*)  d_in[1];
    const float* Wr = (const float*)d_in[2];
    const float* Wp = (const float*)d_in[3];
    const float* W1 = (const float*)d_in[4];
    const float* W2 = (const float*)d_in[5];
    const float* W3 = (const float*)d_in[6];
    float* out = (float*)d_out;

    static int attr_done = 0;
    if (!attr_done) {
        cudaFuncSetAttribute(ffn1_kernel, cudaFuncAttributeMaxDynamicSharedMemorySize, FFN_SMEM);
        cudaFuncSetAttribute(ffn2_kernel, cudaFuncAttributeMaxDynamicSharedMemorySize, FFN_SMEM);
        attr_done = 1;
    }

    cudaMemsetAsync(d_out, 0, (size_t)out_size * sizeof(float));
    {
        dim3 gP(64, 64, 25), bP(32, 8);
        prep_kernel<<<gP, bP>>>(x, W1, W2, W3);
    }
    router_kernel<<<NTOK / 128, 256>>>(x, pid, Wr, Wp);
    prefix_kernel<<<1, 1>>>();

    dim3 gA(NTOK / 128, TH / 128, TE);
    ffn1_kernel<<<gA, 256, FFN_SMEM>>>();

    dim3 gB(NTOK / 128, TD / 256, TE);
    ffn2_kernel<<<gB, 256, FFN_SMEM>>>(out);

    losses_kernel<<<1, 1>>>(Wp, out, out_size - 3);
}

// round 7
// speedup vs baseline: 1.5337x; 1.5337x over previous
#include <cuda_runtime.h>
#include <cuda_fp16.h>
#include <math.h>
#include <stdint.h>

#define TB 8
#define TS 4096
#define TD 512
#define TH 2048
#define TE 8
#define TP 16
#define NTOK (TB*TS)          /* 32768 tokens */

/* ---------------- device state ---------------- */
__device__ int    g_counts[TE];
__device__ int    g_base[TE];
__device__ int    g_tok[TE * NTOK];
__device__ float  g_gate[TE * NTOK];
__device__ double g_zsum;
__device__ double g_psum[TE];
__device__ __half g_H[(size_t)2 * NTOK * TH];     /* fp16 H scratch, 256 MB */
__device__ __half g_xh[(size_t)NTOK * TD];        /* fp16 x */
__device__ __half g_w1h[(size_t)TE * TH * TD];    /* W1^T: [e][h][d] (K-major) */
__device__ __half g_w3h[(size_t)TE * TH * TD];
__device__ __half g_w2h[(size_t)TE * TD * TH];    /* W2^T: [e][d][h] */

/* ---------------- helpers ---------------- */
__device__ __forceinline__ void mma_f16(
    float& c0, float& c1, float& c2, float& c3,
    unsigned a0, unsigned a1, unsigned a2, unsigned a3,
    unsigned b0, unsigned b1)
{
    asm volatile(
        "mma.sync.aligned.m16n8k16.row.col.f32.f16.f16.f32 "
        "{%0,%1,%2,%3}, {%4,%5,%6,%7}, {%8,%9}, {%0,%1,%2,%3};"
        : "+f"(c0), "+f"(c1), "+f"(c2), "+f"(c3)
        : "r"(a0), "r"(a1), "r"(a2), "r"(a3), "r"(b0), "r"(b1));
}

#define CP16(dst, src) \
    asm volatile("cp.async.cg.shared.global [%0], [%1], 16;" :: "r"(dst), "l"(src))
#define CP_COMMIT() asm volatile("cp.async.commit_group;")
#define CP_WAIT1()  asm volatile("cp.async.wait_group 1;")
#define CP_WAIT0()  asm volatile("cp.async.wait_group 0;")

__device__ __forceinline__ unsigned sptr(const void* p) {
    return (unsigned)__cvta_generic_to_shared(p);
}

/* row of 32 data halfs padded to 40 (80 B): bank = (20*lg + lt) mod 32 -> conflict-free */
#define ROWH 40

/* ffn1 stage: A 128x40 halfs (10240B) @0, B1 64x40 (5120B) @10240, B3 @15360 */
#define STG1   20480
#define HDR1   1024
#define FFN1_SMEM (HDR1 + 3 * STG1)     /* 62464 B */
/* ffn2 stage: A 128x40 (10240B) @0, B 128x40 (10240B) @10240 */
#define STG2   20480
#define HDR2   2048
#define FFN2_SMEM (HDR2 + 3 * STG2)     /* 63488 B */

/* ---------------- prep: transpose+round weights to fp16, round x, zero state ---------------- */
__global__ __launch_bounds__(256) void prep_kernel(
    const float* __restrict__ x, const float* __restrict__ W1,
    const float* __restrict__ W2, const float* __restrict__ W3)
{
    const int m = blockIdx.z;
    const int tx = threadIdx.x, ty = threadIdx.y;
    if (m < 24) {
        const float* src; __half* dst; int R, C;
        if (m < 8)       { src = W1 + (size_t)m * TD * TH;        dst = g_w1h + (size_t)m * TH * TD;        R = TD; C = TH; }
        else if (m < 16) { src = W3 + (size_t)(m - 8) * TD * TH;  dst = g_w3h + (size_t)(m - 8) * TH * TD;  R = TD; C = TH; }
        else             { src = W2 + (size_t)(m - 16) * TH * TD; dst = g_w2h + (size_t)(m - 16) * TD * TH; R = TH; C = TD; }
        const int bx = blockIdx.x, by = blockIdx.y;
        if (bx * 32 >= C || by * 32 >= R) return;
        __shared__ float t[32][33];
        #pragma unroll
        for (int i = 0; i < 4; ++i)
            t[ty + 8 * i][tx] = src[(size_t)(by * 32 + ty + 8 * i) * C + bx * 32 + tx];
        __syncthreads();
        #pragma unroll
        for (int i = 0; i < 4; ++i)
            dst[(size_t)(bx * 32 + ty + 8 * i) * R + by * 32 + tx] = __float2half_rn(t[tx][ty + 8 * i]);
    } else {
        const int tid = ty * 32 + tx;
        const size_t nb = (size_t)blockIdx.y * 64 + blockIdx.x;   /* 0..4095 */
        if (nb == 0 && tid < TE) { g_counts[tid] = 0; g_psum[tid] = 0.0; if (tid == 0) g_zsum = 0.0; }
        const size_t NX8 = (size_t)NTOK * TD / 8;
        const size_t stride = (size_t)4096 * 256;
        const float4* x4 = (const float4*)x;
        for (size_t i = nb * 256 + tid; i < NX8; i += stride) {
            float4 v0 = x4[2 * i], v1 = x4[2 * i + 1];
            __half2* dst = (__half2*)(g_xh + i * 8);
            dst[0] = __floats2half2_rn(v0.x, v0.y);
            dst[1] = __floats2half2_rn(v0.z, v0.w);
            dst[2] = __floats2half2_rn(v1.x, v1.y);
            dst[3] = __floats2half2_rn(v1.z, v1.w);
        }
    }
}

/* ---------------- router (fp32, unchanged, passing) ---------------- */
__global__ __launch_bounds__(256) void router_kernel(
    const float* __restrict__ x, const int* __restrict__ pid,
    const float* __restrict__ Wr, const float* __restrict__ Wp)
{
    __shared__ float sWrT[TE * TD];
    __shared__ float sPsum[TE];
    __shared__ float sZsum;
    __shared__ int   sCnt[TE];
    __shared__ int   sGbase[TE];
    __shared__ unsigned char sE[256];
    __shared__ short sSlot[256];
    __shared__ float sG[256];

    const int tid = threadIdx.x;
    for (int idx = tid; idx < TD * TE; idx += 256) {
        int d = idx >> 3, e = idx & 7;
        sWrT[e * TD + d] = Wr[idx];
    }
    if (tid < TE) { sPsum[tid] = 0.f; sCnt[tid] = 0; }
    if (tid == 0) sZsum = 0.f;
    __syncthreads();

    const int warp = tid >> 5, lane = tid & 31;
    const int tok0 = blockIdx.x * 128 + warp * 16;

    for (int tt = 0; tt < 16; ++tt) {
        const int t = tok0 + tt;
        float acc[TE];
        #pragma unroll
        for (int e = 0; e < TE; ++e) acc[e] = 0.f;
        const float* xr = x + (size_t)t * TD;
        for (int i = lane; i < TD; i += 32) {
            float xv = xr[i];
            #pragma unroll
            for (int e = 0; e < TE; ++e)
                acc[e] = fmaf(xv, sWrT[e * TD + i], acc[e]);
        }
        #pragma unroll
        for (int off = 16; off >= 1; off >>= 1) {
            #pragma unroll
            for (int e = 0; e < TE; ++e)
                acc[e] += __shfl_down_sync(0xffffffffu, acc[e], off);
        }
        if (lane == 0) {
            const int b = t / TS;
            const int p = pid[b];
            float l[TE];
            float zs = 0.f, mx = -1e30f;
            #pragma unroll
            for (int e = 0; e < TE; ++e) {
                l[e] = acc[e] + Wp[p * TE + e];
                zs += l[e] * l[e];
                mx = fmaxf(mx, l[e]);
            }
            atomicAdd(&sZsum, zs);
            float s = 0.f, pr[TE];
            #pragma unroll
            for (int e = 0; e < TE; ++e) { pr[e] = expf(l[e] - mx); s += pr[e]; }
            const float inv = 1.f / s;
            #pragma unroll
            for (int e = 0; e < TE; ++e) atomicAdd(&sPsum[e], pr[e] * inv);
            int i0 = 0;
            #pragma unroll
            for (int e = 1; e < TE; ++e) if (l[e] > l[i0]) i0 = e;
            int i1 = (i0 == 0) ? 1 : 0;
            #pragma unroll
            for (int e = 0; e < TE; ++e) if (e != i0 && l[e] > l[i1]) i1 = e;
            const float e1 = expf(l[i1] - l[i0]);
            const float g0 = 1.f / (1.f + e1);
            const float g1 = e1 * g0;
            const int s0 = atomicAdd(&sCnt[i0], 1);
            const int s1 = atomicAdd(&sCnt[i1], 1);
            const int loc = (warp * 16 + tt) * 2;
            sE[loc]     = (unsigned char)i0; sSlot[loc]     = (short)s0; sG[loc]     = g0;
            sE[loc + 1] = (unsigned char)i1; sSlot[loc + 1] = (short)s1; sG[loc + 1] = g1;
        }
    }
    __syncthreads();
    if (tid < TE) {
        sGbase[tid] = atomicAdd(&g_counts[tid], sCnt[tid]);
        atomicAdd(&g_psum[tid], (double)sPsum[tid]);
    }
    if (tid == 0) atomicAdd(&g_zsum, (double)sZsum);
    __syncthreads();
    {
        const int e = sE[tid];
        const int pos = sGbase[e] + sSlot[tid];
        const int t = blockIdx.x * 128 + (tid >> 1);
        g_tok[e * NTOK + pos]  = t;
        g_gate[e * NTOK + pos] = sG[tid];
    }
}

__global__ void prefix_kernel() {
    if (threadIdx.x == 0) {
        int s = 0;
        for (int e = 0; e < TE; ++e) { g_base[e] = s; s += g_counts[e]; }
    }
}

/* ================= FFN stage 1 (fp16 mma): H = (X@W1) * silu(X@W3) =================
   CTA 128(M) x 64(N) x 2 gemms. BK=32 halfs, 16 iters, 3-stage cp.async.
   8 warps = 4m x 2n; warp tile 32x32 per gemm (mi 0..1, ni 0..3 of n8).
   Smem rows padded to 40 halfs -> conflict-free fragment LDS. */
__global__ __launch_bounds__(256, 2) void ffn1_kernel()
{
    const int e   = blockIdx.z;
    const int cnt = g_counts[e];
    const int m0  = blockIdx.x * 128;
    if (m0 >= cnt) return;
    const int n0   = blockIdx.y * 64;
    const int base = g_base[e];

    extern __shared__ char smc[];
    int* stok = (int*)smc;

    const int tid = threadIdx.x;
    if (tid < 128) {
        const int r = m0 + tid;
        stok[tid] = (r < cnt) ? g_tok[e * NTOK + r] : g_tok[e * NTOK];
    }
    __syncthreads();

    const __half* W1e = g_w1h + (size_t)e * TH * TD;
    const __half* W3e = g_w3h + (size_t)e * TH * TD;

    const int warp = tid >> 5, lane = tid & 31;
    const int warp_m = warp & 3;     /* *32 */
    const int warp_n = warp >> 2;    /* *32 */
    const int lg = lane >> 2, lt = lane & 3;

    auto issue = [&](int it, int stg) {
        const int k0 = it * 32;
        char* S = smc + HDR1 + stg * STG1;
        #pragma unroll
        for (int j = 0; j < 2; ++j) {              /* A: 512 chunks */
            const int q = tid + 256 * j;
            const int row = q >> 2, c = q & 3;
            CP16(sptr(S + row * 80 + c * 16),
                 g_xh + (size_t)stok[row] * TD + k0 + c * 8);
        }
        {                                           /* B1, B3: 256 chunks each */
            const int row = tid >> 2, c = tid & 3;
            CP16(sptr(S + 10240 + row * 80 + c * 16),
                 W1e + (size_t)(n0 + row) * TD + k0 + c * 8);
            CP16(sptr(S + 15360 + row * 80 + c * 16),
                 W3e + (size_t)(n0 + row) * TD + k0 + c * 8);
        }
        CP_COMMIT();
    };

    float acc1[2][4][4], acc3[2][4][4];
    #pragma unroll
    for (int i = 0; i < 2; ++i)
        #pragma unroll
        for (int j = 0; j < 4; ++j)
            #pragma unroll
            for (int k = 0; k < 4; ++k) { acc1[i][j][k] = 0.f; acc3[i][j][k] = 0.f; }

    issue(0, 0);
    issue(1, 1);
    int sa = 0, sc = 2;
    const int NIT = TD / 32;   /* 16 */

    #pragma unroll 1
    for (int it = 0; it < NIT; ++it) {
        if (it < NIT - 1) { CP_WAIT1(); } else { CP_WAIT0(); }
        __syncthreads();

        const __half* A  = (const __half*)(smc + HDR1 + sa * STG1);
        const __half* B1 = A + 5120;   /* +10240 B */
        const __half* B3 = A + 7680;   /* +15360 B */

        #pragma unroll
        for (int ks = 0; ks < 2; ++ks) {
            const int kk = ks * 16;
            unsigned a[2][4];
            #pragma unroll
            for (int mi = 0; mi < 2; ++mi) {
                const int r0 = (warp_m * 32 + mi * 16 + lg) * ROWH;
                a[mi][0] = *(const unsigned*)&A[r0 + kk + 2 * lt];
                a[mi][1] = *(const unsigned*)&A[r0 + 8 * ROWH + kk + 2 * lt];
                a[mi][2] = *(const unsigned*)&A[r0 + kk + 8 + 2 * lt];
                a[mi][3] = *(const unsigned*)&A[r0 + 8 * ROWH + kk + 8 + 2 * lt];
            }
            unsigned b1f[4][2], b3f[4][2];
            #pragma unroll
            for (int ni = 0; ni < 4; ++ni) {
                const int rn = (warp_n * 32 + ni * 8 + lg) * ROWH;
                b1f[ni][0] = *(const unsigned*)&B1[rn + kk + 2 * lt];
                b1f[ni][1] = *(const unsigned*)&B1[rn + kk + 8 + 2 * lt];
                b3f[ni][0] = *(const unsigned*)&B3[rn + kk + 2 * lt];
                b3f[ni][1] = *(const unsigned*)&B3[rn + kk + 8 + 2 * lt];
            }
            #pragma unroll
            for (int mi = 0; mi < 2; ++mi)
                #pragma unroll
                for (int ni = 0; ni < 4; ++ni) {
                    mma_f16(acc1[mi][ni][0], acc1[mi][ni][1], acc1[mi][ni][2], acc1[mi][ni][3],
                            a[mi][0], a[mi][1], a[mi][2], a[mi][3], b1f[ni][0], b1f[ni][1]);
                    mma_f16(acc3[mi][ni][0], acc3[mi][ni][1], acc3[mi][ni][2], acc3[mi][ni][3],
                            a[mi][0], a[mi][1], a[mi][2], a[mi][3], b3f[ni][0], b3f[ni][1]);
                }
        }

        if (it + 2 < NIT) issue(it + 2, sc);
        if (++sa == 3) sa = 0;
        if (++sc == 3) sc = 0;
    }

    /* epilogue: h = (X@W1) * silu(X@W3), store fp16 */
    #pragma unroll
    for (int mi = 0; mi < 2; ++mi) {
        #pragma unroll
        for (int half = 0; half < 2; ++half) {
            const int rl = warp_m * 32 + mi * 16 + half * 8 + lg;
            const int r  = m0 + rl;
            if (r < cnt) {
                __half* hrow = g_H + (size_t)(base + r) * TH + n0 + warp_n * 32;
                #pragma unroll
                for (int ni = 0; ni < 4; ++ni) {
                    const float g1v = acc1[mi][ni][half * 2 + 0];
                    const float g1w = acc1[mi][ni][half * 2 + 1];
                    const float g3v = acc3[mi][ni][half * 2 + 0];
                    const float g3w = acc3[mi][ni][half * 2 + 1];
                    const float hx = g1v * (g3v / (1.f + expf(-g3v)));
                    const float hy = g1w * (g3w / (1.f + expf(-g3w)));
                    *(__half2*)(hrow + ni * 8 + 2 * lt) = __floats2half2_rn(hx, hy);
                }
            }
        }
    }
}

/* ================= FFN stage 2 (fp16 mma): y += gate * (H @ W2) =================
   CTA 128(M) x 128(N). BK=32, 64 iters, 3-stage cp.async.
   8 warps = 2m x 4n; warp tile 64x32 (mi 0..3, ni 0..3). */
__global__ __launch_bounds__(256, 2) void ffn2_kernel(float* __restrict__ y)
{
    const int e   = blockIdx.z;
    const int cnt = g_counts[e];
    const int m0  = blockIdx.x * 128;
    if (m0 >= cnt) return;
    const int n0   = blockIdx.y * 128;
    const int base = g_base[e];

    extern __shared__ char smc[];
    int*   sslot = (int*)smc;            /* 128 */
    int*   stokT = (int*)(smc + 512);    /* 128 */
    float* sgate = (float*)(smc + 1024); /* 128 */

    const int tid = threadIdx.x;
    if (tid < 128) {
        const int r = m0 + tid;
        const int rc = (r < cnt) ? r : (cnt - 1);
        sslot[tid] = base + rc;
        stokT[tid] = g_tok[e * NTOK + rc];
        sgate[tid] = (r < cnt) ? g_gate[e * NTOK + r] : 0.f;
    }
    __syncthreads();

    const __half* W2e = g_w2h + (size_t)e * TD * TH;

    const int warp = tid >> 5, lane = tid & 31;
    const int warp_m = warp >> 2;    /* *64 */
    const int warp_n = warp & 3;     /* *32 */
    const int lg = lane >> 2, lt = lane & 3;

    auto issue = [&](int it, int stg) {
        const int k0 = it * 32;
        char* S = smc + HDR2 + stg * STG2;
        #pragma unroll
        for (int j = 0; j < 2; ++j) {              /* A(H): 512 chunks */
            const int q = tid + 256 * j;
            const int row = q >> 2, c = q & 3;
            CP16(sptr(S + row * 80 + c * 16),
                 g_H + (size_t)sslot[row] * TH + k0 + c * 8);
        }
        #pragma unroll
        for (int j = 0; j < 2; ++j) {              /* B(W2): 512 chunks */
            const int q = tid + 256 * j;
            const int row = q >> 2, c = q & 3;
            CP16(sptr(S + 10240 + row * 80 + c * 16),
                 W2e + (size_t)(n0 + row) * TH + k0 + c * 8);
        }
        CP_COMMIT();
    };

    float acc[4][4][4];
    #pragma unroll
    for (int i = 0; i < 4; ++i)
        #pragma unroll
        for (int j = 0; j < 4; ++j)
            #pragma unroll
            for (int k = 0; k < 4; ++k) acc[i][j][k] = 0.f;

    issue(0, 0);
    issue(1, 1);
    int sa = 0, sc = 2;
    const int NIT = TH / 32;   /* 64 */

    #pragma unroll 1
    for (int it = 0; it < NIT; ++it) {
        if (it < NIT - 1) { CP_WAIT1(); } else { CP_WAIT0(); }
        __syncthreads();

        const __half* A = (const __half*)(smc + HDR2 + sa * STG2);
        const __half* B = A + 5120;

        #pragma unroll
        for (int ks = 0; ks < 2; ++ks) {
            const int kk = ks * 16;
            unsigned a[4][4];
            #pragma unroll
            for (int mi = 0; mi < 4; ++mi) {
                const int r0 = (warp_m * 64 + mi * 16 + lg) * ROWH;
                a[mi][0] = *(const unsigned*)&A[r0 + kk + 2 * lt];
                a[mi][1] = *(const unsigned*)&A[r0 + 8 * ROWH + kk + 2 * lt];
                a[mi][2] = *(const unsigned*)&A[r0 + kk + 8 + 2 * lt];
                a[mi][3] = *(const unsigned*)&A[r0 + 8 * ROWH + kk + 8 + 2 * lt];
            }
            unsigned b[4][2];
            #pragma unroll
            for (int ni = 0; ni < 4; ++ni) {
                const int rn = (warp_n * 32 + ni * 8 + lg) * ROWH;
                b[ni][0] = *(const unsigned*)&B[rn + kk + 2 * lt];
                b[ni][1] = *(const unsigned*)&B[rn + kk + 8 + 2 * lt];
            }
            #pragma unroll
            for (int mi = 0; mi < 4; ++mi)
                #pragma unroll
                for (int ni = 0; ni < 4; ++ni)
                    mma_f16(acc[mi][ni][0], acc[mi][ni][1], acc[mi][ni][2], acc[mi][ni][3],
                            a[mi][0], a[mi][1], a[mi][2], a[mi][3], b[ni][0], b[ni][1]);
        }

        if (it + 2 < NIT) issue(it + 2, sc);
        if (++sa == 3) sa = 0;
        if (++sc == 3) sc = 0;
    }

    #pragma unroll
    for (int mi = 0; mi < 4; ++mi) {
        #pragma unroll
        for (int half = 0; half < 2; ++half) {
            const int rl = warp_m * 64 + mi * 16 + half * 8 + lg;
            if (m0 + rl < cnt) {
                const int t = stokT[rl];
                const float g = sgate[rl];
                float* yr = y + (size_t)t * TD + n0 + warp_n * 32;
                #pragma unroll
                for (int ni = 0; ni < 4; ++ni) {
                    const int col = ni * 8 + 2 * lt;
                    atomicAdd(&yr[col],     g * acc[mi][ni][half * 2 + 0]);
                    atomicAdd(&yr[col + 1], g * acc[mi][ni][half * 2 + 1]);
                }
            }
        }
    }
}

/* ---------------- losses ---------------- */
__global__ void losses_kernel(const float* __restrict__ Wp, float* __restrict__ out, int sbase)
{
    if (threadIdx.x != 0) return;
    const double z = g_zsum / (double)((size_t)NTOK * TE) * 0.001;
    double sb = 0.0;
    for (int e = 0; e < TE; ++e) {
        const double m = g_psum[e] / (double)NTOK;
        const double d = m - 1.0 / TE;
        sb += d * d;
    }
    sb /= TE;
    float Pn[TP][TE];
    for (int p = 0; p < TP; ++p) {
        float mx = -1e30f;
        for (int e = 0; e < TE; ++e) mx = fmaxf(mx, Wp[p * TE + e]);
        float s = 0.f;
        for (int e = 0; e < TE; ++e) { Pn[p][e] = expf(Wp[p * TE + e] - mx); s += Pn[p][e]; }
        const float inv = 1.f / s;
        for (int e = 0; e < TE; ++e) Pn[p][e] *= inv;
    }
    double acc = 0.0;
    for (int p = 0; p < TP; ++p)
        for (int q = 0; q < TP; ++q)
            if (p != q) {
                float d = 0.f;
                for (int e = 0; e < TE; ++e) d += Pn[p][e] * Pn[q][e];
                acc += (double)d;
            }
    const double spec = acc / (double)(TP * TP) * 0.1;
    out[sbase + 0] = (float)z;
    out[sbase + 1] = (float)sb;
    out[sbase + 2] = (float)spec;
}

/* ---------------- launch ---------------- */
extern "C" void kernel_launch(void* const* d_in, const int* in_sizes, int n_in,
                              void* d_out, int out_size)
{
    const float* x  = (const float*)d_in[0];
    const int*   pid= (const int*)  d_in[1];
    const float* Wr = (const float*)d_in[2];
    const float* Wp = (const float*)d_in[3];
    const float* W1 = (const float*)d_in[4];
    const float* W2 = (const float*)d_in[5];
    const float* W3 = (const float*)d_in[6];
    float* out = (float*)d_out;

    static int attr_done = 0;
    if (!attr_done) {
        cudaFuncSetAttribute(ffn1_kernel, cudaFuncAttributeMaxDynamicSharedMemorySize, FFN1_SMEM);
        cudaFuncSetAttribute(ffn2_kernel, cudaFuncAttributeMaxDynamicSharedMemorySize, FFN2_SMEM);
        attr_done = 1;
    }

    cudaMemsetAsync(d_out, 0, (size_t)out_size * sizeof(float));
    {
        dim3 gP(64, 64, 25), bP(32, 8);
        prep_kernel<<<gP, bP>>>(x, W1, W2, W3);
    }
    router_kernel<<<NTOK / 128, 256>>>(x, pid, Wr, Wp);
    prefix_kernel<<<1, 1>>>();

    dim3 gA(NTOK / 128, TH / 64, TE);
    ffn1_kernel<<<gA, 256, FFN1_SMEM>>>();

    dim3 gB(NTOK / 128, TD / 128, TE);
    ffn2_kernel<<<gB, 256, FFN2_SMEM>>>(out);

    losses_kernel<<<1, 1>>>(Wp, out, out_size - 3);
}

// round 8
// speedup vs baseline: 1.6723x; 1.0904x over previous
#include <cuda_runtime.h>
#include <cuda_fp16.h>
#include <math.h>
#include <stdint.h>

#define TB 8
#define TS 4096
#define TD 512
#define TH 2048
#define TE 8
#define TP 16
#define NTOK (TB*TS)          /* 32768 tokens */

/* ---------------- device state ---------------- */
__device__ int    g_counts[TE];
__device__ int    g_base[TE];
__device__ int    g_tok[TE * NTOK];
__device__ float  g_gate[TE * NTOK];
__device__ double g_zsum;
__device__ double g_psum[TE];
__device__ __half g_H[(size_t)2 * NTOK * TH];     /* fp16 H scratch, 256 MB */
__device__ __half g_xh[(size_t)NTOK * TD];        /* fp16 x */
__device__ __half g_w1h[(size_t)TE * TH * TD];    /* W1^T: [e][h][d] (K-major) */
__device__ __half g_w3h[(size_t)TE * TH * TD];
__device__ __half g_w2h[(size_t)TE * TD * TH];    /* W2^T: [e][d][h] */

/* ---------------- helpers ---------------- */
__device__ __forceinline__ void mma_f16(
    float& c0, float& c1, float& c2, float& c3,
    unsigned a0, unsigned a1, unsigned a2, unsigned a3,
    unsigned b0, unsigned b1)
{
    asm volatile(
        "mma.sync.aligned.m16n8k16.row.col.f32.f16.f16.f32 "
        "{%0,%1,%2,%3}, {%4,%5,%6,%7}, {%8,%9}, {%0,%1,%2,%3};"
        : "+f"(c0), "+f"(c1), "+f"(c2), "+f"(c3)
        : "r"(a0), "r"(a1), "r"(a2), "r"(a3), "r"(b0), "r"(b1));
}

#define LDSM4(r0, r1, r2, r3, addr) \
    asm volatile("ldmatrix.sync.aligned.m8n8.x4.shared.b16 {%0,%1,%2,%3}, [%4];" \
                 : "=r"(r0), "=r"(r1), "=r"(r2), "=r"(r3) : "r"(addr))

#define CP16(dst, src) \
    asm volatile("cp.async.cg.shared.global [%0], [%1], 16;" :: "r"(dst), "l"(src))
#define CP_COMMIT() asm volatile("cp.async.commit_group;")
#define CP_WAIT1()  asm volatile("cp.async.wait_group 1;")
#define CP_WAIT0()  asm volatile("cp.async.wait_group 0;")

__device__ __forceinline__ unsigned sptr(const void* p) {
    return (unsigned)__cvta_generic_to_shared(p);
}

/* rows of 32 data halfs padded to 40 (80 B): LDSM phases touch all 32 banks once */
#define ROWB 80

/* ffn1 stage: A 128x80B (10240B) @0, B1 64x80B (5120B) @10240, B3 @15360 */
#define STG1   20480
#define HDR1   1024
#define FFN1_SMEM (HDR1 + 3 * STG1)     /* 62464 B */
/* ffn2 stage: A 128x80B @0, B 128x80B @10240 */
#define STG2   20480
#define HDR2   2048
#define FFN2_SMEM (HDR2 + 3 * STG2)     /* 63488 B */

/* ---------------- prep: transpose+round weights to fp16, round x, zero state ---------------- */
__global__ __launch_bounds__(256) void prep_kernel(
    const float* __restrict__ x, const float* __restrict__ W1,
    const float* __restrict__ W2, const float* __restrict__ W3)
{
    const int m = blockIdx.z;
    const int tx = threadIdx.x, ty = threadIdx.y;
    if (m < 24) {
        const float* src; __half* dst; int R, C;
        if (m < 8)       { src = W1 + (size_t)m * TD * TH;        dst = g_w1h + (size_t)m * TH * TD;        R = TD; C = TH; }
        else if (m < 16) { src = W3 + (size_t)(m - 8) * TD * TH;  dst = g_w3h + (size_t)(m - 8) * TH * TD;  R = TD; C = TH; }
        else             { src = W2 + (size_t)(m - 16) * TH * TD; dst = g_w2h + (size_t)(m - 16) * TD * TH; R = TH; C = TD; }
        const int bx = blockIdx.x, by = blockIdx.y;
        if (bx * 32 >= C || by * 32 >= R) return;
        __shared__ float t[32][33];
        #pragma unroll
        for (int i = 0; i < 4; ++i)
            t[ty + 8 * i][tx] = src[(size_t)(by * 32 + ty + 8 * i) * C + bx * 32 + tx];
        __syncthreads();
        #pragma unroll
        for (int i = 0; i < 4; ++i)
            dst[(size_t)(bx * 32 + ty + 8 * i) * R + by * 32 + tx] = __float2half_rn(t[tx][ty + 8 * i]);
    } else {
        const int tid = ty * 32 + tx;
        const size_t nb = (size_t)blockIdx.y * 64 + blockIdx.x;   /* 0..4095 */
        if (nb == 0 && tid < TE) { g_counts[tid] = 0; g_psum[tid] = 0.0; if (tid == 0) g_zsum = 0.0; }
        const size_t NX8 = (size_t)NTOK * TD / 8;
        const size_t stride = (size_t)4096 * 256;
        const float4* x4 = (const float4*)x;
        for (size_t i = nb * 256 + tid; i < NX8; i += stride) {
            float4 v0 = x4[2 * i], v1 = x4[2 * i + 1];
            __half2* dst = (__half2*)(g_xh + i * 8);
            dst[0] = __floats2half2_rn(v0.x, v0.y);
            dst[1] = __floats2half2_rn(v0.z, v0.w);
            dst[2] = __floats2half2_rn(v1.x, v1.y);
            dst[3] = __floats2half2_rn(v1.z, v1.w);
        }
    }
}

/* ---------------- router (fp32, unchanged, passing) ---------------- */
__global__ __launch_bounds__(256) void router_kernel(
    const float* __restrict__ x, const int* __restrict__ pid,
    const float* __restrict__ Wr, const float* __restrict__ Wp)
{
    __shared__ float sWrT[TE * TD];
    __shared__ float sPsum[TE];
    __shared__ float sZsum;
    __shared__ int   sCnt[TE];
    __shared__ int   sGbase[TE];
    __shared__ unsigned char sE[256];
    __shared__ short sSlot[256];
    __shared__ float sG[256];

    const int tid = threadIdx.x;
    for (int idx = tid; idx < TD * TE; idx += 256) {
        int d = idx >> 3, e = idx & 7;
        sWrT[e * TD + d] = Wr[idx];
    }
    if (tid < TE) { sPsum[tid] = 0.f; sCnt[tid] = 0; }
    if (tid == 0) sZsum = 0.f;
    __syncthreads();

    const int warp = tid >> 5, lane = tid & 31;
    const int tok0 = blockIdx.x * 128 + warp * 16;

    for (int tt = 0; tt < 16; ++tt) {
        const int t = tok0 + tt;
        float acc[TE];
        #pragma unroll
        for (int e = 0; e < TE; ++e) acc[e] = 0.f;
        const float* xr = x + (size_t)t * TD;
        for (int i = lane; i < TD; i += 32) {
            float xv = xr[i];
            #pragma unroll
            for (int e = 0; e < TE; ++e)
                acc[e] = fmaf(xv, sWrT[e * TD + i], acc[e]);
        }
        #pragma unroll
        for (int off = 16; off >= 1; off >>= 1) {
            #pragma unroll
            for (int e = 0; e < TE; ++e)
                acc[e] += __shfl_down_sync(0xffffffffu, acc[e], off);
        }
        if (lane == 0) {
            const int b = t / TS;
            const int p = pid[b];
            float l[TE];
            float zs = 0.f, mx = -1e30f;
            #pragma unroll
            for (int e = 0; e < TE; ++e) {
                l[e] = acc[e] + Wp[p * TE + e];
                zs += l[e] * l[e];
                mx = fmaxf(mx, l[e]);
            }
            atomicAdd(&sZsum, zs);
            float s = 0.f, pr[TE];
            #pragma unroll
            for (int e = 0; e < TE; ++e) { pr[e] = expf(l[e] - mx); s += pr[e]; }
            const float inv = 1.f / s;
            #pragma unroll
            for (int e = 0; e < TE; ++e) atomicAdd(&sPsum[e], pr[e] * inv);
            int i0 = 0;
            #pragma unroll
            for (int e = 1; e < TE; ++e) if (l[e] > l[i0]) i0 = e;
            int i1 = (i0 == 0) ? 1 : 0;
            #pragma unroll
            for (int e = 0; e < TE; ++e) if (e != i0 && l[e] > l[i1]) i1 = e;
            const float e1 = expf(l[i1] - l[i0]);
            const float g0 = 1.f / (1.f + e1);
            const float g1 = e1 * g0;
            const int s0 = atomicAdd(&sCnt[i0], 1);
            const int s1 = atomicAdd(&sCnt[i1], 1);
            const int loc = (warp * 16 + tt) * 2;
            sE[loc]     = (unsigned char)i0; sSlot[loc]     = (short)s0; sG[loc]     = g0;
            sE[loc + 1] = (unsigned char)i1; sSlot[loc + 1] = (short)s1; sG[loc + 1] = g1;
        }
    }
    __syncthreads();
    if (tid < TE) {
        sGbase[tid] = atomicAdd(&g_counts[tid], sCnt[tid]);
        atomicAdd(&g_psum[tid], (double)sPsum[tid]);
    }
    if (tid == 0) atomicAdd(&g_zsum, (double)sZsum);
    __syncthreads();
    {
        const int e = sE[tid];
        const int pos = sGbase[e] + sSlot[tid];
        const int t = blockIdx.x * 128 + (tid >> 1);
        g_tok[e * NTOK + pos]  = t;
        g_gate[e * NTOK + pos] = sG[tid];
    }
}

__global__ void prefix_kernel() {
    if (threadIdx.x == 0) {
        int s = 0;
        for (int e = 0; e < TE; ++e) { g_base[e] = s; s += g_counts[e]; }
    }
}

/* ================= FFN stage 1 (fp16 mma + ldmatrix) =================
   CTA 128(M) x 64(N) x 2 gemms. BK=32 halfs, 16 iters, 3-stage cp.async.
   8 warps = 4m x 2n; warp tile 32x32 per gemm. */
__global__ __launch_bounds__(256, 2) void ffn1_kernel()
{
    const int e   = blockIdx.z;
    const int cnt = g_counts[e];
    const int m0  = blockIdx.x * 128;
    if (m0 >= cnt) return;
    const int n0   = blockIdx.y * 64;
    const int base = g_base[e];

    extern __shared__ char smc[];
    int* stok = (int*)smc;

    const int tid = threadIdx.x;
    if (tid < 128) {
        const int r = m0 + tid;
        stok[tid] = (r < cnt) ? g_tok[e * NTOK + r] : g_tok[e * NTOK];
    }
    __syncthreads();

    const __half* W1e = g_w1h + (size_t)e * TH * TD;
    const __half* W3e = g_w3h + (size_t)e * TH * TD;

    const int warp = tid >> 5, lane = tid & 31;
    const int warp_m = warp & 3;     /* *32 */
    const int warp_n = warp >> 2;    /* *32 */
    const int lg = lane >> 2, lt = lane & 3;

    /* per-lane ldmatrix offsets (bytes, within stage buffer) */
    const uint32_t a_off = (uint32_t)(warp_m * 32 + (lane & 15)) * ROWB + (lane >> 4) * 16;
    const uint32_t b_row = (uint32_t)(warp_n * 32 + (lane & 7) + ((lane >> 4) << 3));
    const uint32_t b_off = b_row * ROWB + ((lane >> 3) & 1) * 16;

    auto issue = [&](int it, int stg) {
        const int k0 = it * 32;
        char* S = smc + HDR1 + stg * STG1;
        #pragma unroll
        for (int j = 0; j < 2; ++j) {              /* A: 512 chunks */
            const int q = tid + 256 * j;
            const int row = q >> 2, c = q & 3;
            CP16(sptr(S + row * ROWB + c * 16),
                 g_xh + (size_t)stok[row] * TD + k0 + c * 8);
        }
        {                                           /* B1, B3: 256 chunks each */
            const int row = tid >> 2, c = tid & 3;
            CP16(sptr(S + 10240 + row * ROWB + c * 16),
                 W1e + (size_t)(n0 + row) * TD + k0 + c * 8);
            CP16(sptr(S + 15360 + row * ROWB + c * 16),
                 W3e + (size_t)(n0 + row) * TD + k0 + c * 8);
        }
        CP_COMMIT();
    };

    float acc1[2][4][4], acc3[2][4][4];
    #pragma unroll
    for (int i = 0; i < 2; ++i)
        #pragma unroll
        for (int j = 0; j < 4; ++j)
            #pragma unroll
            for (int k = 0; k < 4; ++k) { acc1[i][j][k] = 0.f; acc3[i][j][k] = 0.f; }

    issue(0, 0);
    issue(1, 1);
    int sa = 0, sc = 2;
    const int NIT = TD / 32;   /* 16 */

    #pragma unroll 1
    for (int it = 0; it < NIT; ++it) {
        if (it < NIT - 1) { CP_WAIT1(); } else { CP_WAIT0(); }
        __syncthreads();

        const uint32_t Sb = sptr(smc + HDR1 + sa * STG1);
        const uint32_t Aa  = Sb + a_off;
        const uint32_t B1a = Sb + 10240 + b_off;
        const uint32_t B3a = Sb + 15360 + b_off;

        #pragma unroll
        for (int ks = 0; ks < 2; ++ks) {
            const uint32_t kb = ks * 32;   /* 16 halfs = 32 B */
            unsigned a[2][4], b1f[4][2], b3f[4][2];
            LDSM4(a[0][0], a[0][1], a[0][2], a[0][3], Aa + kb);
            LDSM4(a[1][0], a[1][1], a[1][2], a[1][3], Aa + 16 * ROWB + kb);
            LDSM4(b1f[0][0], b1f[0][1], b1f[1][0], b1f[1][1], B1a + kb);
            LDSM4(b1f[2][0], b1f[2][1], b1f[3][0], b1f[3][1], B1a + 16 * ROWB + kb);
            LDSM4(b3f[0][0], b3f[0][1], b3f[1][0], b3f[1][1], B3a + kb);
            LDSM4(b3f[2][0], b3f[2][1], b3f[3][0], b3f[3][1], B3a + 16 * ROWB + kb);
            #pragma unroll
            for (int mi = 0; mi < 2; ++mi)
                #pragma unroll
                for (int ni = 0; ni < 4; ++ni) {
                    mma_f16(acc1[mi][ni][0], acc1[mi][ni][1], acc1[mi][ni][2], acc1[mi][ni][3],
                            a[mi][0], a[mi][1], a[mi][2], a[mi][3], b1f[ni][0], b1f[ni][1]);
                    mma_f16(acc3[mi][ni][0], acc3[mi][ni][1], acc3[mi][ni][2], acc3[mi][ni][3],
                            a[mi][0], a[mi][1], a[mi][2], a[mi][3], b3f[ni][0], b3f[ni][1]);
                }
        }

        if (it + 2 < NIT) issue(it + 2, sc);
        if (++sa == 3) sa = 0;
        if (++sc == 3) sc = 0;
    }

    /* epilogue: h = (X@W1) * silu(X@W3), store fp16 */
    #pragma unroll
    for (int mi = 0; mi < 2; ++mi) {
        #pragma unroll
        for (int half = 0; half < 2; ++half) {
            const int rl = warp_m * 32 + mi * 16 + half * 8 + lg;
            const int r  = m0 + rl;
            if (r < cnt) {
                __half* hrow = g_H + (size_t)(base + r) * TH + n0 + warp_n * 32;
                #pragma unroll
                for (int ni = 0; ni < 4; ++ni) {
                    const float g1v = acc1[mi][ni][half * 2 + 0];
                    const float g1w = acc1[mi][ni][half * 2 + 1];
                    const float g3v = acc3[mi][ni][half * 2 + 0];
                    const float g3w = acc3[mi][ni][half * 2 + 1];
                    const float hx = g1v * (g3v / (1.f + expf(-g3v)));
                    const float hy = g1w * (g3w / (1.f + expf(-g3w)));
                    *(__half2*)(hrow + ni * 8 + 2 * lt) = __floats2half2_rn(hx, hy);
                }
            }
        }
    }
}

/* ================= FFN stage 2 (fp16 mma + ldmatrix) =================
   CTA 128(M) x 128(N). BK=32, 64 iters, 3-stage cp.async.
   8 warps = 2m x 4n; warp tile 64x32. */
__global__ __launch_bounds__(256, 2) void ffn2_kernel(float* __restrict__ y)
{
    const int e   = blockIdx.z;
    const int cnt = g_counts[e];
    const int m0  = blockIdx.x * 128;
    if (m0 >= cnt) return;
    const int n0   = blockIdx.y * 128;
    const int base = g_base[e];

    extern __shared__ char smc[];
    int*   sslot = (int*)smc;            /* 128 */
    int*   stokT = (int*)(smc + 512);    /* 128 */
    float* sgate = (float*)(smc + 1024); /* 128 */

    const int tid = threadIdx.x;
    if (tid < 128) {
        const int r = m0 + tid;
        const int rc = (r < cnt) ? r : (cnt - 1);
        sslot[tid] = base + rc;
        stokT[tid] = g_tok[e * NTOK + rc];
        sgate[tid] = (r < cnt) ? g_gate[e * NTOK + r] : 0.f;
    }
    __syncthreads();

    const __half* W2e = g_w2h + (size_t)e * TD * TH;

    const int warp = tid >> 5, lane = tid & 31;
    const int warp_m = warp >> 2;    /* *64 */
    const int warp_n = warp & 3;     /* *32 */
    const int lg = lane >> 2, lt = lane & 3;

    const uint32_t a_off = (uint32_t)(warp_m * 64 + (lane & 15)) * ROWB + (lane >> 4) * 16;
    const uint32_t b_row = (uint32_t)(warp_n * 32 + (lane & 7) + ((lane >> 4) << 3));
    const uint32_t b_off = b_row * ROWB + ((lane >> 3) & 1) * 16;

    auto issue = [&](int it, int stg) {
        const int k0 = it * 32;
        char* S = smc + HDR2 + stg * STG2;
        #pragma unroll
        for (int j = 0; j < 2; ++j) {              /* A(H): 512 chunks */
            const int q = tid + 256 * j;
            const int row = q >> 2, c = q & 3;
            CP16(sptr(S + row * ROWB + c * 16),
                 g_H + (size_t)sslot[row] * TH + k0 + c * 8);
        }
        #pragma unroll
        for (int j = 0; j < 2; ++j) {              /* B(W2): 512 chunks */
            const int q = tid + 256 * j;
            const int row = q >> 2, c = q & 3;
            CP16(sptr(S + 10240 + row * ROWB + c * 16),
                 W2e + (size_t)(n0 + row) * TH + k0 + c * 8);
        }
        CP_COMMIT();
    };

    float acc[4][4][4];
    #pragma unroll
    for (int i = 0; i < 4; ++i)
        #pragma unroll
        for (int j = 0; j < 4; ++j)
            #pragma unroll
            for (int k = 0; k < 4; ++k) acc[i][j][k] = 0.f;

    issue(0, 0);
    issue(1, 1);
    int sa = 0, sc = 2;
    const int NIT = TH / 32;   /* 64 */

    #pragma unroll 1
    for (int it = 0; it < NIT; ++it) {
        if (it < NIT - 1) { CP_WAIT1(); } else { CP_WAIT0(); }
        __syncthreads();

        const uint32_t Sb = sptr(smc + HDR2 + sa * STG2);
        const uint32_t Aa = Sb + a_off;
        const uint32_t Ba = Sb + 10240 + b_off;

        #pragma unroll
        for (int ks = 0; ks < 2; ++ks) {
            const uint32_t kb = ks * 32;
            unsigned a[4][4], b[4][2];
            LDSM4(a[0][0], a[0][1], a[0][2], a[0][3], Aa + kb);
            LDSM4(a[1][0], a[1][1], a[1][2], a[1][3], Aa + 16 * ROWB + kb);
            LDSM4(a[2][0], a[2][1], a[2][2], a[2][3], Aa + 32 * ROWB + kb);
            LDSM4(a[3][0], a[3][1], a[3][2], a[3][3], Aa + 48 * ROWB + kb);
            LDSM4(b[0][0], b[0][1], b[1][0], b[1][1], Ba + kb);
            LDSM4(b[2][0], b[2][1], b[3][0], b[3][1], Ba + 16 * ROWB + kb);
            #pragma unroll
            for (int mi = 0; mi < 4; ++mi)
                #pragma unroll
                for (int ni = 0; ni < 4; ++ni)
                    mma_f16(acc[mi][ni][0], acc[mi][ni][1], acc[mi][ni][2], acc[mi][ni][3],
                            a[mi][0], a[mi][1], a[mi][2], a[mi][3], b[ni][0], b[ni][1]);
        }

        if (it + 2 < NIT) issue(it + 2, sc);
        if (++sa == 3) sa = 0;
        if (++sc == 3) sc = 0;
    }

    #pragma unroll
    for (int mi = 0; mi < 4; ++mi) {
        #pragma unroll
        for (int half = 0; half < 2; ++half) {
            const int rl = warp_m * 64 + mi * 16 + half * 8 + lg;
            if (m0 + rl < cnt) {
                const int t = stokT[rl];
                const float g = sgate[rl];
                float* yr = y + (size_t)t * TD + n0 + warp_n * 32;
                #pragma unroll
                for (int ni = 0; ni < 4; ++ni) {
                    const int col = ni * 8 + 2 * lt;
                    atomicAdd(&yr[col],     g * acc[mi][ni][half * 2 + 0]);
                    atomicAdd(&yr[col + 1], g * acc[mi][ni][half * 2 + 1]);
                }
            }
        }
    }
}

/* ---------------- losses ---------------- */
__global__ void losses_kernel(const float* __restrict__ Wp, float* __restrict__ out, int sbase)
{
    if (threadIdx.x != 0) return;
    const double z = g_zsum / (double)((size_t)NTOK * TE) * 0.001;
    double sb = 0.0;
    for (int e = 0; e < TE; ++e) {
        const double m = g_psum[e] / (double)NTOK;
        const double d = m - 1.0 / TE;
        sb += d * d;
    }
    sb /= TE;
    float Pn[TP][TE];
    for (int p = 0; p < TP; ++p) {
        float mx = -1e30f;
        for (int e = 0; e < TE; ++e) mx = fmaxf(mx, Wp[p * TE + e]);
        float s = 0.f;
        for (int e = 0; e < TE; ++e) { Pn[p][e] = expf(Wp[p * TE + e] - mx); s += Pn[p][e]; }
        const float inv = 1.f / s;
        for (int e = 0; e < TE; ++e) Pn[p][e] *= inv;
    }
    double acc = 0.0;
    for (int p = 0; p < TP; ++p)
        for (int q = 0; q < TP; ++q)
            if (p != q) {
                float d = 0.f;
                for (int e = 0; e < TE; ++e) d += Pn[p][e] * Pn[q][e];
                acc += (double)d;
            }
    const double spec = acc / (double)(TP * TP) * 0.1;
    out[sbase + 0] = (float)z;
    out[sbase + 1] = (float)sb;
    out[sbase + 2] = (float)spec;
}

/* ---------------- launch ---------------- */
extern "C" void kernel_launch(void* const* d_in, const int* in_sizes, int n_in,
                              void* d_out, int out_size)
{
    const float* x  = (const float*)d_in[0];
    const int*   pid= (const int*)  d_in[1];
    const float* Wr = (const float*)d_in[2];
    const float* Wp = (const float*)d_in[3];
    const float* W1 = (const float*)d_in[4];
    const float* W2 = (const float*)d_in[5];
    const float* W3 = (const float*)d_in[6];
    float* out = (float*)d_out;

    static int attr_done = 0;
    if (!attr_done) {
        cudaFuncSetAttribute(ffn1_kernel, cudaFuncAttributeMaxDynamicSharedMemorySize, FFN1_SMEM);
        cudaFuncSetAttribute(ffn2_kernel, cudaFuncAttributeMaxDynamicSharedMemorySize, FFN2_SMEM);
        attr_done = 1;
    }

    cudaMemsetAsync(d_out, 0, (size_t)out_size * sizeof(float));
    {
        dim3 gP(64, 64, 25), bP(32, 8);
        prep_kernel<<<gP, bP>>>(x, W1, W2, W3);
    }
    router_kernel<<<NTOK / 128, 256>>>(x, pid, Wr, Wp);
    prefix_kernel<<<1, 1>>>();

    dim3 gA(NTOK / 128, TH / 64, TE);
    ffn1_kernel<<<gA, 256, FFN1_SMEM>>>();

    dim3 gB(NTOK / 128, TD / 128, TE);
    ffn2_kernel<<<gB, 256, FFN2_SMEM>>>(out);

    losses_kernel<<<1, 1>>>(Wp, out, out_size - 3);
}

// round 9
// speedup vs baseline: 1.7929x; 1.0721x over previous
#include <cuda_runtime.h>
#include <cuda_fp16.h>
#include <math.h>
#include <stdint.h>

#define TB 8
#define TS 4096
#define TD 512
#define TH 2048
#define TE 8
#define TP 16
#define NTOK (TB*TS)          /* 32768 tokens */

/* ---------------- device state ---------------- */
__device__ int    g_counts[TE];
__device__ int    g_base[TE];
__device__ int    g_tok[TE * NTOK];
__device__ float  g_gate[TE * NTOK];
__device__ double g_zsum;
__device__ double g_psum[TE];
__device__ __half g_H[(size_t)2 * NTOK * TH];     /* fp16 H scratch, 256 MB */
__device__ __half g_xh[(size_t)NTOK * TD];        /* fp16 x */
__device__ __half g_w1h[(size_t)TE * TH * TD];    /* W1^T: [e][h][d] (K-major) */
__device__ __half g_w3h[(size_t)TE * TH * TD];
__device__ __half g_w2h[(size_t)TE * TD * TH];    /* W2^T: [e][d][h] */

/* ---------------- helpers ---------------- */
__device__ __forceinline__ void mma_f16(
    float& c0, float& c1, float& c2, float& c3,
    unsigned a0, unsigned a1, unsigned a2, unsigned a3,
    unsigned b0, unsigned b1)
{
    asm volatile(
        "mma.sync.aligned.m16n8k16.row.col.f32.f16.f16.f32 "
        "{%0,%1,%2,%3}, {%4,%5,%6,%7}, {%8,%9}, {%0,%1,%2,%3};"
        : "+f"(c0), "+f"(c1), "+f"(c2), "+f"(c3)
        : "r"(a0), "r"(a1), "r"(a2), "r"(a3), "r"(b0), "r"(b1));
}

#define LDSM4(r0, r1, r2, r3, addr) \
    asm volatile("ldmatrix.sync.aligned.m8n8.x4.shared.b16 {%0,%1,%2,%3}, [%4];" \
                 : "=r"(r0), "=r"(r1), "=r"(r2), "=r"(r3) : "r"(addr))

#define CP16(dst, src) \
    asm volatile("cp.async.cg.shared.global [%0], [%1], 16;" :: "r"(dst), "l"(src))
#define CP_COMMIT() asm volatile("cp.async.commit_group;")
#define CP_WAIT0()  asm volatile("cp.async.wait_group 0;")

__device__ __forceinline__ unsigned sptr(const void* p) {
    return (unsigned)__cvta_generic_to_shared(p);
}

/* rows of 64 data halfs (128B) padded to 144B: LDSM phases and STS phases
   each touch all 32 banks exactly once (36 words/row, 36 mod 32 = 4). */
#define ROWB 144

/* ffn1 stage: A 128x144B (18432) @0, B1 64x144B (9216) @18432, B3 @27648 */
#define STG1   36864
#define HDR1   1024
#define FFN1_SMEM (HDR1 + 2 * STG1)     /* 74752 B */
/* ffn2 stage: A 128x144B @0, B 128x144B @18432 */
#define STG2   36864
#define HDR2   2048
#define FFN2_SMEM (HDR2 + 2 * STG2)     /* 75776 B */

/* ---------------- prep: transpose+round weights to fp16, round x, zero state ---------------- */
__global__ __launch_bounds__(256) void prep_kernel(
    const float* __restrict__ x, const float* __restrict__ W1,
    const float* __restrict__ W2, const float* __restrict__ W3)
{
    const int m = blockIdx.z;
    const int tx = threadIdx.x, ty = threadIdx.y;
    if (m < 24) {
        const float* src; __half* dst; int R, C;
        if (m < 8)       { src = W1 + (size_t)m * TD * TH;        dst = g_w1h + (size_t)m * TH * TD;        R = TD; C = TH; }
        else if (m < 16) { src = W3 + (size_t)(m - 8) * TD * TH;  dst = g_w3h + (size_t)(m - 8) * TH * TD;  R = TD; C = TH; }
        else             { src = W2 + (size_t)(m - 16) * TH * TD; dst = g_w2h + (size_t)(m - 16) * TD * TH; R = TH; C = TD; }
        const int bx = blockIdx.x, by = blockIdx.y;
        if (bx * 32 >= C || by * 32 >= R) return;
        __shared__ float t[32][33];
        #pragma unroll
        for (int i = 0; i < 4; ++i)
            t[ty + 8 * i][tx] = src[(size_t)(by * 32 + ty + 8 * i) * C + bx * 32 + tx];
        __syncthreads();
        #pragma unroll
        for (int i = 0; i < 4; ++i)
            dst[(size_t)(bx * 32 + ty + 8 * i) * R + by * 32 + tx] = __float2half_rn(t[tx][ty + 8 * i]);
    } else {
        const int tid = ty * 32 + tx;
        const size_t nb = (size_t)blockIdx.y * 64 + blockIdx.x;   /* 0..4095 */
        if (nb == 0 && tid < TE) { g_counts[tid] = 0; g_psum[tid] = 0.0; if (tid == 0) g_zsum = 0.0; }
        const size_t NX8 = (size_t)NTOK * TD / 8;
        const size_t stride = (size_t)4096 * 256;
        const float4* x4 = (const float4*)x;
        for (size_t i = nb * 256 + tid; i < NX8; i += stride) {
            float4 v0 = x4[2 * i], v1 = x4[2 * i + 1];
            __half2* dst = (__half2*)(g_xh + i * 8);
            dst[0] = __floats2half2_rn(v0.x, v0.y);
            dst[1] = __floats2half2_rn(v0.z, v0.w);
            dst[2] = __floats2half2_rn(v1.x, v1.y);
            dst[3] = __floats2half2_rn(v1.z, v1.w);
        }
    }
}

/* ---------------- router (fp32, unchanged, passing) ---------------- */
__global__ __launch_bounds__(256) void router_kernel(
    const float* __restrict__ x, const int* __restrict__ pid,
    const float* __restrict__ Wr, const float* __restrict__ Wp)
{
    __shared__ float sWrT[TE * TD];
    __shared__ float sPsum[TE];
    __shared__ float sZsum;
    __shared__ int   sCnt[TE];
    __shared__ int   sGbase[TE];
    __shared__ unsigned char sE[256];
    __shared__ short sSlot[256];
    __shared__ float sG[256];

    const int tid = threadIdx.x;
    for (int idx = tid; idx < TD * TE; idx += 256) {
        int d = idx >> 3, e = idx & 7;
        sWrT[e * TD + d] = Wr[idx];
    }
    if (tid < TE) { sPsum[tid] = 0.f; sCnt[tid] = 0; }
    if (tid == 0) sZsum = 0.f;
    __syncthreads();

    const int warp = tid >> 5, lane = tid & 31;
    const int tok0 = blockIdx.x * 128 + warp * 16;

    for (int tt = 0; tt < 16; ++tt) {
        const int t = tok0 + tt;
        float acc[TE];
        #pragma unroll
        for (int e = 0; e < TE; ++e) acc[e] = 0.f;
        const float* xr = x + (size_t)t * TD;
        for (int i = lane; i < TD; i += 32) {
            float xv = xr[i];
            #pragma unroll
            for (int e = 0; e < TE; ++e)
                acc[e] = fmaf(xv, sWrT[e * TD + i], acc[e]);
        }
        #pragma unroll
        for (int off = 16; off >= 1; off >>= 1) {
            #pragma unroll
            for (int e = 0; e < TE; ++e)
                acc[e] += __shfl_down_sync(0xffffffffu, acc[e], off);
        }
        if (lane == 0) {
            const int b = t / TS;
            const int p = pid[b];
            float l[TE];
            float zs = 0.f, mx = -1e30f;
            #pragma unroll
            for (int e = 0; e < TE; ++e) {
                l[e] = acc[e] + Wp[p * TE + e];
                zs += l[e] * l[e];
                mx = fmaxf(mx, l[e]);
            }
            atomicAdd(&sZsum, zs);
            float s = 0.f, pr[TE];
            #pragma unroll
            for (int e = 0; e < TE; ++e) { pr[e] = expf(l[e] - mx); s += pr[e]; }
            const float inv = 1.f / s;
            #pragma unroll
            for (int e = 0; e < TE; ++e) atomicAdd(&sPsum[e], pr[e] * inv);
            int i0 = 0;
            #pragma unroll
            for (int e = 1; e < TE; ++e) if (l[e] > l[i0]) i0 = e;
            int i1 = (i0 == 0) ? 1 : 0;
            #pragma unroll
            for (int e = 0; e < TE; ++e) if (e != i0 && l[e] > l[i1]) i1 = e;
            const float e1 = expf(l[i1] - l[i0]);
            const float g0 = 1.f / (1.f + e1);
            const float g1 = e1 * g0;
            const int s0 = atomicAdd(&sCnt[i0], 1);
            const int s1 = atomicAdd(&sCnt[i1], 1);
            const int loc = (warp * 16 + tt) * 2;
            sE[loc]     = (unsigned char)i0; sSlot[loc]     = (short)s0; sG[loc]     = g0;
            sE[loc + 1] = (unsigned char)i1; sSlot[loc + 1] = (short)s1; sG[loc + 1] = g1;
        }
    }
    __syncthreads();
    if (tid < TE) {
        sGbase[tid] = atomicAdd(&g_counts[tid], sCnt[tid]);
        atomicAdd(&g_psum[tid], (double)sPsum[tid]);
    }
    if (tid == 0) atomicAdd(&g_zsum, (double)sZsum);
    __syncthreads();
    {
        const int e = sE[tid];
        const int pos = sGbase[e] + sSlot[tid];
        const int t = blockIdx.x * 128 + (tid >> 1);
        g_tok[e * NTOK + pos]  = t;
        g_gate[e * NTOK + pos] = sG[tid];
    }
}

__global__ void prefix_kernel() {
    if (threadIdx.x == 0) {
        int s = 0;
        for (int e = 0; e < TE; ++e) { g_base[e] = s; s += g_counts[e]; }
    }
}

/* ================= FFN stage 1 (fp16 mma + ldmatrix, BK=64, 2-stage) =================
   CTA 128(M) x 64(N) x 2 gemms. BK=64 halfs, 8 iters.
   8 warps = 4m x 2n; warp tile 32x32 per gemm. */
__global__ __launch_bounds__(256, 2) void ffn1_kernel()
{
    const int e   = blockIdx.z;
    const int cnt = g_counts[e];
    const int m0  = blockIdx.x * 128;
    if (m0 >= cnt) return;
    const int n0   = blockIdx.y * 64;
    const int base = g_base[e];

    extern __shared__ char smc[];
    int* stok = (int*)smc;

    const int tid = threadIdx.x;
    if (tid < 128) {
        const int r = m0 + tid;
        stok[tid] = (r < cnt) ? g_tok[e * NTOK + r] : g_tok[e * NTOK];
    }
    __syncthreads();

    const __half* W1e = g_w1h + (size_t)e * TH * TD;
    const __half* W3e = g_w3h + (size_t)e * TH * TD;

    const int warp = tid >> 5, lane = tid & 31;
    const int warp_m = warp & 3;     /* *32 */
    const int warp_n = warp >> 2;    /* *32 */
    const int lg = lane >> 2, lt = lane & 3;

    /* per-lane ldmatrix offsets (bytes, within stage buffer) */
    const uint32_t a_off = (uint32_t)(warp_m * 32 + (lane & 15)) * ROWB + (lane >> 4) * 16;
    const uint32_t b_row = (uint32_t)(warp_n * 32 + (lane & 7) + ((lane >> 4) << 3));
    const uint32_t b_off = b_row * ROWB + ((lane >> 3) & 1) * 16;

    auto issue = [&](int it, int stg) {
        const int k0 = it * 64;
        char* S = smc + HDR1 + stg * STG1;
        #pragma unroll
        for (int j = 0; j < 4; ++j) {              /* A: 1024 chunks of 16B */
            const int q = tid + 256 * j;
            const int row = q >> 3, c = q & 7;
            CP16(sptr(S + row * ROWB + c * 16),
                 g_xh + (size_t)stok[row] * TD + k0 + c * 8);
        }
        #pragma unroll
        for (int j = 0; j < 2; ++j) {              /* B1, B3: 512 chunks each */
            const int q = tid + 256 * j;
            const int row = q >> 3, c = q & 7;
            CP16(sptr(S + 18432 + row * ROWB + c * 16),
                 W1e + (size_t)(n0 + row) * TD + k0 + c * 8);
            CP16(sptr(S + 27648 + row * ROWB + c * 16),
                 W3e + (size_t)(n0 + row) * TD + k0 + c * 8);
        }
        CP_COMMIT();
    };

    float acc1[2][4][4], acc3[2][4][4];
    #pragma unroll
    for (int i = 0; i < 2; ++i)
        #pragma unroll
        for (int j = 0; j < 4; ++j)
            #pragma unroll
            for (int k = 0; k < 4; ++k) { acc1[i][j][k] = 0.f; acc3[i][j][k] = 0.f; }

    issue(0, 0);
    const int NIT = TD / 64;   /* 8 */

    #pragma unroll 1
    for (int it = 0; it < NIT; ++it) {
        CP_WAIT0();
        __syncthreads();
        if (it + 1 < NIT) issue(it + 1, (it + 1) & 1);

        const uint32_t Sb = sptr(smc + HDR1 + (it & 1) * STG1);
        const uint32_t Aa  = Sb + a_off;
        const uint32_t B1a = Sb + 18432 + b_off;
        const uint32_t B3a = Sb + 27648 + b_off;

        #pragma unroll
        for (int ks = 0; ks < 4; ++ks) {
            const uint32_t kb = ks * 32;   /* 16 halfs = 32 B */
            unsigned a[2][4], b1f[4][2], b3f[4][2];
            LDSM4(a[0][0], a[0][1], a[0][2], a[0][3], Aa + kb);
            LDSM4(a[1][0], a[1][1], a[1][2], a[1][3], Aa + 16 * ROWB + kb);
            LDSM4(b1f[0][0], b1f[0][1], b1f[1][0], b1f[1][1], B1a + kb);
            LDSM4(b1f[2][0], b1f[2][1], b1f[3][0], b1f[3][1], B1a + 16 * ROWB + kb);
            LDSM4(b3f[0][0], b3f[0][1], b3f[1][0], b3f[1][1], B3a + kb);
            LDSM4(b3f[2][0], b3f[2][1], b3f[3][0], b3f[3][1], B3a + 16 * ROWB + kb);
            #pragma unroll
            for (int mi = 0; mi < 2; ++mi)
                #pragma unroll
                for (int ni = 0; ni < 4; ++ni) {
                    mma_f16(acc1[mi][ni][0], acc1[mi][ni][1], acc1[mi][ni][2], acc1[mi][ni][3],
                            a[mi][0], a[mi][1], a[mi][2], a[mi][3], b1f[ni][0], b1f[ni][1]);
                    mma_f16(acc3[mi][ni][0], acc3[mi][ni][1], acc3[mi][ni][2], acc3[mi][ni][3],
                            a[mi][0], a[mi][1], a[mi][2], a[mi][3], b3f[ni][0], b3f[ni][1]);
                }
        }
    }

    /* epilogue: h = (X@W1) * silu(X@W3), store fp16 */
    #pragma unroll
    for (int mi = 0; mi < 2; ++mi) {
        #pragma unroll
        for (int half = 0; half < 2; ++half) {
            const int rl = warp_m * 32 + mi * 16 + half * 8 + lg;
            const int r  = m0 + rl;
            if (r < cnt) {
                __half* hrow = g_H + (size_t)(base + r) * TH + n0 + warp_n * 32;
                #pragma unroll
                for (int ni = 0; ni < 4; ++ni) {
                    const float g1v = acc1[mi][ni][half * 2 + 0];
                    const float g1w = acc1[mi][ni][half * 2 + 1];
                    const float g3v = acc3[mi][ni][half * 2 + 0];
                    const float g3w = acc3[mi][ni][half * 2 + 1];
                    const float hx = g1v * (g3v / (1.f + expf(-g3v)));
                    const float hy = g1w * (g3w / (1.f + expf(-g3w)));
                    *(__half2*)(hrow + ni * 8 + 2 * lt) = __floats2half2_rn(hx, hy);
                }
            }
        }
    }
}

/* ================= FFN stage 2 (fp16 mma + ldmatrix, BK=64, 2-stage) =================
   CTA 128(M) x 128(N). BK=64, 32 iters.
   8 warps = 2m x 4n; warp tile 64x32. */
__global__ __launch_bounds__(256, 2) void ffn2_kernel(float* __restrict__ y)
{
    const int e   = blockIdx.z;
    const int cnt = g_counts[e];
    const int m0  = blockIdx.x * 128;
    if (m0 >= cnt) return;
    const int n0   = blockIdx.y * 128;
    const int base = g_base[e];

    extern __shared__ char smc[];
    int*   sslot = (int*)smc;            /* 128 */
    int*   stokT = (int*)(smc + 512);    /* 128 */
    float* sgate = (float*)(smc + 1024); /* 128 */

    const int tid = threadIdx.x;
    if (tid < 128) {
        const int r = m0 + tid;
        const int rc = (r < cnt) ? r : (cnt - 1);
        sslot[tid] = base + rc;
        stokT[tid] = g_tok[e * NTOK + rc];
        sgate[tid] = (r < cnt) ? g_gate[e * NTOK + r] : 0.f;
    }
    __syncthreads();

    const __half* W2e = g_w2h + (size_t)e * TD * TH;

    const int warp = tid >> 5, lane = tid & 31;
    const int warp_m = warp >> 2;    /* *64 */
    const int warp_n = warp & 3;     /* *32 */
    const int lg = lane >> 2, lt = lane & 3;

    const uint32_t a_off = (uint32_t)(warp_m * 64 + (lane & 15)) * ROWB + (lane >> 4) * 16;
    const uint32_t b_row = (uint32_t)(warp_n * 32 + (lane & 7) + ((lane >> 4) << 3));
    const uint32_t b_off = b_row * ROWB + ((lane >> 3) & 1) * 16;

    auto issue = [&](int it, int stg) {
        const int k0 = it * 64;
        char* S = smc + HDR2 + stg * STG2;
        #pragma unroll
        for (int j = 0; j < 4; ++j) {              /* A(H): 1024 chunks */
            const int q = tid + 256 * j;
            const int row = q >> 3, c = q & 7;
            CP16(sptr(S + row * ROWB + c * 16),
                 g_H + (size_t)sslot[row] * TH + k0 + c * 8);
        }
        #pragma unroll
        for (int j = 0; j < 4; ++j) {              /* B(W2): 1024 chunks */
            const int q = tid + 256 * j;
            const int row = q >> 3, c = q & 7;
            CP16(sptr(S + 18432 + row * ROWB + c * 16),
                 W2e + (size_t)(n0 + row) * TH + k0 + c * 8);
        }
        CP_COMMIT();
    };

    float acc[4][4][4];
    #pragma unroll
    for (int i = 0; i < 4; ++i)
        #pragma unroll
        for (int j = 0; j < 4; ++j)
            #pragma unroll
            for (int k = 0; k < 4; ++k) acc[i][j][k] = 0.f;

    issue(0, 0);
    const int NIT = TH / 64;   /* 32 */

    #pragma unroll 1
    for (int it = 0; it < NIT; ++it) {
        CP_WAIT0();
        __syncthreads();
        if (it + 1 < NIT) issue(it + 1, (it + 1) & 1);

        const uint32_t Sb = sptr(smc + HDR2 + (it & 1) * STG2);
        const uint32_t Aa = Sb + a_off;
        const uint32_t Ba = Sb + 18432 + b_off;

        #pragma unroll
        for (int ks = 0; ks < 4; ++ks) {
            const uint32_t kb = ks * 32;
            unsigned a[4][4], b[4][2];
            LDSM4(a[0][0], a[0][1], a[0][2], a[0][3], Aa + kb);
            LDSM4(a[1][0], a[1][1], a[1][2], a[1][3], Aa + 16 * ROWB + kb);
            LDSM4(a[2][0], a[2][1], a[2][2], a[2][3], Aa + 32 * ROWB + kb);
            LDSM4(a[3][0], a[3][1], a[3][2], a[3][3], Aa + 48 * ROWB + kb);
            LDSM4(b[0][0], b[0][1], b[1][0], b[1][1], Ba + kb);
            LDSM4(b[2][0], b[2][1], b[3][0], b[3][1], Ba + 16 * ROWB + kb);
            #pragma unroll
            for (int mi = 0; mi < 4; ++mi)
                #pragma unroll
                for (int ni = 0; ni < 4; ++ni)
                    mma_f16(acc[mi][ni][0], acc[mi][ni][1], acc[mi][ni][2], acc[mi][ni][3],
                            a[mi][0], a[mi][1], a[mi][2], a[mi][3], b[ni][0], b[ni][1]);
        }
    }

    #pragma unroll
    for (int mi = 0; mi < 4; ++mi) {
        #pragma unroll
        for (int half = 0; half < 2; ++half) {
            const int rl = warp_m * 64 + mi * 16 + half * 8 + lg;
            if (m0 + rl < cnt) {
                const int t = stokT[rl];
                const float g = sgate[rl];
                float* yr = y + (size_t)t * TD + n0 + warp_n * 32;
                #pragma unroll
                for (int ni = 0; ni < 4; ++ni) {
                    const int col = ni * 8 + 2 * lt;
                    atomicAdd(&yr[col],     g * acc[mi][ni][half * 2 + 0]);
                    atomicAdd(&yr[col + 1], g * acc[mi][ni][half * 2 + 1]);
                }
            }
        }
    }
}

/* ---------------- losses ---------------- */
__global__ void losses_kernel(const float* __restrict__ Wp, float* __restrict__ out, int sbase)
{
    if (threadIdx.x != 0) return;
    const double z = g_zsum / (double)((size_t)NTOK * TE) * 0.001;
    double sb = 0.0;
    for (int e = 0; e < TE; ++e) {
        const double m = g_psum[e] / (double)NTOK;
        const double d = m - 1.0 / TE;
        sb += d * d;
    }
    sb /= TE;
    float Pn[TP][TE];
    for (int p = 0; p < TP; ++p) {
        float mx = -1e30f;
        for (int e = 0; e < TE; ++e) mx = fmaxf(mx, Wp[p * TE + e]);
        float s = 0.f;
        for (int e = 0; e < TE; ++e) { Pn[p][e] = expf(Wp[p * TE + e] - mx); s += Pn[p][e]; }
        const float inv = 1.f / s;
        for (int e = 0; e < TE; ++e) Pn[p][e] *= inv;
    }
    double acc = 0.0;
    for (int p = 0; p < TP; ++p)
        for (int q = 0; q < TP; ++q)
            if (p != q) {
                float d = 0.f;
                for (int e = 0; e < TE; ++e) d += Pn[p][e] * Pn[q][e];
                acc += (double)d;
            }
    const double spec = acc / (double)(TP * TP) * 0.1;
    out[sbase + 0] = (float)z;
    out[sbase + 1] = (float)sb;
    out[sbase + 2] = (float)spec;
}

/* ---------------- launch ---------------- */
extern "C" void kernel_launch(void* const* d_in, const int* in_sizes, int n_in,
                              void* d_out, int out_size)
{
    const float* x  = (const float*)d_in[0];
    const int*   pid= (const int*)  d_in[1];
    const float* Wr = (const float*)d_in[2];
    const float* Wp = (const float*)d_in[3];
    const float* W1 = (const float*)d_in[4];
    const float* W2 = (const float*)d_in[5];
    const float* W3 = (const float*)d_in[6];
    float* out = (float*)d_out;

    static int attr_done = 0;
    if (!attr_done) {
        cudaFuncSetAttribute(ffn1_kernel, cudaFuncAttributeMaxDynamicSharedMemorySize, FFN1_SMEM);
        cudaFuncSetAttribute(ffn2_kernel, cudaFuncAttributeMaxDynamicSharedMemorySize, FFN2_SMEM);
        attr_done = 1;
    }

    cudaMemsetAsync(d_out, 0, (size_t)out_size * sizeof(float));
    {
        dim3 gP(64, 64, 25), bP(32, 8);
        prep_kernel<<<gP, bP>>>(x, W1, W2, W3);
    }
    router_kernel<<<NTOK / 128, 256>>>(x, pid, Wr, Wp);
    prefix_kernel<<<1, 1>>>();

    dim3 gA(NTOK / 128, TH / 64, TE);
    ffn1_kernel<<<gA, 256, FFN1_SMEM>>>();

    dim3 gB(NTOK / 128, TD / 128, TE);
    ffn2_kernel<<<gB, 256, FFN2_SMEM>>>(out);

    losses_kernel<<<1, 1>>>(Wp, out, out_size - 3);
}

// round 10
// speedup vs baseline: 1.7997x; 1.0038x over previous
#include <cuda_runtime.h>
#include <cuda_fp16.h>
#include <math.h>
#include <stdint.h>

#define TB 8
#define TS 4096
#define TD 512
#define TH 2048
#define TE 8
#define TP 16
#define NTOK (TB*TS)          /* 32768 tokens */

/* ---------------- device state ---------------- */
__device__ int    g_counts[TE];
__device__ int    g_base[TE];
__device__ int    g_tok[TE * NTOK];     /* packed: token*2 + rank */
__device__ float  g_gate[TE * NTOK];
__device__ int    g_tmap[544];          /* (e<<16) | mtile */
__device__ int    g_ntiles;
__device__ double g_zsum;
__device__ double g_psum[TE];
__device__ __half g_H[(size_t)2 * NTOK * TH];     /* fp16 H scratch */
__device__ float  g_part[(size_t)2 * NTOK * TD];  /* rank-major partial y, 134 MB */
__device__ __half g_xh[(size_t)NTOK * TD];        /* fp16 x */
__device__ __half g_w1h[(size_t)TE * TH * TD];    /* W1^T: [e][h][d] (K-major) */
__device__ __half g_w3h[(size_t)TE * TH * TD];
__device__ __half g_w2h[(size_t)TE * TD * TH];    /* W2^T: [e][d][h] */

/* ---------------- helpers ---------------- */
__device__ __forceinline__ void mma_f16(
    float& c0, float& c1, float& c2, float& c3,
    unsigned a0, unsigned a1, unsigned a2, unsigned a3,
    unsigned b0, unsigned b1)
{
    asm volatile(
        "mma.sync.aligned.m16n8k16.row.col.f32.f16.f16.f32 "
        "{%0,%1,%2,%3}, {%4,%5,%6,%7}, {%8,%9}, {%0,%1,%2,%3};"
        : "+f"(c0), "+f"(c1), "+f"(c2), "+f"(c3)
        : "r"(a0), "r"(a1), "r"(a2), "r"(a3), "r"(b0), "r"(b1));
}

#define LDSM4(r0, r1, r2, r3, addr) \
    asm volatile("ldmatrix.sync.aligned.m8n8.x4.shared.b16 {%0,%1,%2,%3}, [%4];" \
                 : "=r"(r0), "=r"(r1), "=r"(r2), "=r"(r3) : "r"(addr))

#define CP16(dst, src) \
    asm volatile("cp.async.cg.shared.global [%0], [%1], 16;" :: "r"(dst), "l"(src))
#define CP_COMMIT() asm volatile("cp.async.commit_group;")
#define CP_WAIT0()  asm volatile("cp.async.wait_group 0;")

__device__ __forceinline__ unsigned sptr(const void* p) {
    return (unsigned)__cvta_generic_to_shared(p);
}

/* rows of 64 data halfs (128B) padded to 144B: conflict-free LDSM and STS phases */
#define ROWB 144

#define STG1   36864
#define HDR1   1024
#define FFN1_SMEM (HDR1 + 2 * STG1)
#define STG2   36864
#define HDR2   2048
#define FFN2_SMEM (HDR2 + 2 * STG2)

/* ---------------- prep: transpose+round weights to fp16, round x, zero state ---------------- */
__global__ __launch_bounds__(256) void prep_kernel(
    const float* __restrict__ x, const float* __restrict__ W1,
    const float* __restrict__ W2, const float* __restrict__ W3)
{
    const int m = blockIdx.z;
    const int tx = threadIdx.x, ty = threadIdx.y;
    if (m < 24) {
        const float* src; __half* dst; int R, C;
        if (m < 8)       { src = W1 + (size_t)m * TD * TH;        dst = g_w1h + (size_t)m * TH * TD;        R = TD; C = TH; }
        else if (m < 16) { src = W3 + (size_t)(m - 8) * TD * TH;  dst = g_w3h + (size_t)(m - 8) * TH * TD;  R = TD; C = TH; }
        else             { src = W2 + (size_t)(m - 16) * TH * TD; dst = g_w2h + (size_t)(m - 16) * TD * TH; R = TH; C = TD; }
        const int bx = blockIdx.x, by = blockIdx.y;
        if (bx * 32 >= C || by * 32 >= R) return;
        __shared__ float t[32][33];
        #pragma unroll
        for (int i = 0; i < 4; ++i)
            t[ty + 8 * i][tx] = src[(size_t)(by * 32 + ty + 8 * i) * C + bx * 32 + tx];
        __syncthreads();
        #pragma unroll
        for (int i = 0; i < 4; ++i)
            dst[(size_t)(bx * 32 + ty + 8 * i) * R + by * 32 + tx] = __float2half_rn(t[tx][ty + 8 * i]);
    } else {
        const int tid = ty * 32 + tx;
        const size_t nb = (size_t)blockIdx.y * 64 + blockIdx.x;   /* 0..4095 */
        if (nb == 0 && tid < TE) { g_counts[tid] = 0; g_psum[tid] = 0.0; if (tid == 0) g_zsum = 0.0; }
        const size_t NX8 = (size_t)NTOK * TD / 8;
        const size_t stride = (size_t)4096 * 256;
        const float4* x4 = (const float4*)x;
        for (size_t i = nb * 256 + tid; i < NX8; i += stride) {
            float4 v0 = x4[2 * i], v1 = x4[2 * i + 1];
            __half2* dst = (__half2*)(g_xh + i * 8);
            dst[0] = __floats2half2_rn(v0.x, v0.y);
            dst[1] = __floats2half2_rn(v0.z, v0.w);
            dst[2] = __floats2half2_rn(v1.x, v1.y);
            dst[3] = __floats2half2_rn(v1.z, v1.w);
        }
    }
}

/* ---------------- router (fp32; g_tok now packed token*2+rank) ---------------- */
__global__ __launch_bounds__(256) void router_kernel(
    const float* __restrict__ x, const int* __restrict__ pid,
    const float* __restrict__ Wr, const float* __restrict__ Wp)
{
    __shared__ float sWrT[TE * TD];
    __shared__ float sPsum[TE];
    __shared__ float sZsum;
    __shared__ int   sCnt[TE];
    __shared__ int   sGbase[TE];
    __shared__ unsigned char sE[256];
    __shared__ short sSlot[256];
    __shared__ float sG[256];

    const int tid = threadIdx.x;
    for (int idx = tid; idx < TD * TE; idx += 256) {
        int d = idx >> 3, e = idx & 7;
        sWrT[e * TD + d] = Wr[idx];
    }
    if (tid < TE) { sPsum[tid] = 0.f; sCnt[tid] = 0; }
    if (tid == 0) sZsum = 0.f;
    __syncthreads();

    const int warp = tid >> 5, lane = tid & 31;
    const int tok0 = blockIdx.x * 128 + warp * 16;

    for (int tt = 0; tt < 16; ++tt) {
        const int t = tok0 + tt;
        float acc[TE];
        #pragma unroll
        for (int e = 0; e < TE; ++e) acc[e] = 0.f;
        const float* xr = x + (size_t)t * TD;
        for (int i = lane; i < TD; i += 32) {
            float xv = xr[i];
            #pragma unroll
            for (int e = 0; e < TE; ++e)
                acc[e] = fmaf(xv, sWrT[e * TD + i], acc[e]);
        }
        #pragma unroll
        for (int off = 16; off >= 1; off >>= 1) {
            #pragma unroll
            for (int e = 0; e < TE; ++e)
                acc[e] += __shfl_down_sync(0xffffffffu, acc[e], off);
        }
        if (lane == 0) {
            const int b = t / TS;
            const int p = pid[b];
            float l[TE];
            float zs = 0.f, mx = -1e30f;
            #pragma unroll
            for (int e = 0; e < TE; ++e) {
                l[e] = acc[e] + Wp[p * TE + e];
                zs += l[e] * l[e];
                mx = fmaxf(mx, l[e]);
            }
            atomicAdd(&sZsum, zs);
            float s = 0.f, pr[TE];
            #pragma unroll
            for (int e = 0; e < TE; ++e) { pr[e] = expf(l[e] - mx); s += pr[e]; }
            const float inv = 1.f / s;
            #pragma unroll
            for (int e = 0; e < TE; ++e) atomicAdd(&sPsum[e], pr[e] * inv);
            int i0 = 0;
            #pragma unroll
            for (int e = 1; e < TE; ++e) if (l[e] > l[i0]) i0 = e;
            int i1 = (i0 == 0) ? 1 : 0;
            #pragma unroll
            for (int e = 0; e < TE; ++e) if (e != i0 && l[e] > l[i1]) i1 = e;
            const float e1 = expf(l[i1] - l[i0]);
            const float g0 = 1.f / (1.f + e1);
            const float g1 = e1 * g0;
            const int s0 = atomicAdd(&sCnt[i0], 1);
            const int s1 = atomicAdd(&sCnt[i1], 1);
            const int loc = (warp * 16 + tt) * 2;
            sE[loc]     = (unsigned char)i0; sSlot[loc]     = (short)s0; sG[loc]     = g0;
            sE[loc + 1] = (unsigned char)i1; sSlot[loc + 1] = (short)s1; sG[loc + 1] = g1;
        }
    }
    __syncthreads();
    if (tid < TE) {
        sGbase[tid] = atomicAdd(&g_counts[tid], sCnt[tid]);
        atomicAdd(&g_psum[tid], (double)sPsum[tid]);
    }
    if (tid == 0) atomicAdd(&g_zsum, (double)sZsum);
    __syncthreads();
    {
        const int e = sE[tid];
        const int pos = sGbase[e] + sSlot[tid];
        const int t = blockIdx.x * 128 + (tid >> 1);
        g_tok[e * NTOK + pos]  = (t << 1) | (tid & 1);   /* pack rank */
        g_gate[e * NTOK + pos] = sG[tid];
    }
}

/* ---------------- prefix + tile map ---------------- */
__global__ void prefix_kernel() {
    if (threadIdx.x == 0) {
        int s = 0, idx = 0;
        for (int e = 0; e < TE; ++e) {
            g_base[e] = s;
            const int cnt = g_counts[e];
            s += cnt;
            const int mt = (cnt + 127) >> 7;
            for (int m = 0; m < mt; ++m) g_tmap[idx++] = (e << 16) | m;
        }
        g_ntiles = idx;
    }
}

/* ================= FFN stage 1 (fp16 mma + ldmatrix, BK=64, 2-stage) ================= */
__global__ __launch_bounds__(256, 2) void ffn1_kernel()
{
    if (blockIdx.x >= g_ntiles) return;
    const int mp  = g_tmap[blockIdx.x];
    const int e   = mp >> 16;
    const int m0  = (mp & 0xffff) << 7;
    const int cnt = g_counts[e];
    const int n0   = blockIdx.y * 64;
    const int base = g_base[e];

    extern __shared__ char smc[];
    int* stok = (int*)smc;

    const int tid = threadIdx.x;
    if (tid < 128) {
        const int r = m0 + tid;
        stok[tid] = ((r < cnt) ? g_tok[e * NTOK + r] : g_tok[e * NTOK]) >> 1;
    }
    __syncthreads();

    const __half* W1e = g_w1h + (size_t)e * TH * TD;
    const __half* W3e = g_w3h + (size_t)e * TH * TD;

    const int warp = tid >> 5, lane = tid & 31;
    const int warp_m = warp & 3;     /* *32 */
    const int warp_n = warp >> 2;    /* *32 */
    const int lg = lane >> 2, lt = lane & 3;

    const uint32_t a_off = (uint32_t)(warp_m * 32 + (lane & 15)) * ROWB + (lane >> 4) * 16;
    const uint32_t b_row = (uint32_t)(warp_n * 32 + (lane & 7) + ((lane >> 4) << 3));
    const uint32_t b_off = b_row * ROWB + ((lane >> 3) & 1) * 16;

    auto issue = [&](int it, int stg) {
        const int k0 = it * 64;
        char* S = smc + HDR1 + stg * STG1;
        #pragma unroll
        for (int j = 0; j < 4; ++j) {
            const int q = tid + 256 * j;
            const int row = q >> 3, c = q & 7;
            CP16(sptr(S + row * ROWB + c * 16),
                 g_xh + (size_t)stok[row] * TD + k0 + c * 8);
        }
        #pragma unroll
        for (int j = 0; j < 2; ++j) {
            const int q = tid + 256 * j;
            const int row = q >> 3, c = q & 7;
            CP16(sptr(S + 18432 + row * ROWB + c * 16),
                 W1e + (size_t)(n0 + row) * TD + k0 + c * 8);
            CP16(sptr(S + 27648 + row * ROWB + c * 16),
                 W3e + (size_t)(n0 + row) * TD + k0 + c * 8);
        }
        CP_COMMIT();
    };

    float acc1[2][4][4], acc3[2][4][4];
    #pragma unroll
    for (int i = 0; i < 2; ++i)
        #pragma unroll
        for (int j = 0; j < 4; ++j)
            #pragma unroll
            for (int k = 0; k < 4; ++k) { acc1[i][j][k] = 0.f; acc3[i][j][k] = 0.f; }

    issue(0, 0);
    const int NIT = TD / 64;   /* 8 */

    #pragma unroll 1
    for (int it = 0; it < NIT; ++it) {
        CP_WAIT0();
        __syncthreads();
        if (it + 1 < NIT) issue(it + 1, (it + 1) & 1);

        const uint32_t Sb = sptr(smc + HDR1 + (it & 1) * STG1);
        const uint32_t Aa  = Sb + a_off;
        const uint32_t B1a = Sb + 18432 + b_off;
        const uint32_t B3a = Sb + 27648 + b_off;

        #pragma unroll
        for (int ks = 0; ks < 4; ++ks) {
            const uint32_t kb = ks * 32;
            unsigned a[2][4], b1f[4][2], b3f[4][2];
            LDSM4(a[0][0], a[0][1], a[0][2], a[0][3], Aa + kb);
            LDSM4(a[1][0], a[1][1], a[1][2], a[1][3], Aa + 16 * ROWB + kb);
            LDSM4(b1f[0][0], b1f[0][1], b1f[1][0], b1f[1][1], B1a + kb);
            LDSM4(b1f[2][0], b1f[2][1], b1f[3][0], b1f[3][1], B1a + 16 * ROWB + kb);
            LDSM4(b3f[0][0], b3f[0][1], b3f[1][0], b3f[1][1], B3a + kb);
            LDSM4(b3f[2][0], b3f[2][1], b3f[3][0], b3f[3][1], B3a + 16 * ROWB + kb);
            #pragma unroll
            for (int mi = 0; mi < 2; ++mi)
                #pragma unroll
                for (int ni = 0; ni < 4; ++ni) {
                    mma_f16(acc1[mi][ni][0], acc1[mi][ni][1], acc1[mi][ni][2], acc1[mi][ni][3],
                            a[mi][0], a[mi][1], a[mi][2], a[mi][3], b1f[ni][0], b1f[ni][1]);
                    mma_f16(acc3[mi][ni][0], acc3[mi][ni][1], acc3[mi][ni][2], acc3[mi][ni][3],
                            a[mi][0], a[mi][1], a[mi][2], a[mi][3], b3f[ni][0], b3f[ni][1]);
                }
        }
    }

    /* epilogue: h = (X@W1) * silu(X@W3), store fp16 */
    #pragma unroll
    for (int mi = 0; mi < 2; ++mi) {
        #pragma unroll
        for (int half = 0; half < 2; ++half) {
            const int rl = warp_m * 32 + mi * 16 + half * 8 + lg;
            const int r  = m0 + rl;
            if (r < cnt) {
                __half* hrow = g_H + (size_t)(base + r) * TH + n0 + warp_n * 32;
                #pragma unroll
                for (int ni = 0; ni < 4; ++ni) {
                    const float g1v = acc1[mi][ni][half * 2 + 0];
                    const float g1w = acc1[mi][ni][half * 2 + 1];
                    const float g3v = acc3[mi][ni][half * 2 + 0];
                    const float g3w = acc3[mi][ni][half * 2 + 1];
                    const float hx = g1v * (g3v / (1.f + expf(-g3v)));
                    const float hy = g1w * (g3w / (1.f + expf(-g3w)));
                    *(__half2*)(hrow + ni * 8 + 2 * lt) = __floats2half2_rn(hx, hy);
                }
            }
        }
    }
}

/* ================= FFN stage 2 (fp16 mma + ldmatrix, BK=64, 2-stage) =================
   Writes gate-scaled partials to g_part[rank][token] non-atomically. */
__global__ __launch_bounds__(256, 2) void ffn2_kernel()
{
    if (blockIdx.x >= g_ntiles) return;
    const int mp  = g_tmap[blockIdx.x];
    const int e   = mp >> 16;
    const int m0  = (mp & 0xffff) << 7;
    const int cnt = g_counts[e];
    const int n0   = blockIdx.y * 128;
    const int base = g_base[e];

    extern __shared__ char smc[];
    int*   sslot = (int*)smc;            /* 128: g_H row */
    int*   spack = (int*)(smc + 512);    /* 128: packed tok*2+rank */
    float* sgate = (float*)(smc + 1024); /* 128 */

    const int tid = threadIdx.x;
    if (tid < 128) {
        const int r = m0 + tid;
        const int rc = (r < cnt) ? r : (cnt - 1);
        sslot[tid] = base + rc;
        spack[tid] = g_tok[e * NTOK + rc];
        sgate[tid] = (r < cnt) ? g_gate[e * NTOK + r] : 0.f;
    }
    __syncthreads();

    const __half* W2e = g_w2h + (size_t)e * TD * TH;

    const int warp = tid >> 5, lane = tid & 31;
    const int warp_m = warp >> 2;    /* *64 */
    const int warp_n = warp & 3;     /* *32 */
    const int lg = lane >> 2, lt = lane & 3;

    const uint32_t a_off = (uint32_t)(warp_m * 64 + (lane & 15)) * ROWB + (lane >> 4) * 16;
    const uint32_t b_row = (uint32_t)(warp_n * 32 + (lane & 7) + ((lane >> 4) << 3));
    const uint32_t b_off = b_row * ROWB + ((lane >> 3) & 1) * 16;

    auto issue = [&](int it, int stg) {
        const int k0 = it * 64;
        char* S = smc + HDR2 + stg * STG2;
        #pragma unroll
        for (int j = 0; j < 4; ++j) {
            const int q = tid + 256 * j;
            const int row = q >> 3, c = q & 7;
            CP16(sptr(S + row * ROWB + c * 16),
                 g_H + (size_t)sslot[row] * TH + k0 + c * 8);
        }
        #pragma unroll
        for (int j = 0; j < 4; ++j) {
            const int q = tid + 256 * j;
            const int row = q >> 3, c = q & 7;
            CP16(sptr(S + 18432 + row * ROWB + c * 16),
                 W2e + (size_t)(n0 + row) * TH + k0 + c * 8);
        }
        CP_COMMIT();
    };

    float acc[4][4][4];
    #pragma unroll
    for (int i = 0; i < 4; ++i)
        #pragma unroll
        for (int j = 0; j < 4; ++j)
            #pragma unroll
            for (int k = 0; k < 4; ++k) acc[i][j][k] = 0.f;

    issue(0, 0);
    const int NIT = TH / 64;   /* 32 */

    #pragma unroll 1
    for (int it = 0; it < NIT; ++it) {
        CP_WAIT0();
        __syncthreads();
        if (it + 1 < NIT) issue(it + 1, (it + 1) & 1);

        const uint32_t Sb = sptr(smc + HDR2 + (it & 1) * STG2);
        const uint32_t Aa = Sb + a_off;
        const uint32_t Ba = Sb + 18432 + b_off;

        #pragma unroll
        for (int ks = 0; ks < 4; ++ks) {
            const uint32_t kb = ks * 32;
            unsigned a[4][4], b[4][2];
            LDSM4(a[0][0], a[0][1], a[0][2], a[0][3], Aa + kb);
            LDSM4(a[1][0], a[1][1], a[1][2], a[1][3], Aa + 16 * ROWB + kb);
            LDSM4(a[2][0], a[2][1], a[2][2], a[2][3], Aa + 32 * ROWB + kb);
            LDSM4(a[3][0], a[3][1], a[3][2], a[3][3], Aa + 48 * ROWB + kb);
            LDSM4(b[0][0], b[0][1], b[1][0], b[1][1], Ba + kb);
            LDSM4(b[2][0], b[2][1], b[3][0], b[3][1], Ba + 16 * ROWB + kb);
            #pragma unroll
            for (int mi = 0; mi < 4; ++mi)
                #pragma unroll
                for (int ni = 0; ni < 4; ++ni)
                    mma_f16(acc[mi][ni][0], acc[mi][ni][1], acc[mi][ni][2], acc[mi][ni][3],
                            a[mi][0], a[mi][1], a[mi][2], a[mi][3], b[ni][0], b[ni][1]);
        }
    }

    /* epilogue: non-atomic gate-scaled partial stores */
    #pragma unroll
    for (int mi = 0; mi < 4; ++mi) {
        #pragma unroll
        for (int half = 0; half < 2; ++half) {
            const int rl = warp_m * 64 + mi * 16 + half * 8 + lg;
            if (m0 + rl < cnt) {
                const int v = spack[rl];
                const float g = sgate[rl];
                float* yr = g_part + ((size_t)(v & 1) * NTOK + (v >> 1)) * TD
                          + n0 + warp_n * 32;
                #pragma unroll
                for (int ni = 0; ni < 4; ++ni) {
                    const int col = ni * 8 + 2 * lt;
                    float2 w;
                    w.x = g * acc[mi][ni][half * 2 + 0];
                    w.y = g * acc[mi][ni][half * 2 + 1];
                    *(float2*)(yr + col) = w;
                }
            }
        }
    }
}

/* ---------------- combine: y = part0 + part1 ---------------- */
__global__ __launch_bounds__(256) void combine_kernel(float* __restrict__ y)
{
    const size_t N4 = (size_t)NTOK * TD / 4;
    const size_t i = (size_t)blockIdx.x * 256 + threadIdx.x;
    if (i < N4) {
        const float4* p0 = (const float4*)g_part;
        const float4* p1 = p0 + N4;
        float4 a = p0[i], b = p1[i];
        float4 r;
        r.x = a.x + b.x; r.y = a.y + b.y; r.z = a.z + b.z; r.w = a.w + b.w;
        ((float4*)y)[i] = r;
    }
}

/* ---------------- losses ---------------- */
__global__ void losses_kernel(const float* __restrict__ Wp, float* __restrict__ out, int sbase)
{
    if (threadIdx.x != 0) return;
    const double z = g_zsum / (double)((size_t)NTOK * TE) * 0.001;
    double sb = 0.0;
    for (int e = 0; e < TE; ++e) {
        const double m = g_psum[e] / (double)NTOK;
        const double d = m - 1.0 / TE;
        sb += d * d;
    }
    sb /= TE;
    float Pn[TP][TE];
    for (int p = 0; p < TP; ++p) {
        float mx = -1e30f;
        for (int e = 0; e < TE; ++e) mx = fmaxf(mx, Wp[p * TE + e]);
        float s = 0.f;
        for (int e = 0; e < TE; ++e) { Pn[p][e] = expf(Wp[p * TE + e] - mx); s += Pn[p][e]; }
        const float inv = 1.f / s;
        for (int e = 0; e < TE; ++e) Pn[p][e] *= inv;
    }
    double acc = 0.0;
    for (int p = 0; p < TP; ++p)
        for (int q = 0; q < TP; ++q)
            if (p != q) {
                float d = 0.f;
                for (int e = 0; e < TE; ++e) d += Pn[p][e] * Pn[q][e];
                acc += (double)d;
            }
    const double spec = acc / (double)(TP * TP) * 0.1;
    out[sbase + 0] = (float)z;
    out[sbase + 1] = (float)sb;
    out[sbase + 2] = (float)spec;
}

/* ---------------- launch ---------------- */
extern "C" void kernel_launch(void* const* d_in, const int* in_sizes, int n_in,
                              void* d_out, int out_size)
{
    const float* x  = (const float*)d_in[0];
    const int*   pid= (const int*)  d_in[1];
    const float* Wr = (const float*)d_in[2];
    const float* Wp = (const float*)d_in[3];
    const float* W1 = (const float*)d_in[4];
    const float* W2 = (const float*)d_in[5];
    const float* W3 = (const float*)d_in[6];
    float* out = (float*)d_out;

    static int attr_done = 0;
    if (!attr_done) {
        cudaFuncSetAttribute(ffn1_kernel, cudaFuncAttributeMaxDynamicSharedMemorySize, FFN1_SMEM);
        cudaFuncSetAttribute(ffn2_kernel, cudaFuncAttributeMaxDynamicSharedMemorySize, FFN2_SMEM);
        attr_done = 1;
    }

    {
        dim3 gP(64, 64, 25), bP(32, 8);
        prep_kernel<<<gP, bP>>>(x, W1, W2, W3);
    }
    router_kernel<<<NTOK / 128, 256>>>(x, pid, Wr, Wp);
    prefix_kernel<<<1, 1>>>();

    dim3 gA(520, TH / 64, 1);
    ffn1_kernel<<<gA, 256, FFN1_SMEM>>>();

    dim3 gB(520, TD / 128, 1);
    ffn2_kernel<<<gB, 256, FFN2_SMEM>>>();

    combine_kernel<<<(NTOK * TD / 4 + 255) / 256, 256>>>(out);
    losses_kernel<<<1, 1>>>(Wp, out, out_size - 3);
}

// round 11
// speedup vs baseline: 1.8602x; 1.0336x over previous
#include <cuda_runtime.h>
#include <cuda_fp16.h>
#include <math.h>
#include <stdint.h>

#define TB 8
#define TS 4096
#define TD 512
#define TH 2048
#define TE 8
#define TP 16
#define NTOK (TB*TS)          /* 32768 tokens */

/* ---------------- device state ---------------- */
__device__ int    g_counts[TE];
__device__ int    g_base[TE];
__device__ int    g_tok[TE * NTOK];     /* packed: token*2 + rank */
__device__ float  g_gate[TE * NTOK];
__device__ int    g_tmap[544];          /* (e<<16) | mtile */
__device__ int    g_ntiles;
__device__ double g_zsum;
__device__ double g_psum[TE];
__device__ __half g_H[(size_t)2 * NTOK * TH];     /* fp16 H scratch */
__device__ float  g_part[(size_t)2 * NTOK * TD];  /* rank-major partial y */
__device__ __half g_xh[(size_t)NTOK * TD];        /* fp16 x */
__device__ __half g_w1h[(size_t)TE * TH * TD];    /* W1^T: [e][h][d] (K-major) */
__device__ __half g_w3h[(size_t)TE * TH * TD];
__device__ __half g_w2h[(size_t)TE * TD * TH];    /* W2^T: [e][d][h] */

/* ---------------- helpers ---------------- */
__device__ __forceinline__ void mma_f16(
    float& c0, float& c1, float& c2, float& c3,
    unsigned a0, unsigned a1, unsigned a2, unsigned a3,
    unsigned b0, unsigned b1)
{
    asm volatile(
        "mma.sync.aligned.m16n8k16.row.col.f32.f16.f16.f32 "
        "{%0,%1,%2,%3}, {%4,%5,%6,%7}, {%8,%9}, {%0,%1,%2,%3};"
        : "+f"(c0), "+f"(c1), "+f"(c2), "+f"(c3)
        : "r"(a0), "r"(a1), "r"(a2), "r"(a3), "r"(b0), "r"(b1));
}

#define LDSM4(r0, r1, r2, r3, addr) \
    asm volatile("ldmatrix.sync.aligned.m8n8.x4.shared.b16 {%0,%1,%2,%3}, [%4];" \
                 : "=r"(r0), "=r"(r1), "=r"(r2), "=r"(r3) : "r"(addr))

#define CP16(dst, src) \
    asm volatile("cp.async.cg.shared.global [%0], [%1], 16;" :: "r"(dst), "l"(src))
#define CP_COMMIT() asm volatile("cp.async.commit_group;")
#define CP_WAIT1()  asm volatile("cp.async.wait_group 1;")
#define CP_WAIT0()  asm volatile("cp.async.wait_group 0;")

__device__ __forceinline__ unsigned sptr(const void* p) {
    return (unsigned)__cvta_generic_to_shared(p);
}

/* rows of 64 data halfs (128B) padded to 144B: conflict-free LDSM and STS phases */
#define ROWB 144

#define STG1   36864
#define HDR1   1024
#define FFN1_SMEM (HDR1 + 3 * STG1)     /* 111616 B -> 2 CTAs/SM */
#define STG2   36864
#define HDR2   2048
#define FFN2_SMEM (HDR2 + 3 * STG2)     /* 112640 B -> 2 CTAs/SM */

/* ---------------- prep: transpose+round weights to fp16, round x, zero state ---------------- */
__global__ __launch_bounds__(256) void prep_kernel(
    const float* __restrict__ x, const float* __restrict__ W1,
    const float* __restrict__ W2, const float* __restrict__ W3)
{
    const int m = blockIdx.z;
    const int tx = threadIdx.x, ty = threadIdx.y;
    if (m < 24) {
        const float* src; __half* dst; int R, C;
        if (m < 8)       { src = W1 + (size_t)m * TD * TH;        dst = g_w1h + (size_t)m * TH * TD;        R = TD; C = TH; }
        else if (m < 16) { src = W3 + (size_t)(m - 8) * TD * TH;  dst = g_w3h + (size_t)(m - 8) * TH * TD;  R = TD; C = TH; }
        else             { src = W2 + (size_t)(m - 16) * TH * TD; dst = g_w2h + (size_t)(m - 16) * TD * TH; R = TH; C = TD; }
        const int bx = blockIdx.x, by = blockIdx.y;
        if (bx * 32 >= C || by * 32 >= R) return;
        __shared__ float t[32][33];
        #pragma unroll
        for (int i = 0; i < 4; ++i)
            t[ty + 8 * i][tx] = src[(size_t)(by * 32 + ty + 8 * i) * C + bx * 32 + tx];
        __syncthreads();
        #pragma unroll
        for (int i = 0; i < 4; ++i)
            dst[(size_t)(bx * 32 + ty + 8 * i) * R + by * 32 + tx] = __float2half_rn(t[tx][ty + 8 * i]);
    } else {
        const int tid = ty * 32 + tx;
        const size_t nb = (size_t)blockIdx.y * 64 + blockIdx.x;   /* 0..4095 */
        if (nb == 0 && tid < TE) { g_counts[tid] = 0; g_psum[tid] = 0.0; if (tid == 0) g_zsum = 0.0; }
        const size_t NX8 = (size_t)NTOK * TD / 8;
        const size_t stride = (size_t)4096 * 256;
        const float4* x4 = (const float4*)x;
        for (size_t i = nb * 256 + tid; i < NX8; i += stride) {
            float4 v0 = x4[2 * i], v1 = x4[2 * i + 1];
            __half2* dst = (__half2*)(g_xh + i * 8);
            dst[0] = __floats2half2_rn(v0.x, v0.y);
            dst[1] = __floats2half2_rn(v0.z, v0.w);
            dst[2] = __floats2half2_rn(v1.x, v1.y);
            dst[3] = __floats2half2_rn(v1.z, v1.w);
        }
    }
}

/* ---------------- router (fp32; g_tok packed token*2+rank) ---------------- */
__global__ __launch_bounds__(256) void router_kernel(
    const float* __restrict__ x, const int* __restrict__ pid,
    const float* __restrict__ Wr, const float* __restrict__ Wp)
{
    __shared__ float sWrT[TE * TD];
    __shared__ float sPsum[TE];
    __shared__ float sZsum;
    __shared__ int   sCnt[TE];
    __shared__ int   sGbase[TE];
    __shared__ unsigned char sE[256];
    __shared__ short sSlot[256];
    __shared__ float sG[256];

    const int tid = threadIdx.x;
    for (int idx = tid; idx < TD * TE; idx += 256) {
        int d = idx >> 3, e = idx & 7;
        sWrT[e * TD + d] = Wr[idx];
    }
    if (tid < TE) { sPsum[tid] = 0.f; sCnt[tid] = 0; }
    if (tid == 0) sZsum = 0.f;
    __syncthreads();

    const int warp = tid >> 5, lane = tid & 31;
    const int tok0 = blockIdx.x * 128 + warp * 16;

    for (int tt = 0; tt < 16; ++tt) {
        const int t = tok0 + tt;
        float acc[TE];
        #pragma unroll
        for (int e = 0; e < TE; ++e) acc[e] = 0.f;
        const float* xr = x + (size_t)t * TD;
        for (int i = lane; i < TD; i += 32) {
            float xv = xr[i];
            #pragma unroll
            for (int e = 0; e < TE; ++e)
                acc[e] = fmaf(xv, sWrT[e * TD + i], acc[e]);
        }
        #pragma unroll
        for (int off = 16; off >= 1; off >>= 1) {
            #pragma unroll
            for (int e = 0; e < TE; ++e)
                acc[e] += __shfl_down_sync(0xffffffffu, acc[e], off);
        }
        if (lane == 0) {
            const int b = t / TS;
            const int p = pid[b];
            float l[TE];
            float zs = 0.f, mx = -1e30f;
            #pragma unroll
            for (int e = 0; e < TE; ++e) {
                l[e] = acc[e] + Wp[p * TE + e];
                zs += l[e] * l[e];
                mx = fmaxf(mx, l[e]);
            }
            atomicAdd(&sZsum, zs);
            float s = 0.f, pr[TE];
            #pragma unroll
            for (int e = 0; e < TE; ++e) { pr[e] = expf(l[e] - mx); s += pr[e]; }
            const float inv = 1.f / s;
            #pragma unroll
            for (int e = 0; e < TE; ++e) atomicAdd(&sPsum[e], pr[e] * inv);
            int i0 = 0;
            #pragma unroll
            for (int e = 1; e < TE; ++e) if (l[e] > l[i0]) i0 = e;
            int i1 = (i0 == 0) ? 1 : 0;
            #pragma unroll
            for (int e = 0; e < TE; ++e) if (e != i0 && l[e] > l[i1]) i1 = e;
            const float e1 = expf(l[i1] - l[i0]);
            const float g0 = 1.f / (1.f + e1);
            const float g1 = e1 * g0;
            const int s0 = atomicAdd(&sCnt[i0], 1);
            const int s1 = atomicAdd(&sCnt[i1], 1);
            const int loc = (warp * 16 + tt) * 2;
            sE[loc]     = (unsigned char)i0; sSlot[loc]     = (short)s0; sG[loc]     = g0;
            sE[loc + 1] = (unsigned char)i1; sSlot[loc + 1] = (short)s1; sG[loc + 1] = g1;
        }
    }
    __syncthreads();
    if (tid < TE) {
        sGbase[tid] = atomicAdd(&g_counts[tid], sCnt[tid]);
        atomicAdd(&g_psum[tid], (double)sPsum[tid]);
    }
    if (tid == 0) atomicAdd(&g_zsum, (double)sZsum);
    __syncthreads();
    {
        const int e = sE[tid];
        const int pos = sGbase[e] + sSlot[tid];
        const int t = blockIdx.x * 128 + (tid >> 1);
        g_tok[e * NTOK + pos]  = (t << 1) | (tid & 1);
        g_gate[e * NTOK + pos] = sG[tid];
    }
}

/* ---------------- prefix + tile map ---------------- */
__global__ void prefix_kernel() {
    if (threadIdx.x == 0) {
        int s = 0, idx = 0;
        for (int e = 0; e < TE; ++e) {
            g_base[e] = s;
            const int cnt = g_counts[e];
            s += cnt;
            const int mt = (cnt + 127) >> 7;
            for (int m = 0; m < mt; ++m) g_tmap[idx++] = (e << 16) | m;
        }
        g_ntiles = idx;
    }
}

/* ================= FFN stage 1 (fp16 mma + ldmatrix, BK=64, 3-stage) ================= */
__global__ __launch_bounds__(256, 2) void ffn1_kernel()
{
    if (blockIdx.x >= g_ntiles) return;
    const int mp  = g_tmap[blockIdx.x];
    const int e   = mp >> 16;
    const int m0  = (mp & 0xffff) << 7;
    const int cnt = g_counts[e];
    const int n0   = blockIdx.y * 64;
    const int base = g_base[e];

    extern __shared__ char smc[];
    int* stok = (int*)smc;

    const int tid = threadIdx.x;
    if (tid < 128) {
        const int r = m0 + tid;
        stok[tid] = ((r < cnt) ? g_tok[e * NTOK + r] : g_tok[e * NTOK]) >> 1;
    }
    __syncthreads();

    const __half* W1e = g_w1h + (size_t)e * TH * TD;
    const __half* W3e = g_w3h + (size_t)e * TH * TD;

    const int warp = tid >> 5, lane = tid & 31;
    const int warp_m = warp & 3;     /* *32 */
    const int warp_n = warp >> 2;    /* *32 */
    const int lg = lane >> 2, lt = lane & 3;

    const uint32_t a_off = (uint32_t)(warp_m * 32 + (lane & 15)) * ROWB + (lane >> 4) * 16;
    const uint32_t b_row = (uint32_t)(warp_n * 32 + (lane & 7) + ((lane >> 4) << 3));
    const uint32_t b_off = b_row * ROWB + ((lane >> 3) & 1) * 16;

    auto issue = [&](int it, int stg) {
        const int k0 = it * 64;
        char* S = smc + HDR1 + stg * STG1;
        #pragma unroll
        for (int j = 0; j < 4; ++j) {
            const int q = tid + 256 * j;
            const int row = q >> 3, c = q & 7;
            CP16(sptr(S + row * ROWB + c * 16),
                 g_xh + (size_t)stok[row] * TD + k0 + c * 8);
        }
        #pragma unroll
        for (int j = 0; j < 2; ++j) {
            const int q = tid + 256 * j;
            const int row = q >> 3, c = q & 7;
            CP16(sptr(S + 18432 + row * ROWB + c * 16),
                 W1e + (size_t)(n0 + row) * TD + k0 + c * 8);
            CP16(sptr(S + 27648 + row * ROWB + c * 16),
                 W3e + (size_t)(n0 + row) * TD + k0 + c * 8);
        }
        CP_COMMIT();
    };

    float acc1[2][4][4], acc3[2][4][4];
    #pragma unroll
    for (int i = 0; i < 2; ++i)
        #pragma unroll
        for (int j = 0; j < 4; ++j)
            #pragma unroll
            for (int k = 0; k < 4; ++k) { acc1[i][j][k] = 0.f; acc3[i][j][k] = 0.f; }

    issue(0, 0);
    issue(1, 1);
    int sa = 0, sc = 2;
    const int NIT = TD / 64;   /* 8 */

    #pragma unroll 1
    for (int it = 0; it < NIT; ++it) {
        if (it < NIT - 1) { CP_WAIT1(); } else { CP_WAIT0(); }
        __syncthreads();

        const uint32_t Sb = sptr(smc + HDR1 + sa * STG1);
        const uint32_t Aa  = Sb + a_off;
        const uint32_t B1a = Sb + 18432 + b_off;
        const uint32_t B3a = Sb + 27648 + b_off;

        #pragma unroll
        for (int ks = 0; ks < 4; ++ks) {
            const uint32_t kb = ks * 32;
            unsigned a[2][4], b1f[4][2], b3f[4][2];
            LDSM4(a[0][0], a[0][1], a[0][2], a[0][3], Aa + kb);
            LDSM4(a[1][0], a[1][1], a[1][2], a[1][3], Aa + 16 * ROWB + kb);
            LDSM4(b1f[0][0], b1f[0][1], b1f[1][0], b1f[1][1], B1a + kb);
            LDSM4(b1f[2][0], b1f[2][1], b1f[3][0], b1f[3][1], B1a + 16 * ROWB + kb);
            LDSM4(b3f[0][0], b3f[0][1], b3f[1][0], b3f[1][1], B3a + kb);
            LDSM4(b3f[2][0], b3f[2][1], b3f[3][0], b3f[3][1], B3a + 16 * ROWB + kb);
            #pragma unroll
            for (int mi = 0; mi < 2; ++mi)
                #pragma unroll
                for (int ni = 0; ni < 4; ++ni) {
                    mma_f16(acc1[mi][ni][0], acc1[mi][ni][1], acc1[mi][ni][2], acc1[mi][ni][3],
                            a[mi][0], a[mi][1], a[mi][2], a[mi][3], b1f[ni][0], b1f[ni][1]);
                    mma_f16(acc3[mi][ni][0], acc3[mi][ni][1], acc3[mi][ni][2], acc3[mi][ni][3],
                            a[mi][0], a[mi][1], a[mi][2], a[mi][3], b3f[ni][0], b3f[ni][1]);
                }
        }

        if (it + 2 < NIT) issue(it + 2, sc);
        if (++sa == 3) sa = 0;
        if (++sc == 3) sc = 0;
    }

    /* epilogue: h = (X@W1) * silu(X@W3), store fp16 */
    #pragma unroll
    for (int mi = 0; mi < 2; ++mi) {
        #pragma unroll
        for (int half = 0; half < 2; ++half) {
            const int rl = warp_m * 32 + mi * 16 + half * 8 + lg;
            const int r  = m0 + rl;
            if (r < cnt) {
                __half* hrow = g_H + (size_t)(base + r) * TH + n0 + warp_n * 32;
                #pragma unroll
                for (int ni = 0; ni < 4; ++ni) {
                    const float g1v = acc1[mi][ni][half * 2 + 0];
                    const float g1w = acc1[mi][ni][half * 2 + 1];
                    const float g3v = acc3[mi][ni][half * 2 + 0];
                    const float g3w = acc3[mi][ni][half * 2 + 1];
                    const float hx = g1v * (g3v / (1.f + expf(-g3v)));
                    const float hy = g1w * (g3w / (1.f + expf(-g3w)));
                    *(__half2*)(hrow + ni * 8 + 2 * lt) = __floats2half2_rn(hx, hy);
                }
            }
        }
    }
}

/* ================= FFN stage 2 (fp16 mma + ldmatrix, BK=64, 3-stage) ================= */
__global__ __launch_bounds__(256, 2) void ffn2_kernel()
{
    if (blockIdx.x >= g_ntiles) return;
    const int mp  = g_tmap[blockIdx.x];
    const int e   = mp >> 16;
    const int m0  = (mp & 0xffff) << 7;
    const int cnt = g_counts[e];
    const int n0   = blockIdx.y * 128;
    const int base = g_base[e];

    extern __shared__ char smc[];
    int*   sslot = (int*)smc;            /* 128 */
    int*   spack = (int*)(smc + 512);    /* 128 */
    float* sgate = (float*)(smc + 1024); /* 128 */

    const int tid = threadIdx.x;
    if (tid < 128) {
        const int r = m0 + tid;
        const int rc = (r < cnt) ? r : (cnt - 1);
        sslot[tid] = base + rc;
        spack[tid] = g_tok[e * NTOK + rc];
        sgate[tid] = (r < cnt) ? g_gate[e * NTOK + r] : 0.f;
    }
    __syncthreads();

    const __half* W2e = g_w2h + (size_t)e * TD * TH;

    const int warp = tid >> 5, lane = tid & 31;
    const int warp_m = warp >> 2;    /* *64 */
    const int warp_n = warp & 3;     /* *32 */
    const int lg = lane >> 2, lt = lane & 3;

    const uint32_t a_off = (uint32_t)(warp_m * 64 + (lane & 15)) * ROWB + (lane >> 4) * 16;
    const uint32_t b_row = (uint32_t)(warp_n * 32 + (lane & 7) + ((lane >> 4) << 3));
    const uint32_t b_off = b_row * ROWB + ((lane >> 3) & 1) * 16;

    auto issue = [&](int it, int stg) {
        const int k0 = it * 64;
        char* S = smc + HDR2 + stg * STG2;
        #pragma unroll
        for (int j = 0; j < 4; ++j) {
            const int q = tid + 256 * j;
            const int row = q >> 3, c = q & 7;
            CP16(sptr(S + row * ROWB + c * 16),
                 g_H + (size_t)sslot[row] * TH + k0 + c * 8);
        }
        #pragma unroll
        for (int j = 0; j < 4; ++j) {
            const int q = tid + 256 * j;
            const int row = q >> 3, c = q & 7;
            CP16(sptr(S + 18432 + row * ROWB + c * 16),
                 W2e + (size_t)(n0 + row) * TH + k0 + c * 8);
        }
        CP_COMMIT();
    };

    float acc[4][4][4];
    #pragma unroll
    for (int i = 0; i < 4; ++i)
        #pragma unroll
        for (int j = 0; j < 4; ++j)
            #pragma unroll
            for (int k = 0; k < 4; ++k) acc[i][j][k] = 0.f;

    issue(0, 0);
    issue(1, 1);
    int sa = 0, sc = 2;
    const int NIT = TH / 64;   /* 32 */

    #pragma unroll 1
    for (int it = 0; it < NIT; ++it) {
        if (it < NIT - 1) { CP_WAIT1(); } else { CP_WAIT0(); }
        __syncthreads();

        const uint32_t Sb = sptr(smc + HDR2 + sa * STG2);
        const uint32_t Aa = Sb + a_off;
        const uint32_t Ba = Sb + 18432 + b_off;

        #pragma unroll
        for (int ks = 0; ks < 4; ++ks) {
            const uint32_t kb = ks * 32;
            unsigned a[4][4], b[4][2];
            LDSM4(a[0][0], a[0][1], a[0][2], a[0][3], Aa + kb);
            LDSM4(a[1][0], a[1][1], a[1][2], a[1][3], Aa + 16 * ROWB + kb);
            LDSM4(a[2][0], a[2][1], a[2][2], a[2][3], Aa + 32 * ROWB + kb);
            LDSM4(a[3][0], a[3][1], a[3][2], a[3][3], Aa + 48 * ROWB + kb);
            LDSM4(b[0][0], b[0][1], b[1][0], b[1][1], Ba + kb);
            LDSM4(b[2][0], b[2][1], b[3][0], b[3][1], Ba + 16 * ROWB + kb);
            #pragma unroll
            for (int mi = 0; mi < 4; ++mi)
                #pragma unroll
                for (int ni = 0; ni < 4; ++ni)
                    mma_f16(acc[mi][ni][0], acc[mi][ni][1], acc[mi][ni][2], acc[mi][ni][3],
                            a[mi][0], a[mi][1], a[mi][2], a[mi][3], b[ni][0], b[ni][1]);
        }

        if (it + 2 < NIT) issue(it + 2, sc);
        if (++sa == 3) sa = 0;
        if (++sc == 3) sc = 0;
    }

    /* epilogue: non-atomic gate-scaled partial stores */
    #pragma unroll
    for (int mi = 0; mi < 4; ++mi) {
        #pragma unroll
        for (int half = 0; half < 2; ++half) {
            const int rl = warp_m * 64 + mi * 16 + half * 8 + lg;
            if (m0 + rl < cnt) {
                const int v = spack[rl];
                const float g = sgate[rl];
                float* yr = g_part + ((size_t)(v & 1) * NTOK + (v >> 1)) * TD
                          + n0 + warp_n * 32;
                #pragma unroll
                for (int ni = 0; ni < 4; ++ni) {
                    const int col = ni * 8 + 2 * lt;
                    float2 w;
                    w.x = g * acc[mi][ni][half * 2 + 0];
                    w.y = g * acc[mi][ni][half * 2 + 1];
                    *(float2*)(yr + col) = w;
                }
            }
        }
    }
}

/* ---------------- combine: y = part0 + part1 ---------------- */
__global__ __launch_bounds__(256) void combine_kernel(float* __restrict__ y)
{
    const size_t N4 = (size_t)NTOK * TD / 4;
    const size_t i = (size_t)blockIdx.x * 256 + threadIdx.x;
    if (i < N4) {
        const float4* p0 = (const float4*)g_part;
        const float4* p1 = p0 + N4;
        float4 a = p0[i], b = p1[i];
        float4 r;
        r.x = a.x + b.x; r.y = a.y + b.y; r.z = a.z + b.z; r.w = a.w + b.w;
        ((float4*)y)[i] = r;
    }
}

/* ---------------- losses ---------------- */
__global__ void losses_kernel(const float* __restrict__ Wp, float* __restrict__ out, int sbase)
{
    if (threadIdx.x != 0) return;
    const double z = g_zsum / (double)((size_t)NTOK * TE) * 0.001;
    double sb = 0.0;
    for (int e = 0; e < TE; ++e) {
        const double m = g_psum[e] / (double)NTOK;
        const double d = m - 1.0 / TE;
        sb += d * d;
    }
    sb /= TE;
    float Pn[TP][TE];
    for (int p = 0; p < TP; ++p) {
        float mx = -1e30f;
        for (int e = 0; e < TE; ++e) mx = fmaxf(mx, Wp[p * TE + e]);
        float s = 0.f;
        for (int e = 0; e < TE; ++e) { Pn[p][e] = expf(Wp[p * TE + e] - mx); s += Pn[p][e]; }
        const float inv = 1.f / s;
        for (int e = 0; e < TE; ++e) Pn[p][e] *= inv;
    }
    double acc = 0.0;
    for (int p = 0; p < TP; ++p)
        for (int q = 0; q < TP; ++q)
            if (p != q) {
                float d = 0.f;
                for (int e = 0; e < TE; ++e) d += Pn[p][e] * Pn[q][e];
                acc += (double)d;
            }
    const double spec = acc / (double)(TP * TP) * 0.1;
    out[sbase + 0] = (float)z;
    out[sbase + 1] = (float)sb;
    out[sbase + 2] = (float)spec;
}

/* ---------------- launch ---------------- */
extern "C" void kernel_launch(void* const* d_in, const int* in_sizes, int n_in,
                              void* d_out, int out_size)
{
    const float* x  = (const float*)d_in[0];
    const int*   pid= (const int*)  d_in[1];
    const float* Wr = (const float*)d_in[2];
    const float* Wp = (const float*)d_in[3];
    const float* W1 = (const float*)d_in[4];
    const float* W2 = (const float*)d_in[5];
    const float* W3 = (const float*)d_in[6];
    float* out = (float*)d_out;

    static int attr_done = 0;
    if (!attr_done) {
        cudaFuncSetAttribute(ffn1_kernel, cudaFuncAttributeMaxDynamicSharedMemorySize, FFN1_SMEM);
        cudaFuncSetAttribute(ffn2_kernel, cudaFuncAttributeMaxDynamicSharedMemorySize, FFN2_SMEM);
        attr_done = 1;
    }

    {
        dim3 gP(64, 64, 25), bP(32, 8);
        prep_kernel<<<gP, bP>>>(x, W1, W2, W3);
    }
    router_kernel<<<NTOK / 128, 256>>>(x, pid, Wr, Wp);
    prefix_kernel<<<1, 1>>>();

    dim3 gA(520, TH / 64, 1);
    ffn1_kernel<<<gA, 256, FFN1_SMEM>>>();

    dim3 gB(520, TD / 128, 1);
    ffn2_kernel<<<gB, 256, FFN2_SMEM>>>();

    combine_kernel<<<(NTOK * TD / 4 + 255) / 256, 256>>>(out);
    losses_kernel<<<1, 1>>>(Wp, out, out_size - 3);
}

// round 12
// speedup vs baseline: 1.8809x; 1.0112x over previous
#include <cuda_runtime.h>
#include <cuda_fp16.h>
#include <math.h>
#include <stdint.h>

#define TB 8
#define TS 4096
#define TD 512
#define TH 2048
#define TE 8
#define TP 16
#define NTOK (TB*TS)          /* 32768 tokens */

/* ---------------- device state ---------------- */
__device__ int    g_counts[TE];
__device__ int    g_base[TE];
__device__ int    g_tok[TE * NTOK];     /* packed: token*2 + rank */
__device__ float  g_gate[TE * NTOK];
__device__ int    g_tmap[544];          /* (e<<16) | mtile */
__device__ int    g_ntiles;
__device__ double g_zsum;
__device__ double g_psum[TE];
__device__ __half g_H[(size_t)2 * NTOK * TH];     /* fp16 H scratch */
__device__ __half g_xh[(size_t)NTOK * TD];        /* fp16 x */
__device__ __half g_w1h[(size_t)TE * TH * TD];    /* W1^T: [e][h][d] (K-major) */
__device__ __half g_w3h[(size_t)TE * TH * TD];
__device__ __half g_w2h[(size_t)TE * TD * TH];    /* W2^T: [e][d][h] */

/* ---------------- helpers ---------------- */
__device__ __forceinline__ void mma_f16(
    float& c0, float& c1, float& c2, float& c3,
    unsigned a0, unsigned a1, unsigned a2, unsigned a3,
    unsigned b0, unsigned b1)
{
    asm volatile(
        "mma.sync.aligned.m16n8k16.row.col.f32.f16.f16.f32 "
        "{%0,%1,%2,%3}, {%4,%5,%6,%7}, {%8,%9}, {%0,%1,%2,%3};"
        : "+f"(c0), "+f"(c1), "+f"(c2), "+f"(c3)
        : "r"(a0), "r"(a1), "r"(a2), "r"(a3), "r"(b0), "r"(b1));
}

#define LDSM4(r0, r1, r2, r3, addr) \
    asm volatile("ldmatrix.sync.aligned.m8n8.x4.shared.b16 {%0,%1,%2,%3}, [%4];" \
                 : "=r"(r0), "=r"(r1), "=r"(r2), "=r"(r3) : "r"(addr))

#define CP16(dst, src) \
    asm volatile("cp.async.cg.shared.global [%0], [%1], 16;" :: "r"(dst), "l"(src))
#define CP_COMMIT() asm volatile("cp.async.commit_group;")
#define CP_WAIT1()  asm volatile("cp.async.wait_group 1;")
#define CP_WAIT0()  asm volatile("cp.async.wait_group 0;")

__device__ __forceinline__ unsigned sptr(const void* p) {
    return (unsigned)__cvta_generic_to_shared(p);
}

/* rows of 64 data halfs (128B) padded to 144B: conflict-free LDSM and STS phases */
#define ROWB 144

#define STG1   36864
#define HDR1   1024
#define FFN1_SMEM (HDR1 + 3 * STG1)     /* 111616 B -> 2 CTAs/SM */
#define STG2   36864
#define HDR2   2048
#define FFN2_SMEM (HDR2 + 3 * STG2)     /* 112640 B -> 2 CTAs/SM */

/* ---------------- prep: transpose+round weights to fp16, round x, zero state ---------------- */
__global__ __launch_bounds__(256) void prep_kernel(
    const float* __restrict__ x, const float* __restrict__ W1,
    const float* __restrict__ W2, const float* __restrict__ W3)
{
    const int m = blockIdx.z;
    const int tx = threadIdx.x, ty = threadIdx.y;
    if (m < 24) {
        const float* src; __half* dst; int R, C;
        if (m < 8)       { src = W1 + (size_t)m * TD * TH;        dst = g_w1h + (size_t)m * TH * TD;        R = TD; C = TH; }
        else if (m < 16) { src = W3 + (size_t)(m - 8) * TD * TH;  dst = g_w3h + (size_t)(m - 8) * TH * TD;  R = TD; C = TH; }
        else             { src = W2 + (size_t)(m - 16) * TH * TD; dst = g_w2h + (size_t)(m - 16) * TD * TH; R = TH; C = TD; }
        const int bx = blockIdx.x, by = blockIdx.y;
        if (bx * 32 >= C || by * 32 >= R) return;
        __shared__ float t[32][33];
        #pragma unroll
        for (int i = 0; i < 4; ++i)
            t[ty + 8 * i][tx] = src[(size_t)(by * 32 + ty + 8 * i) * C + bx * 32 + tx];
        __syncthreads();
        #pragma unroll
        for (int i = 0; i < 4; ++i)
            dst[(size_t)(bx * 32 + ty + 8 * i) * R + by * 32 + tx] = __float2half_rn(t[tx][ty + 8 * i]);
    } else {
        const int tid = ty * 32 + tx;
        const size_t nb = (size_t)blockIdx.y * 64 + blockIdx.x;   /* 0..4095 */
        if (nb == 0 && tid < TE) { g_counts[tid] = 0; g_psum[tid] = 0.0; if (tid == 0) g_zsum = 0.0; }
        const size_t NX8 = (size_t)NTOK * TD / 8;
        const size_t stride = (size_t)4096 * 256;
        const float4* x4 = (const float4*)x;
        for (size_t i = nb * 256 + tid; i < NX8; i += stride) {
            float4 v0 = x4[2 * i], v1 = x4[2 * i + 1];
            __half2* dst = (__half2*)(g_xh + i * 8);
            dst[0] = __floats2half2_rn(v0.x, v0.y);
            dst[1] = __floats2half2_rn(v0.z, v0.w);
            dst[2] = __floats2half2_rn(v1.x, v1.y);
            dst[3] = __floats2half2_rn(v1.z, v1.w);
        }
    }
}

/* ---------------- router (fp32; per-warp register accumulation of loss sums) ---------------- */
__global__ __launch_bounds__(256) void router_kernel(
    const float* __restrict__ x, const int* __restrict__ pid,
    const float* __restrict__ Wr, const float* __restrict__ Wp)
{
    __shared__ float sWrT[TE * TD];
    __shared__ float sPsum[TE];
    __shared__ float sZsum;
    __shared__ int   sCnt[TE];
    __shared__ int   sGbase[TE];
    __shared__ unsigned char sE[256];
    __shared__ short sSlot[256];
    __shared__ float sG[256];

    const int tid = threadIdx.x;
    for (int idx = tid; idx < TD * TE; idx += 256) {
        int d = idx >> 3, e = idx & 7;
        sWrT[e * TD + d] = Wr[idx];
    }
    if (tid < TE) { sPsum[tid] = 0.f; sCnt[tid] = 0; }
    if (tid == 0) sZsum = 0.f;
    __syncthreads();

    const int warp = tid >> 5, lane = tid & 31;
    const int tok0 = blockIdx.x * 128 + warp * 16;

    float rpsum[TE];
    #pragma unroll
    for (int e = 0; e < TE; ++e) rpsum[e] = 0.f;
    float rzs = 0.f;

    for (int tt = 0; tt < 16; ++tt) {
        const int t = tok0 + tt;
        float acc[TE];
        #pragma unroll
        for (int e = 0; e < TE; ++e) acc[e] = 0.f;
        const float* xr = x + (size_t)t * TD;
        for (int i = lane; i < TD; i += 32) {
            float xv = xr[i];
            #pragma unroll
            for (int e = 0; e < TE; ++e)
                acc[e] = fmaf(xv, sWrT[e * TD + i], acc[e]);
        }
        #pragma unroll
        for (int off = 16; off >= 1; off >>= 1) {
            #pragma unroll
            for (int e = 0; e < TE; ++e)
                acc[e] += __shfl_down_sync(0xffffffffu, acc[e], off);
        }
        if (lane == 0) {
            const int b = t / TS;
            const int p = pid[b];
            float l[TE];
            float mx = -1e30f;
            #pragma unroll
            for (int e = 0; e < TE; ++e) {
                l[e] = acc[e] + Wp[p * TE + e];
                rzs += l[e] * l[e];
                mx = fmaxf(mx, l[e]);
            }
            float s = 0.f, pr[TE];
            #pragma unroll
            for (int e = 0; e < TE; ++e) { pr[e] = expf(l[e] - mx); s += pr[e]; }
            const float inv = 1.f / s;
            #pragma unroll
            for (int e = 0; e < TE; ++e) rpsum[e] += pr[e] * inv;
            int i0 = 0;
            #pragma unroll
            for (int e = 1; e < TE; ++e) if (l[e] > l[i0]) i0 = e;
            int i1 = (i0 == 0) ? 1 : 0;
            #pragma unroll
            for (int e = 0; e < TE; ++e) if (e != i0 && l[e] > l[i1]) i1 = e;
            const float e1 = expf(l[i1] - l[i0]);
            const float g0 = 1.f / (1.f + e1);
            const float g1 = e1 * g0;
            const int s0 = atomicAdd(&sCnt[i0], 1);
            const int s1 = atomicAdd(&sCnt[i1], 1);
            const int loc = (warp * 16 + tt) * 2;
            sE[loc]     = (unsigned char)i0; sSlot[loc]     = (short)s0; sG[loc]     = g0;
            sE[loc + 1] = (unsigned char)i1; sSlot[loc + 1] = (short)s1; sG[loc + 1] = g1;
        }
    }
    if (lane == 0) {
        #pragma unroll
        for (int e = 0; e < TE; ++e) atomicAdd(&sPsum[e], rpsum[e]);
        atomicAdd(&sZsum, rzs);
    }
    __syncthreads();
    if (tid < TE) {
        sGbase[tid] = atomicAdd(&g_counts[tid], sCnt[tid]);
        atomicAdd(&g_psum[tid], (double)sPsum[tid]);
    }
    if (tid == 0) atomicAdd(&g_zsum, (double)sZsum);
    __syncthreads();
    {
        const int e = sE[tid];
        const int pos = sGbase[e] + sSlot[tid];
        const int t = blockIdx.x * 128 + (tid >> 1);
        g_tok[e * NTOK + pos]  = (t << 1) | (tid & 1);
        g_gate[e * NTOK + pos] = sG[tid];
    }
}

/* ---------------- prefix + tile map + losses (fused; both tiny, deps satisfied) ---------------- */
__global__ void prefix_losses_kernel(const float* __restrict__ Wp,
                                     float* __restrict__ out, int sbase)
{
    if (threadIdx.x != 0) return;
    int s = 0, idx = 0;
    for (int e = 0; e < TE; ++e) {
        g_base[e] = s;
        const int cnt = g_counts[e];
        s += cnt;
        const int mt = (cnt + 127) >> 7;
        for (int m = 0; m < mt; ++m) g_tmap[idx++] = (e << 16) | m;
    }
    g_ntiles = idx;

    const double z = g_zsum / (double)((size_t)NTOK * TE) * 0.001;
    double sb = 0.0;
    for (int e = 0; e < TE; ++e) {
        const double m = g_psum[e] / (double)NTOK;
        const double d = m - 1.0 / TE;
        sb += d * d;
    }
    sb /= TE;
    float Pn[TP][TE];
    for (int p = 0; p < TP; ++p) {
        float mx = -1e30f;
        for (int e = 0; e < TE; ++e) mx = fmaxf(mx, Wp[p * TE + e]);
        float ss = 0.f;
        for (int e = 0; e < TE; ++e) { Pn[p][e] = expf(Wp[p * TE + e] - mx); ss += Pn[p][e]; }
        const float inv = 1.f / ss;
        for (int e = 0; e < TE; ++e) Pn[p][e] *= inv;
    }
    double acc = 0.0;
    for (int p = 0; p < TP; ++p)
        for (int q = 0; q < TP; ++q)
            if (p != q) {
                float d = 0.f;
                for (int e = 0; e < TE; ++e) d += Pn[p][e] * Pn[q][e];
                acc += (double)d;
            }
    const double spec = acc / (double)(TP * TP) * 0.1;
    out[sbase + 0] = (float)z;
    out[sbase + 1] = (float)sb;
    out[sbase + 2] = (float)spec;
}

/* ================= FFN stage 1 (fp16 mma + ldmatrix, BK=64, 3-stage) ================= */
__global__ __launch_bounds__(256, 2) void ffn1_kernel()
{
    if (blockIdx.x >= g_ntiles) return;
    const int mp  = g_tmap[blockIdx.x];
    const int e   = mp >> 16;
    const int m0  = (mp & 0xffff) << 7;
    const int cnt = g_counts[e];
    const int n0   = blockIdx.y * 64;
    const int base = g_base[e];

    extern __shared__ char smc[];
    int* stok = (int*)smc;

    const int tid = threadIdx.x;
    if (tid < 128) {
        const int r = m0 + tid;
        stok[tid] = ((r < cnt) ? g_tok[e * NTOK + r] : g_tok[e * NTOK]) >> 1;
    }
    __syncthreads();

    const __half* W1e = g_w1h + (size_t)e * TH * TD;
    const __half* W3e = g_w3h + (size_t)e * TH * TD;

    const int warp = tid >> 5, lane = tid & 31;
    const int warp_m = warp & 3;     /* *32 */
    const int warp_n = warp >> 2;    /* *32 */
    const int lg = lane >> 2, lt = lane & 3;

    const uint32_t a_off = (uint32_t)(warp_m * 32 + (lane & 15)) * ROWB + (lane >> 4) * 16;
    const uint32_t b_row = (uint32_t)(warp_n * 32 + (lane & 7) + ((lane >> 4) << 3));
    const uint32_t b_off = b_row * ROWB + ((lane >> 3) & 1) * 16;

    auto issue = [&](int it, int stg) {
        const int k0 = it * 64;
        char* S = smc + HDR1 + stg * STG1;
        #pragma unroll
        for (int j = 0; j < 4; ++j) {
            const int q = tid + 256 * j;
            const int row = q >> 3, c = q & 7;
            CP16(sptr(S + row * ROWB + c * 16),
                 g_xh + (size_t)stok[row] * TD + k0 + c * 8);
        }
        #pragma unroll
        for (int j = 0; j < 2; ++j) {
            const int q = tid + 256 * j;
            const int row = q >> 3, c = q & 7;
            CP16(sptr(S + 18432 + row * ROWB + c * 16),
                 W1e + (size_t)(n0 + row) * TD + k0 + c * 8);
            CP16(sptr(S + 27648 + row * ROWB + c * 16),
                 W3e + (size_t)(n0 + row) * TD + k0 + c * 8);
        }
        CP_COMMIT();
    };

    float acc1[2][4][4], acc3[2][4][4];
    #pragma unroll
    for (int i = 0; i < 2; ++i)
        #pragma unroll
        for (int j = 0; j < 4; ++j)
            #pragma unroll
            for (int k = 0; k < 4; ++k) { acc1[i][j][k] = 0.f; acc3[i][j][k] = 0.f; }

    issue(0, 0);
    issue(1, 1);
    int sa = 0, sc = 2;
    const int NIT = TD / 64;   /* 8 */

    #pragma unroll 1
    for (int it = 0; it < NIT; ++it) {
        if (it < NIT - 1) { CP_WAIT1(); } else { CP_WAIT0(); }
        __syncthreads();

        const uint32_t Sb = sptr(smc + HDR1 + sa * STG1);
        const uint32_t Aa  = Sb + a_off;
        const uint32_t B1a = Sb + 18432 + b_off;
        const uint32_t B3a = Sb + 27648 + b_off;

        #pragma unroll
        for (int ks = 0; ks < 4; ++ks) {
            const uint32_t kb = ks * 32;
            unsigned a[2][4], b1f[4][2], b3f[4][2];
            LDSM4(a[0][0], a[0][1], a[0][2], a[0][3], Aa + kb);
            LDSM4(a[1][0], a[1][1], a[1][2], a[1][3], Aa + 16 * ROWB + kb);
            LDSM4(b1f[0][0], b1f[0][1], b1f[1][0], b1f[1][1], B1a + kb);
            LDSM4(b1f[2][0], b1f[2][1], b1f[3][0], b1f[3][1], B1a + 16 * ROWB + kb);
            LDSM4(b3f[0][0], b3f[0][1], b3f[1][0], b3f[1][1], B3a + kb);
            LDSM4(b3f[2][0], b3f[2][1], b3f[3][0], b3f[3][1], B3a + 16 * ROWB + kb);
            #pragma unroll
            for (int mi = 0; mi < 2; ++mi)
                #pragma unroll
                for (int ni = 0; ni < 4; ++ni) {
                    mma_f16(acc1[mi][ni][0], acc1[mi][ni][1], acc1[mi][ni][2], acc1[mi][ni][3],
                            a[mi][0], a[mi][1], a[mi][2], a[mi][3], b1f[ni][0], b1f[ni][1]);
                    mma_f16(acc3[mi][ni][0], acc3[mi][ni][1], acc3[mi][ni][2], acc3[mi][ni][3],
                            a[mi][0], a[mi][1], a[mi][2], a[mi][3], b3f[ni][0], b3f[ni][1]);
                }
        }

        if (it + 2 < NIT) issue(it + 2, sc);
        if (++sa == 3) sa = 0;
        if (++sc == 3) sc = 0;
    }

    /* epilogue: h = (X@W1) * silu(X@W3), store fp16 */
    #pragma unroll
    for (int mi = 0; mi < 2; ++mi) {
        #pragma unroll
        for (int half = 0; half < 2; ++half) {
            const int rl = warp_m * 32 + mi * 16 + half * 8 + lg;
            const int r  = m0 + rl;
            if (r < cnt) {
                __half* hrow = g_H + (size_t)(base + r) * TH + n0 + warp_n * 32;
                #pragma unroll
                for (int ni = 0; ni < 4; ++ni) {
                    const float g1v = acc1[mi][ni][half * 2 + 0];
                    const float g1w = acc1[mi][ni][half * 2 + 1];
                    const float g3v = acc3[mi][ni][half * 2 + 0];
                    const float g3w = acc3[mi][ni][half * 2 + 1];
                    const float hx = g1v * (g3v / (1.f + expf(-g3v)));
                    const float hy = g1w * (g3w / (1.f + expf(-g3w)));
                    *(__half2*)(hrow + ni * 8 + 2 * lt) = __floats2half2_rn(hx, hy);
                }
            }
        }
    }
}

/* ================= FFN stage 2 (fp16 mma + ldmatrix, BK=64, 3-stage) =================
   Atomic fp32 epilogue directly into y (R8 path — measured faster than partials+combine). */
__global__ __launch_bounds__(256, 2) void ffn2_kernel(float* __restrict__ y)
{
    if (blockIdx.x >= g_ntiles) return;
    const int mp  = g_tmap[blockIdx.x];
    const int e   = mp >> 16;
    const int m0  = (mp & 0xffff) << 7;
    const int cnt = g_counts[e];
    const int n0   = blockIdx.y * 128;
    const int base = g_base[e];

    extern __shared__ char smc[];
    int*   sslot = (int*)smc;            /* 128 */
    int*   stokT = (int*)(smc + 512);    /* 128 */
    float* sgate = (float*)(smc + 1024); /* 128 */

    const int tid = threadIdx.x;
    if (tid < 128) {
        const int r = m0 + tid;
        const int rc = (r < cnt) ? r : (cnt - 1);
        sslot[tid] = base + rc;
        stokT[tid] = g_tok[e * NTOK + rc] >> 1;
        sgate[tid] = (r < cnt) ? g_gate[e * NTOK + r] : 0.f;
    }
    __syncthreads();

    const __half* W2e = g_w2h + (size_t)e * TD * TH;

    const int warp = tid >> 5, lane = tid & 31;
    const int warp_m = warp >> 2;    /* *64 */
    const int warp_n = warp & 3;     /* *32 */
    const int lg = lane >> 2, lt = lane & 3;

    const uint32_t a_off = (uint32_t)(warp_m * 64 + (lane & 15)) * ROWB + (lane >> 4) * 16;
    const uint32_t b_row = (uint32_t)(warp_n * 32 + (lane & 7) + ((lane >> 4) << 3));
    const uint32_t b_off = b_row * ROWB + ((lane >> 3) & 1) * 16;

    auto issue = [&](int it, int stg) {
        const int k0 = it * 64;
        char* S = smc + HDR2 + stg * STG2;
        #pragma unroll
        for (int j = 0; j < 4; ++j) {
            const int q = tid + 256 * j;
            const int row = q >> 3, c = q & 7;
            CP16(sptr(S + row * ROWB + c * 16),
                 g_H + (size_t)sslot[row] * TH + k0 + c * 8);
        }
        #pragma unroll
        for (int j = 0; j < 4; ++j) {
            const int q = tid + 256 * j;
            const int row = q >> 3, c = q & 7;
            CP16(sptr(S + 18432 + row * ROWB + c * 16),
                 W2e + (size_t)(n0 + row) * TH + k0 + c * 8);
        }
        CP_COMMIT();
    };

    float acc[4][4][4];
    #pragma unroll
    for (int i = 0; i < 4; ++i)
        #pragma unroll
        for (int j = 0; j < 4; ++j)
            #pragma unroll
            for (int k = 0; k < 4; ++k) acc[i][j][k] = 0.f;

    issue(0, 0);
    issue(1, 1);
    int sa = 0, sc = 2;
    const int NIT = TH / 64;   /* 32 */

    #pragma unroll 1
    for (int it = 0; it < NIT; ++it) {
        if (it < NIT - 1) { CP_WAIT1(); } else { CP_WAIT0(); }
        __syncthreads();

        const uint32_t Sb = sptr(smc + HDR2 + sa * STG2);
        const uint32_t Aa = Sb + a_off;
        const uint32_t Ba = Sb + 18432 + b_off;

        #pragma unroll
        for (int ks = 0; ks < 4; ++ks) {
            const uint32_t kb = ks * 32;
            unsigned a[4][4], b[4][2];
            LDSM4(a[0][0], a[0][1], a[0][2], a[0][3], Aa + kb);
            LDSM4(a[1][0], a[1][1], a[1][2], a[1][3], Aa + 16 * ROWB + kb);
            LDSM4(a[2][0], a[2][1], a[2][2], a[2][3], Aa + 32 * ROWB + kb);
            LDSM4(a[3][0], a[3][1], a[3][2], a[3][3], Aa + 48 * ROWB + kb);
            LDSM4(b[0][0], b[0][1], b[1][0], b[1][1], Ba + kb);
            LDSM4(b[2][0], b[2][1], b[3][0], b[3][1], Ba + 16 * ROWB + kb);
            #pragma unroll
            for (int mi = 0; mi < 4; ++mi)
                #pragma unroll
                for (int ni = 0; ni < 4; ++ni)
                    mma_f16(acc[mi][ni][0], acc[mi][ni][1], acc[mi][ni][2], acc[mi][ni][3],
                            a[mi][0], a[mi][1], a[mi][2], a[mi][3], b[ni][0], b[ni][1]);
        }

        if (it + 2 < NIT) issue(it + 2, sc);
        if (++sa == 3) sa = 0;
        if (++sc == 3) sc = 0;
    }

    #pragma unroll
    for (int mi = 0; mi < 4; ++mi) {
        #pragma unroll
        for (int half = 0; half < 2; ++half) {
            const int rl = warp_m * 64 + mi * 16 + half * 8 + lg;
            if (m0 + rl < cnt) {
                const int t = stokT[rl];
                const float g = sgate[rl];
                float* yr = y + (size_t)t * TD + n0 + warp_n * 32;
                #pragma unroll
                for (int ni = 0; ni < 4; ++ni) {
                    const int col = ni * 8 + 2 * lt;
                    atomicAdd(&yr[col],     g * acc[mi][ni][half * 2 + 0]);
                    atomicAdd(&yr[col + 1], g * acc[mi][ni][half * 2 + 1]);
                }
            }
        }
    }
}

/* ---------------- launch ---------------- */
extern "C" void kernel_launch(void* const* d_in, const int* in_sizes, int n_in,
                              void* d_out, int out_size)
{
    const float* x  = (const float*)d_in[0];
    const int*   pid= (const int*)  d_in[1];
    const float* Wr = (const float*)d_in[2];
    const float* Wp = (const float*)d_in[3];
    const float* W1 = (const float*)d_in[4];
    const float* W2 = (const float*)d_in[5];
    const float* W3 = (const float*)d_in[6];
    float* out = (float*)d_out;

    static int attr_done = 0;
    if (!attr_done) {
        cudaFuncSetAttribute(ffn1_kernel, cudaFuncAttributeMaxDynamicSharedMemorySize, FFN1_SMEM);
        cudaFuncSetAttribute(ffn2_kernel, cudaFuncAttributeMaxDynamicSharedMemorySize, FFN2_SMEM);
        attr_done = 1;
    }

    cudaMemsetAsync(d_out, 0, (size_t)out_size * sizeof(float));
    {
        dim3 gP(64, 64, 25), bP(32, 8);
        prep_kernel<<<gP, bP>>>(x, W1, W2, W3);
    }
    router_kernel<<<NTOK / 128, 256>>>(x, pid, Wr, Wp);
    prefix_losses_kernel<<<1, 1>>>(Wp, out, out_size - 3);

    dim3 gA(520, TH / 64, 1);
    ffn1_kernel<<<gA, 256, FFN1_SMEM>>>();

    dim3 gB(520, TD / 128, 1);
    ffn2_kernel<<<gB, 256, FFN2_SMEM>>>(out);
}

// round 13
// speedup vs baseline: 1.9011x; 1.0107x over previous
#include <cuda_runtime.h>
#include <cuda_fp16.h>
#include <math.h>
#include <stdint.h>

#define TB 8
#define TS 4096
#define TD 512
#define TH 2048
#define TE 8
#define TP 16
#define NTOK (TB*TS)          /* 32768 tokens */

/* ---------------- device state ---------------- */
struct Acc { int counts[TE]; double psum[TE]; double zsum; };
__device__ Acc    g_acc;                /* zeroed by host memset each launch */
__device__ int    g_base[TE];
__device__ int    g_tok[TE * NTOK];     /* packed: token*2 + rank */
__device__ float  g_gate[TE * NTOK];
__device__ int    g_tmap[544];          /* (e<<16) | mtile */
__device__ int    g_ntiles;
__device__ __half g_H[(size_t)2 * NTOK * TH];     /* fp16 H scratch */
__device__ __half g_xh[(size_t)NTOK * TD];        /* fp16 x */
__device__ __half g_w1h[(size_t)TE * TH * TD];    /* W1^T: [e][h][d] (K-major) */
__device__ __half g_w3h[(size_t)TE * TH * TD];
__device__ __half g_w2h[(size_t)TE * TD * TH];    /* W2^T: [e][d][h] */

/* ---------------- helpers ---------------- */
__device__ __forceinline__ void mma_f16(
    float& c0, float& c1, float& c2, float& c3,
    unsigned a0, unsigned a1, unsigned a2, unsigned a3,
    unsigned b0, unsigned b1)
{
    asm volatile(
        "mma.sync.aligned.m16n8k16.row.col.f32.f16.f16.f32 "
        "{%0,%1,%2,%3}, {%4,%5,%6,%7}, {%8,%9}, {%0,%1,%2,%3};"
        : "+f"(c0), "+f"(c1), "+f"(c2), "+f"(c3)
        : "r"(a0), "r"(a1), "r"(a2), "r"(a3), "r"(b0), "r"(b1));
}

#define LDSM4(r0, r1, r2, r3, addr) \
    asm volatile("ldmatrix.sync.aligned.m8n8.x4.shared.b16 {%0,%1,%2,%3}, [%4];" \
                 : "=r"(r0), "=r"(r1), "=r"(r2), "=r"(r3) : "r"(addr))

#define CP16(dst, src) \
    asm volatile("cp.async.cg.shared.global [%0], [%1], 16;" :: "r"(dst), "l"(src))
#define CP_COMMIT() asm volatile("cp.async.commit_group;")
#define CP_WAIT1()  asm volatile("cp.async.wait_group 1;")
#define CP_WAIT0()  asm volatile("cp.async.wait_group 0;")

__device__ __forceinline__ unsigned sptr(const void* p) {
    return (unsigned)__cvta_generic_to_shared(p);
}

/* rows of 64 data halfs (128B) padded to 144B: conflict-free LDSM and STS phases */
#define ROWB 144

#define STG1   36864
#define HDR1   1024
#define FFN1_SMEM (HDR1 + 3 * STG1)     /* 111616 B -> 2 CTAs/SM */
#define STG2   36864
#define HDR2   2048
#define FFN2_SMEM (HDR2 + 3 * STG2)     /* 112640 B -> 2 CTAs/SM */

/* ============ fused prep + router ============
   z=0           : router (blocks with by<4; block id = by*64+bx, 256 blocks)
   z=1..24       : weight transpose+cvt (m = z-1)
   z=25          : x convert (all 4096 xy blocks)
   Router blocks dispatch first and overlap with the bandwidth-bound prep blocks. */
__global__ __launch_bounds__(256) void prep_router_kernel(
    const float* __restrict__ x, const float* __restrict__ W1,
    const float* __restrict__ W2, const float* __restrict__ W3,
    const int* __restrict__ pid, const float* __restrict__ Wr,
    const float* __restrict__ Wp)
{
    const int z = blockIdx.z;
    const int tx = threadIdx.x, ty = threadIdx.y;
    const int tid = ty * 32 + tx;

    if (z == 0) {
        /* ---------------- router ---------------- */
        if (blockIdx.y >= 4) return;
        const int blk = blockIdx.y * 64 + blockIdx.x;   /* 0..255 */

        __shared__ float sWrT[TE * TD];
        __shared__ float sPsum[TE];
        __shared__ float sZsum;
        __shared__ int   sCnt[TE];
        __shared__ int   sGbase[TE];
        __shared__ unsigned char sE[256];
        __shared__ short sSlot[256];
        __shared__ float sG[256];

        for (int idx = tid; idx < TD * TE; idx += 256) {
            int d = idx >> 3, e = idx & 7;
            sWrT[e * TD + d] = Wr[idx];
        }
        if (tid < TE) { sPsum[tid] = 0.f; sCnt[tid] = 0; }
        if (tid == 0) sZsum = 0.f;
        __syncthreads();

        const int warp = tid >> 5, lane = tid & 31;
        const int tok0 = blk * 128 + warp * 16;

        float rpsum[TE];
        #pragma unroll
        for (int e = 0; e < TE; ++e) rpsum[e] = 0.f;
        float rzs = 0.f;

        for (int tt = 0; tt < 16; ++tt) {
            const int t = tok0 + tt;
            float acc[TE];
            #pragma unroll
            for (int e = 0; e < TE; ++e) acc[e] = 0.f;
            const float* xr = x + (size_t)t * TD;
            for (int i = lane; i < TD; i += 32) {
                float xv = xr[i];
                #pragma unroll
                for (int e = 0; e < TE; ++e)
                    acc[e] = fmaf(xv, sWrT[e * TD + i], acc[e]);
            }
            #pragma unroll
            for (int off = 16; off >= 1; off >>= 1) {
                #pragma unroll
                for (int e = 0; e < TE; ++e)
                    acc[e] += __shfl_down_sync(0xffffffffu, acc[e], off);
            }
            if (lane == 0) {
                const int b = t / TS;
                const int p = pid[b];
                float l[TE];
                float mx = -1e30f;
                #pragma unroll
                for (int e = 0; e < TE; ++e) {
                    l[e] = acc[e] + Wp[p * TE + e];
                    rzs += l[e] * l[e];
                    mx = fmaxf(mx, l[e]);
                }
                float s = 0.f, pr[TE];
                #pragma unroll
                for (int e = 0; e < TE; ++e) { pr[e] = expf(l[e] - mx); s += pr[e]; }
                const float inv = 1.f / s;
                #pragma unroll
                for (int e = 0; e < TE; ++e) rpsum[e] += pr[e] * inv;
                int i0 = 0;
                #pragma unroll
                for (int e = 1; e < TE; ++e) if (l[e] > l[i0]) i0 = e;
                int i1 = (i0 == 0) ? 1 : 0;
                #pragma unroll
                for (int e = 0; e < TE; ++e) if (e != i0 && l[e] > l[i1]) i1 = e;
                const float e1 = expf(l[i1] - l[i0]);
                const float g0 = 1.f / (1.f + e1);
                const float g1 = e1 * g0;
                const int s0 = atomicAdd(&sCnt[i0], 1);
                const int s1 = atomicAdd(&sCnt[i1], 1);
                const int loc = (warp * 16 + tt) * 2;
                sE[loc]     = (unsigned char)i0; sSlot[loc]     = (short)s0; sG[loc]     = g0;
                sE[loc + 1] = (unsigned char)i1; sSlot[loc + 1] = (short)s1; sG[loc + 1] = g1;
            }
        }
        if (lane == 0) {
            #pragma unroll
            for (int e = 0; e < TE; ++e) atomicAdd(&sPsum[e], rpsum[e]);
            atomicAdd(&sZsum, rzs);
        }
        __syncthreads();
        if (tid < TE) {
            sGbase[tid] = atomicAdd(&g_acc.counts[tid], sCnt[tid]);
            atomicAdd(&g_acc.psum[tid], (double)sPsum[tid]);
        }
        if (tid == 0) atomicAdd(&g_acc.zsum, (double)sZsum);
        __syncthreads();
        {
            const int e = sE[tid];
            const int pos = sGbase[e] + sSlot[tid];
            const int t = blk * 128 + (tid >> 1);
            g_tok[e * NTOK + pos]  = (t << 1) | (tid & 1);
            g_gate[e * NTOK + pos] = sG[tid];
        }
    } else if (z <= 24) {
        /* ---------------- weight transpose + fp16 round ---------------- */
        const int m = z - 1;
        const float* src; __half* dst; int R, C;
        if (m < 8)       { src = W1 + (size_t)m * TD * TH;        dst = g_w1h + (size_t)m * TH * TD;        R = TD; C = TH; }
        else if (m < 16) { src = W3 + (size_t)(m - 8) * TD * TH;  dst = g_w3h + (size_t)(m - 8) * TH * TD;  R = TD; C = TH; }
        else             { src = W2 + (size_t)(m - 16) * TH * TD; dst = g_w2h + (size_t)(m - 16) * TD * TH; R = TH; C = TD; }
        const int bx = blockIdx.x, by = blockIdx.y;
        if (bx * 32 >= C || by * 32 >= R) return;
        __shared__ float t[32][33];
        #pragma unroll
        for (int i = 0; i < 4; ++i)
            t[ty + 8 * i][tx] = src[(size_t)(by * 32 + ty + 8 * i) * C + bx * 32 + tx];
        __syncthreads();
        #pragma unroll
        for (int i = 0; i < 4; ++i)
            dst[(size_t)(bx * 32 + ty + 8 * i) * R + by * 32 + tx] = __float2half_rn(t[tx][ty + 8 * i]);
    } else {
        /* ---------------- x -> fp16 ---------------- */
        const size_t nb = (size_t)blockIdx.y * 64 + blockIdx.x;   /* 0..4095 */
        const size_t NX8 = (size_t)NTOK * TD / 8;
        const size_t stride = (size_t)4096 * 256;
        const float4* x4 = (const float4*)x;
        for (size_t i = nb * 256 + tid; i < NX8; i += stride) {
            float4 v0 = x4[2 * i], v1 = x4[2 * i + 1];
            __half2* dst = (__half2*)(g_xh + i * 8);
            dst[0] = __floats2half2_rn(v0.x, v0.y);
            dst[1] = __floats2half2_rn(v0.z, v0.w);
            dst[2] = __floats2half2_rn(v1.x, v1.y);
            dst[3] = __floats2half2_rn(v1.z, v1.w);
        }
    }
}

/* ---------------- prefix + tile map + losses ---------------- */
__global__ void prefix_losses_kernel(const float* __restrict__ Wp,
                                     float* __restrict__ out, int sbase)
{
    if (threadIdx.x != 0) return;
    int s = 0, idx = 0;
    for (int e = 0; e < TE; ++e) {
        g_base[e] = s;
        const int cnt = g_acc.counts[e];
        s += cnt;
        const int mt = (cnt + 127) >> 7;
        for (int m = 0; m < mt; ++m) g_tmap[idx++] = (e << 16) | m;
    }
    g_ntiles = idx;

    const double z = g_acc.zsum / (double)((size_t)NTOK * TE) * 0.001;
    double sb = 0.0;
    for (int e = 0; e < TE; ++e) {
        const double m = g_acc.psum[e] / (double)NTOK;
        const double d = m - 1.0 / TE;
        sb += d * d;
    }
    sb /= TE;
    float Pn[TP][TE];
    for (int p = 0; p < TP; ++p) {
        float mx = -1e30f;
        for (int e = 0; e < TE; ++e) mx = fmaxf(mx, Wp[p * TE + e]);
        float ss = 0.f;
        for (int e = 0; e < TE; ++e) { Pn[p][e] = expf(Wp[p * TE + e] - mx); ss += Pn[p][e]; }
        const float inv = 1.f / ss;
        for (int e = 0; e < TE; ++e) Pn[p][e] *= inv;
    }
    double acc = 0.0;
    for (int p = 0; p < TP; ++p)
        for (int q = 0; q < TP; ++q)
            if (p != q) {
                float d = 0.f;
                for (int e = 0; e < TE; ++e) d += Pn[p][e] * Pn[q][e];
                acc += (double)d;
            }
    const double spec = acc / (double)(TP * TP) * 0.1;
    out[sbase + 0] = (float)z;
    out[sbase + 1] = (float)sb;
    out[sbase + 2] = (float)spec;
}

/* ================= FFN stage 1 (fp16 mma + ldmatrix, BK=64, 3-stage) ================= */
__global__ __launch_bounds__(256, 2) void ffn1_kernel()
{
    if (blockIdx.x >= g_ntiles) return;
    const int mp  = g_tmap[blockIdx.x];
    const int e   = mp >> 16;
    const int m0  = (mp & 0xffff) << 7;
    const int cnt = g_acc.counts[e];
    const int n0   = blockIdx.y * 64;
    const int base = g_base[e];

    extern __shared__ char smc[];
    int* stok = (int*)smc;

    const int tid = threadIdx.x;
    if (tid < 128) {
        const int r = m0 + tid;
        stok[tid] = ((r < cnt) ? g_tok[e * NTOK + r] : g_tok[e * NTOK]) >> 1;
    }
    __syncthreads();

    const __half* W1e = g_w1h + (size_t)e * TH * TD;
    const __half* W3e = g_w3h + (size_t)e * TH * TD;

    const int warp = tid >> 5, lane = tid & 31;
    const int warp_m = warp & 3;     /* *32 */
    const int warp_n = warp >> 2;    /* *32 */
    const int lg = lane >> 2, lt = lane & 3;

    const uint32_t a_off = (uint32_t)(warp_m * 32 + (lane & 15)) * ROWB + (lane >> 4) * 16;
    const uint32_t b_row = (uint32_t)(warp_n * 32 + (lane & 7) + ((lane >> 4) << 3));
    const uint32_t b_off = b_row * ROWB + ((lane >> 3) & 1) * 16;

    auto issue = [&](int it, int stg) {
        const int k0 = it * 64;
        char* S = smc + HDR1 + stg * STG1;
        #pragma unroll
        for (int j = 0; j < 4; ++j) {
            const int q = tid + 256 * j;
            const int row = q >> 3, c = q & 7;
            CP16(sptr(S + row * ROWB + c * 16),
                 g_xh + (size_t)stok[row] * TD + k0 + c * 8);
        }
        #pragma unroll
        for (int j = 0; j < 2; ++j) {
            const int q = tid + 256 * j;
            const int row = q >> 3, c = q & 7;
            CP16(sptr(S + 18432 + row * ROWB + c * 16),
                 W1e + (size_t)(n0 + row) * TD + k0 + c * 8);
            CP16(sptr(S + 27648 + row * ROWB + c * 16),
                 W3e + (size_t)(n0 + row) * TD + k0 + c * 8);
        }
        CP_COMMIT();
    };

    float acc1[2][4][4], acc3[2][4][4];
    #pragma unroll
    for (int i = 0; i < 2; ++i)
        #pragma unroll
        for (int j = 0; j < 4; ++j)
            #pragma unroll
            for (int k = 0; k < 4; ++k) { acc1[i][j][k] = 0.f; acc3[i][j][k] = 0.f; }

    issue(0, 0);
    issue(1, 1);
    int sa = 0, sc = 2;
    const int NIT = TD / 64;   /* 8 */

    #pragma unroll 1
    for (int it = 0; it < NIT; ++it) {
        if (it < NIT - 1) { CP_WAIT1(); } else { CP_WAIT0(); }
        __syncthreads();

        const uint32_t Sb = sptr(smc + HDR1 + sa * STG1);
        const uint32_t Aa  = Sb + a_off;
        const uint32_t B1a = Sb + 18432 + b_off;
        const uint32_t B3a = Sb + 27648 + b_off;

        #pragma unroll
        for (int ks = 0; ks < 4; ++ks) {
            const uint32_t kb = ks * 32;
            unsigned a[2][4], b1f[4][2], b3f[4][2];
            LDSM4(a[0][0], a[0][1], a[0][2], a[0][3], Aa + kb);
            LDSM4(a[1][0], a[1][1], a[1][2], a[1][3], Aa + 16 * ROWB + kb);
            LDSM4(b1f[0][0], b1f[0][1], b1f[1][0], b1f[1][1], B1a + kb);
            LDSM4(b1f[2][0], b1f[2][1], b1f[3][0], b1f[3][1], B1a + 16 * ROWB + kb);
            LDSM4(b3f[0][0], b3f[0][1], b3f[1][0], b3f[1][1], B3a + kb);
            LDSM4(b3f[2][0], b3f[2][1], b3f[3][0], b3f[3][1], B3a + 16 * ROWB + kb);
            #pragma unroll
            for (int mi = 0; mi < 2; ++mi)
                #pragma unroll
                for (int ni = 0; ni < 4; ++ni) {
                    mma_f16(acc1[mi][ni][0], acc1[mi][ni][1], acc1[mi][ni][2], acc1[mi][ni][3],
                            a[mi][0], a[mi][1], a[mi][2], a[mi][3], b1f[ni][0], b1f[ni][1]);
                    mma_f16(acc3[mi][ni][0], acc3[mi][ni][1], acc3[mi][ni][2], acc3[mi][ni][3],
                            a[mi][0], a[mi][1], a[mi][2], a[mi][3], b3f[ni][0], b3f[ni][1]);
                }
        }

        if (it + 2 < NIT) issue(it + 2, sc);
        if (++sa == 3) sa = 0;
        if (++sc == 3) sc = 0;
    }

    /* epilogue: h = (X@W1) * silu(X@W3), store fp16 */
    #pragma unroll
    for (int mi = 0; mi < 2; ++mi) {
        #pragma unroll
        for (int half = 0; half < 2; ++half) {
            const int rl = warp_m * 32 + mi * 16 + half * 8 + lg;
            const int r  = m0 + rl;
            if (r < cnt) {
                __half* hrow = g_H + (size_t)(base + r) * TH + n0 + warp_n * 32;
                #pragma unroll
                for (int ni = 0; ni < 4; ++ni) {
                    const float g1v = acc1[mi][ni][half * 2 + 0];
                    const float g1w = acc1[mi][ni][half * 2 + 1];
                    const float g3v = acc3[mi][ni][half * 2 + 0];
                    const float g3w = acc3[mi][ni][half * 2 + 1];
                    const float hx = g1v * (g3v / (1.f + expf(-g3v)));
                    const float hy = g1w * (g3w / (1.f + expf(-g3w)));
                    *(__half2*)(hrow + ni * 8 + 2 * lt) = __floats2half2_rn(hx, hy);
                }
            }
        }
    }
}

/* ================= FFN stage 2 (fp16 mma + ldmatrix, BK=64, 3-stage, atomic epilogue) ================= */
__global__ __launch_bounds__(256, 2) void ffn2_kernel(float* __restrict__ y)
{
    if (blockIdx.x >= g_ntiles) return;
    const int mp  = g_tmap[blockIdx.x];
    const int e   = mp >> 16;
    const int m0  = (mp & 0xffff) << 7;
    const int cnt = g_acc.counts[e];
    const int n0   = blockIdx.y * 128;
    const int base = g_base[e];

    extern __shared__ char smc[];
    int*   sslot = (int*)smc;            /* 128 */
    int*   stokT = (int*)(smc + 512);    /* 128 */
    float* sgate = (float*)(smc + 1024); /* 128 */

    const int tid = threadIdx.x;
    if (tid < 128) {
        const int r = m0 + tid;
        const int rc = (r < cnt) ? r : (cnt - 1);
        sslot[tid] = base + rc;
        stokT[tid] = g_tok[e * NTOK + rc] >> 1;
        sgate[tid] = (r < cnt) ? g_gate[e * NTOK + r] : 0.f;
    }
    __syncthreads();

    const __half* W2e = g_w2h + (size_t)e * TD * TH;

    const int warp = tid >> 5, lane = tid & 31;
    const int warp_m = warp >> 2;    /* *64 */
    const int warp_n = warp & 3;     /* *32 */
    const int lg = lane >> 2, lt = lane & 3;

    const uint32_t a_off = (uint32_t)(warp_m * 64 + (lane & 15)) * ROWB + (lane >> 4) * 16;
    const uint32_t b_row = (uint32_t)(warp_n * 32 + (lane & 7) + ((lane >> 4) << 3));
    const uint32_t b_off = b_row * ROWB + ((lane >> 3) & 1) * 16;

    auto issue = [&](int it, int stg) {
        const int k0 = it * 64;
        char* S = smc + HDR2 + stg * STG2;
        #pragma unroll
        for (int j = 0; j < 4; ++j) {
            const int q = tid + 256 * j;
            const int row = q >> 3, c = q & 7;
            CP16(sptr(S + row * ROWB + c * 16),
                 g_H + (size_t)sslot[row] * TH + k0 + c * 8);
        }
        #pragma unroll
        for (int j = 0; j < 4; ++j) {
            const int q = tid + 256 * j;
            const int row = q >> 3, c = q & 7;
            CP16(sptr(S + 18432 + row * ROWB + c * 16),
                 W2e + (size_t)(n0 + row) * TH + k0 + c * 8);
        }
        CP_COMMIT();
    };

    float acc[4][4][4];
    #pragma unroll
    for (int i = 0; i < 4; ++i)
        #pragma unroll
        for (int j = 0; j < 4; ++j)
            #pragma unroll
            for (int k = 0; k < 4; ++k) acc[i][j][k] = 0.f;

    issue(0, 0);
    issue(1, 1);
    int sa = 0, sc = 2;
    const int NIT = TH / 64;   /* 32 */

    #pragma unroll 1
    for (int it = 0; it < NIT; ++it) {
        if (it < NIT - 1) { CP_WAIT1(); } else { CP_WAIT0(); }
        __syncthreads();

        const uint32_t Sb = sptr(smc + HDR2 + sa * STG2);
        const uint32_t Aa = Sb + a_off;
        const uint32_t Ba = Sb + 18432 + b_off;

        #pragma unroll
        for (int ks = 0; ks < 4; ++ks) {
            const uint32_t kb = ks * 32;
            unsigned a[4][4], b[4][2];
            LDSM4(a[0][0], a[0][1], a[0][2], a[0][3], Aa + kb);
            LDSM4(a[1][0], a[1][1], a[1][2], a[1][3], Aa + 16 * ROWB + kb);
            LDSM4(a[2][0], a[2][1], a[2][2], a[2][3], Aa + 32 * ROWB + kb);
            LDSM4(a[3][0], a[3][1], a[3][2], a[3][3], Aa + 48 * ROWB + kb);
            LDSM4(b[0][0], b[0][1], b[1][0], b[1][1], Ba + kb);
            LDSM4(b[2][0], b[2][1], b[3][0], b[3][1], Ba + 16 * ROWB + kb);
            #pragma unroll
            for (int mi = 0; mi < 4; ++mi)
                #pragma unroll
                for (int ni = 0; ni < 4; ++ni)
                    mma_f16(acc[mi][ni][0], acc[mi][ni][1], acc[mi][ni][2], acc[mi][ni][3],
                            a[mi][0], a[mi][1], a[mi][2], a[mi][3], b[ni][0], b[ni][1]);
        }

        if (it + 2 < NIT) issue(it + 2, sc);
        if (++sa == 3) sa = 0;
        if (++sc == 3) sc = 0;
    }

    #pragma unroll
    for (int mi = 0; mi < 4; ++mi) {
        #pragma unroll
        for (int half = 0; half < 2; ++half) {
            const int rl = warp_m * 64 + mi * 16 + half * 8 + lg;
            if (m0 + rl < cnt) {
                const int t = stokT[rl];
                const float g = sgate[rl];
                float* yr = y + (size_t)t * TD + n0 + warp_n * 32;
                #pragma unroll
                for (int ni = 0; ni < 4; ++ni) {
                    const int col = ni * 8 + 2 * lt;
                    atomicAdd(&yr[col],     g * acc[mi][ni][half * 2 + 0]);
                    atomicAdd(&yr[col + 1], g * acc[mi][ni][half * 2 + 1]);
                }
            }
        }
    }
}

/* ---------------- launch ---------------- */
extern "C" void kernel_launch(void* const* d_in, const int* in_sizes, int n_in,
                              void* d_out, int out_size)
{
    const float* x  = (const float*)d_in[0];
    const int*   pid= (const int*)  d_in[1];
    const float* Wr = (const float*)d_in[2];
    const float* Wp = (const float*)d_in[3];
    const float* W1 = (const float*)d_in[4];
    const float* W2 = (const float*)d_in[5];
    const float* W3 = (const float*)d_in[6];
    float* out = (float*)d_out;

    static void* accAddr = nullptr;
    static int attr_done = 0;
    if (!attr_done) {
        cudaFuncSetAttribute(ffn1_kernel, cudaFuncAttributeMaxDynamicSharedMemorySize, FFN1_SMEM);
        cudaFuncSetAttribute(ffn2_kernel, cudaFuncAttributeMaxDynamicSharedMemorySize, FFN2_SMEM);
        cudaGetSymbolAddress(&accAddr, g_acc);
        attr_done = 1;
    }

    cudaMemsetAsync(d_out, 0, (size_t)out_size * sizeof(float));
    cudaMemsetAsync(accAddr, 0, sizeof(Acc));

    {
        dim3 gP(64, 64, 26), bP(32, 8);
        prep_router_kernel<<<gP, bP>>>(x, W1, W2, W3, pid, Wr, Wp);
    }
    prefix_losses_kernel<<<1, 1>>>(Wp, out, out_size - 3);

    dim3 gA(520, TH / 64, 1);
    ffn1_kernel<<<gA, 256, FFN1_SMEM>>>();

    dim3 gB(520, TD / 128, 1);
    ffn2_kernel<<<gB, 256, FFN2_SMEM>>>(out);
}

// round 14
// speedup vs baseline: 1.9072x; 1.0032x over previous
#include <cuda_runtime.h>
#include <cuda_fp16.h>
#include <math.h>
#include <stdint.h>

#define TB 8
#define TS 4096
#define TD 512
#define TH 2048
#define TE 8
#define TP 16
#define NTOK (TB*TS)          /* 32768 tokens */

/* ---------------- device state ---------------- */
struct Acc { int counts[TE]; double psum[TE]; double zsum; };
__device__ Acc    g_acc;                /* zeroed by host memset each launch */
__device__ int    g_base[TE];
__device__ int    g_tok[TE * NTOK];     /* packed: token*2 + rank */
__device__ float  g_gate[TE * NTOK];
__device__ int    g_tmap[544];          /* (e<<16) | mtile */
__device__ int    g_ntiles;
__device__ __half g_H[(size_t)2 * NTOK * TH];     /* fp16 H scratch */
__device__ __half g_xh[(size_t)NTOK * TD];        /* fp16 x */
__device__ __half g_w1h[(size_t)TE * TH * TD];    /* W1^T: [e][h][d] (K-major) */
__device__ __half g_w3h[(size_t)TE * TH * TD];
__device__ __half g_w2h[(size_t)TE * TD * TH];    /* W2^T: [e][d][h] */

/* ---------------- helpers ---------------- */
__device__ __forceinline__ void mma_f16(
    float& c0, float& c1, float& c2, float& c3,
    unsigned a0, unsigned a1, unsigned a2, unsigned a3,
    unsigned b0, unsigned b1)
{
    asm volatile(
        "mma.sync.aligned.m16n8k16.row.col.f32.f16.f16.f32 "
        "{%0,%1,%2,%3}, {%4,%5,%6,%7}, {%8,%9}, {%0,%1,%2,%3};"
        : "+f"(c0), "+f"(c1), "+f"(c2), "+f"(c3)
        : "r"(a0), "r"(a1), "r"(a2), "r"(a3), "r"(b0), "r"(b1));
}

#define LDSM4(r0, r1, r2, r3, addr) \
    asm volatile("ldmatrix.sync.aligned.m8n8.x4.shared.b16 {%0,%1,%2,%3}, [%4];" \
                 : "=r"(r0), "=r"(r1), "=r"(r2), "=r"(r3) : "r"(addr))

#define CP16(dst, src) \
    asm volatile("cp.async.cg.shared.global [%0], [%1], 16;" :: "r"(dst), "l"(src))
#define CP_COMMIT() asm volatile("cp.async.commit_group;")
#define CP_WAIT1()  asm volatile("cp.async.wait_group 1;")
#define CP_WAIT0()  asm volatile("cp.async.wait_group 0;")

__device__ __forceinline__ unsigned sptr(const void* p) {
    return (unsigned)__cvta_generic_to_shared(p);
}

/* rows of 64 data halfs (128B) padded to 144B: conflict-free LDSM and STS phases */
#define ROWB 144

#define STG1   36864
#define HDR1   1024
#define FFN1_SMEM (HDR1 + 3 * STG1)     /* 111616 B -> 2 CTAs/SM */
#define STG2   36864
#define HDR2   2048
#define FFN2_SMEM (HDR2 + 3 * STG2)     /* 112640 B -> 2 CTAs/SM */

/* ============ fused prep + router ============ */
__global__ __launch_bounds__(256) void prep_router_kernel(
    const float* __restrict__ x, const float* __restrict__ W1,
    const float* __restrict__ W2, const float* __restrict__ W3,
    const int* __restrict__ pid, const float* __restrict__ Wr,
    const float* __restrict__ Wp)
{
    const int z = blockIdx.z;
    const int tx = threadIdx.x, ty = threadIdx.y;
    const int tid = ty * 32 + tx;

    if (z == 0) {
        /* ---------------- router ---------------- */
        if (blockIdx.y >= 4) return;
        const int blk = blockIdx.y * 64 + blockIdx.x;   /* 0..255 */

        __shared__ float sWrT[TE * TD];
        __shared__ float sPsum[TE];
        __shared__ float sZsum;
        __shared__ int   sCnt[TE];
        __shared__ int   sGbase[TE];
        __shared__ unsigned char sE[256];
        __shared__ short sSlot[256];
        __shared__ float sG[256];

        for (int idx = tid; idx < TD * TE; idx += 256) {
            int d = idx >> 3, e = idx & 7;
            sWrT[e * TD + d] = Wr[idx];
        }
        if (tid < TE) { sPsum[tid] = 0.f; sCnt[tid] = 0; }
        if (tid == 0) sZsum = 0.f;
        __syncthreads();

        const int warp = tid >> 5, lane = tid & 31;
        const int tok0 = blk * 128 + warp * 16;

        float rpsum[TE];
        #pragma unroll
        for (int e = 0; e < TE; ++e) rpsum[e] = 0.f;
        float rzs = 0.f;

        for (int tt = 0; tt < 16; ++tt) {
            const int t = tok0 + tt;
            float acc[TE];
            #pragma unroll
            for (int e = 0; e < TE; ++e) acc[e] = 0.f;
            const float* xr = x + (size_t)t * TD;
            for (int i = lane; i < TD; i += 32) {
                float xv = xr[i];
                #pragma unroll
                for (int e = 0; e < TE; ++e)
                    acc[e] = fmaf(xv, sWrT[e * TD + i], acc[e]);
            }
            #pragma unroll
            for (int off = 16; off >= 1; off >>= 1) {
                #pragma unroll
                for (int e = 0; e < TE; ++e)
                    acc[e] += __shfl_down_sync(0xffffffffu, acc[e], off);
            }
            if (lane == 0) {
                const int b = t / TS;
                const int p = pid[b];
                float l[TE];
                float mx = -1e30f;
                #pragma unroll
                for (int e = 0; e < TE; ++e) {
                    l[e] = acc[e] + Wp[p * TE + e];
                    rzs += l[e] * l[e];
                    mx = fmaxf(mx, l[e]);
                }
                float s = 0.f, pr[TE];
                #pragma unroll
                for (int e = 0; e < TE; ++e) { pr[e] = expf(l[e] - mx); s += pr[e]; }
                const float inv = 1.f / s;
                #pragma unroll
                for (int e = 0; e < TE; ++e) rpsum[e] += pr[e] * inv;
                int i0 = 0;
                #pragma unroll
                for (int e = 1; e < TE; ++e) if (l[e] > l[i0]) i0 = e;
                int i1 = (i0 == 0) ? 1 : 0;
                #pragma unroll
                for (int e = 0; e < TE; ++e) if (e != i0 && l[e] > l[i1]) i1 = e;
                const float e1 = expf(l[i1] - l[i0]);
                const float g0 = 1.f / (1.f + e1);
                const float g1 = e1 * g0;
                const int s0 = atomicAdd(&sCnt[i0], 1);
                const int s1 = atomicAdd(&sCnt[i1], 1);
                const int loc = (warp * 16 + tt) * 2;
                sE[loc]     = (unsigned char)i0; sSlot[loc]     = (short)s0; sG[loc]     = g0;
                sE[loc + 1] = (unsigned char)i1; sSlot[loc + 1] = (short)s1; sG[loc + 1] = g1;
            }
        }
        if (lane == 0) {
            #pragma unroll
            for (int e = 0; e < TE; ++e) atomicAdd(&sPsum[e], rpsum[e]);
            atomicAdd(&sZsum, rzs);
        }
        __syncthreads();
        if (tid < TE) {
            sGbase[tid] = atomicAdd(&g_acc.counts[tid], sCnt[tid]);
            atomicAdd(&g_acc.psum[tid], (double)sPsum[tid]);
        }
        if (tid == 0) atomicAdd(&g_acc.zsum, (double)sZsum);
        __syncthreads();
        {
            const int e = sE[tid];
            const int pos = sGbase[e] + sSlot[tid];
            const int t = blk * 128 + (tid >> 1);
            g_tok[e * NTOK + pos]  = (t << 1) | (tid & 1);
            g_gate[e * NTOK + pos] = sG[tid];
        }
    } else if (z <= 24) {
        /* ---------------- weight transpose + fp16 round ---------------- */
        const int m = z - 1;
        const float* src; __half* dst; int R, C;
        if (m < 8)       { src = W1 + (size_t)m * TD * TH;        dst = g_w1h + (size_t)m * TH * TD;        R = TD; C = TH; }
        else if (m < 16) { src = W3 + (size_t)(m - 8) * TD * TH;  dst = g_w3h + (size_t)(m - 8) * TH * TD;  R = TD; C = TH; }
        else             { src = W2 + (size_t)(m - 16) * TH * TD; dst = g_w2h + (size_t)(m - 16) * TD * TH; R = TH; C = TD; }
        const int bx = blockIdx.x, by = blockIdx.y;
        if (bx * 32 >= C || by * 32 >= R) return;
        __shared__ float t[32][33];
        #pragma unroll
        for (int i = 0; i < 4; ++i)
            t[ty + 8 * i][tx] = src[(size_t)(by * 32 + ty + 8 * i) * C + bx * 32 + tx];
        __syncthreads();
        #pragma unroll
        for (int i = 0; i < 4; ++i)
            dst[(size_t)(bx * 32 + ty + 8 * i) * R + by * 32 + tx] = __float2half_rn(t[tx][ty + 8 * i]);
    } else {
        /* ---------------- x -> fp16 ---------------- */
        const size_t nb = (size_t)blockIdx.y * 64 + blockIdx.x;   /* 0..4095 */
        const size_t NX8 = (size_t)NTOK * TD / 8;
        const size_t stride = (size_t)4096 * 256;
        const float4* x4 = (const float4*)x;
        for (size_t i = nb * 256 + tid; i < NX8; i += stride) {
            float4 v0 = x4[2 * i], v1 = x4[2 * i + 1];
            __half2* dst = (__half2*)(g_xh + i * 8);
            dst[0] = __floats2half2_rn(v0.x, v0.y);
            dst[1] = __floats2half2_rn(v0.z, v0.w);
            dst[2] = __floats2half2_rn(v1.x, v1.y);
            dst[3] = __floats2half2_rn(v1.z, v1.w);
        }
    }
}

/* ---------------- prefix + tile map + losses ---------------- */
__global__ void prefix_losses_kernel(const float* __restrict__ Wp,
                                     float* __restrict__ out, int sbase)
{
    if (threadIdx.x != 0) return;
    int s = 0, idx = 0;
    for (int e = 0; e < TE; ++e) {
        g_base[e] = s;
        const int cnt = g_acc.counts[e];
        s += cnt;
        const int mt = (cnt + 127) >> 7;
        for (int m = 0; m < mt; ++m) g_tmap[idx++] = (e << 16) | m;
    }
    g_ntiles = idx;

    const double z = g_acc.zsum / (double)((size_t)NTOK * TE) * 0.001;
    double sb = 0.0;
    for (int e = 0; e < TE; ++e) {
        const double m = g_acc.psum[e] / (double)NTOK;
        const double d = m - 1.0 / TE;
        sb += d * d;
    }
    sb /= TE;
    float Pn[TP][TE];
    for (int p = 0; p < TP; ++p) {
        float mx = -1e30f;
        for (int e = 0; e < TE; ++e) mx = fmaxf(mx, Wp[p * TE + e]);
        float ss = 0.f;
        for (int e = 0; e < TE; ++e) { Pn[p][e] = expf(Wp[p * TE + e] - mx); ss += Pn[p][e]; }
        const float inv = 1.f / ss;
        for (int e = 0; e < TE; ++e) Pn[p][e] *= inv;
    }
    double acc = 0.0;
    for (int p = 0; p < TP; ++p)
        for (int q = 0; q < TP; ++q)
            if (p != q) {
                float d = 0.f;
                for (int e = 0; e < TE; ++e) d += Pn[p][e] * Pn[q][e];
                acc += (double)d;
            }
    const double spec = acc / (double)(TP * TP) * 0.1;
    out[sbase + 0] = (float)z;
    out[sbase + 1] = (float)sb;
    out[sbase + 2] = (float)spec;
}

/* ================= FFN stage 1 (fp16 mma + ldmatrix, BK=64, 3-stage) ================= */
__global__ __launch_bounds__(256, 2) void ffn1_kernel()
{
    if (blockIdx.x >= g_ntiles) return;
    const int mp  = g_tmap[blockIdx.x];
    const int e   = mp >> 16;
    const int m0  = (mp & 0xffff) << 7;
    const int cnt = g_acc.counts[e];
    const int n0   = blockIdx.y * 64;
    const int base = g_base[e];

    extern __shared__ char smc[];
    int* stok = (int*)smc;

    const int tid = threadIdx.x;
    if (tid < 128) {
        const int r = m0 + tid;
        stok[tid] = ((r < cnt) ? g_tok[e * NTOK + r] : g_tok[e * NTOK]) >> 1;
    }
    __syncthreads();

    const __half* W1e = g_w1h + (size_t)e * TH * TD;
    const __half* W3e = g_w3h + (size_t)e * TH * TD;

    const int warp = tid >> 5, lane = tid & 31;
    const int warp_m = warp & 3;     /* *32 */
    const int warp_n = warp >> 2;    /* *32 */
    const int lg = lane >> 2, lt = lane & 3;

    const uint32_t a_off = (uint32_t)(warp_m * 32 + (lane & 15)) * ROWB + (lane >> 4) * 16;
    const uint32_t b_row = (uint32_t)(warp_n * 32 + (lane & 7) + ((lane >> 4) << 3));
    const uint32_t b_off = b_row * ROWB + ((lane >> 3) & 1) * 16;

    auto issue = [&](int it, int stg) {
        const int k0 = it * 64;
        char* S = smc + HDR1 + stg * STG1;
        #pragma unroll
        for (int j = 0; j < 4; ++j) {
            const int q = tid + 256 * j;
            const int row = q >> 3, c = q & 7;
            CP16(sptr(S + row * ROWB + c * 16),
                 g_xh + (size_t)stok[row] * TD + k0 + c * 8);
        }
        #pragma unroll
        for (int j = 0; j < 2; ++j) {
            const int q = tid + 256 * j;
            const int row = q >> 3, c = q & 7;
            CP16(sptr(S + 18432 + row * ROWB + c * 16),
                 W1e + (size_t)(n0 + row) * TD + k0 + c * 8);
            CP16(sptr(S + 27648 + row * ROWB + c * 16),
                 W3e + (size_t)(n0 + row) * TD + k0 + c * 8);
        }
        CP_COMMIT();
    };

    float acc1[2][4][4], acc3[2][4][4];
    #pragma unroll
    for (int i = 0; i < 2; ++i)
        #pragma unroll
        for (int j = 0; j < 4; ++j)
            #pragma unroll
            for (int k = 0; k < 4; ++k) { acc1[i][j][k] = 0.f; acc3[i][j][k] = 0.f; }

    issue(0, 0);
    issue(1, 1);
    int sa = 0, sc = 2;
    const int NIT = TD / 64;   /* 8 */

    #pragma unroll 1
    for (int it = 0; it < NIT; ++it) {
        if (it < NIT - 1) { CP_WAIT1(); } else { CP_WAIT0(); }
        __syncthreads();

        const uint32_t Sb = sptr(smc + HDR1 + sa * STG1);
        const uint32_t Aa  = Sb + a_off;
        const uint32_t B1a = Sb + 18432 + b_off;
        const uint32_t B3a = Sb + 27648 + b_off;

        #pragma unroll
        for (int ks = 0; ks < 4; ++ks) {
            const uint32_t kb = ks * 32;
            unsigned a[2][4], b1f[4][2], b3f[4][2];
            LDSM4(a[0][0], a[0][1], a[0][2], a[0][3], Aa + kb);
            LDSM4(a[1][0], a[1][1], a[1][2], a[1][3], Aa + 16 * ROWB + kb);
            LDSM4(b1f[0][0], b1f[0][1], b1f[1][0], b1f[1][1], B1a + kb);
            LDSM4(b1f[2][0], b1f[2][1], b1f[3][0], b1f[3][1], B1a + 16 * ROWB + kb);
            LDSM4(b3f[0][0], b3f[0][1], b3f[1][0], b3f[1][1], B3a + kb);
            LDSM4(b3f[2][0], b3f[2][1], b3f[3][0], b3f[3][1], B3a + 16 * ROWB + kb);
            #pragma unroll
            for (int mi = 0; mi < 2; ++mi)
                #pragma unroll
                for (int ni = 0; ni < 4; ++ni) {
                    mma_f16(acc1[mi][ni][0], acc1[mi][ni][1], acc1[mi][ni][2], acc1[mi][ni][3],
                            a[mi][0], a[mi][1], a[mi][2], a[mi][3], b1f[ni][0], b1f[ni][1]);
                    mma_f16(acc3[mi][ni][0], acc3[mi][ni][1], acc3[mi][ni][2], acc3[mi][ni][3],
                            a[mi][0], a[mi][1], a[mi][2], a[mi][3], b3f[ni][0], b3f[ni][1]);
                }
        }

        if (it + 2 < NIT) issue(it + 2, sc);
        if (++sa == 3) sa = 0;
        if (++sc == 3) sc = 0;
    }

    /* epilogue: h = (X@W1) * silu(X@W3), store fp16 */
    #pragma unroll
    for (int mi = 0; mi < 2; ++mi) {
        #pragma unroll
        for (int half = 0; half < 2; ++half) {
            const int rl = warp_m * 32 + mi * 16 + half * 8 + lg;
            const int r  = m0 + rl;
            if (r < cnt) {
                __half* hrow = g_H + (size_t)(base + r) * TH + n0 + warp_n * 32;
                #pragma unroll
                for (int ni = 0; ni < 4; ++ni) {
                    const float g1v = acc1[mi][ni][half * 2 + 0];
                    const float g1w = acc1[mi][ni][half * 2 + 1];
                    const float g3v = acc3[mi][ni][half * 2 + 0];
                    const float g3w = acc3[mi][ni][half * 2 + 1];
                    const float hx = g1v * (g3v / (1.f + expf(-g3v)));
                    const float hy = g1w * (g3w / (1.f + expf(-g3w)));
                    *(__half2*)(hrow + ni * 8 + 2 * lt) = __floats2half2_rn(hx, hy);
                }
            }
        }
    }
}

/* ================= FFN stage 2 (fp16 mma + ldmatrix, BK=64, 3-stage, atomic epilogue) =================
   Grid: x = n-tile (4), y = m-tile (520). Consecutive blocks share the same m-tile's H slice
   so the 4 n-tiles are co-resident and H is fetched from DRAM once (L2 reuse). */
__global__ __launch_bounds__(256, 2) void ffn2_kernel(float* __restrict__ y)
{
    if (blockIdx.y >= g_ntiles) return;
    const int mp  = g_tmap[blockIdx.y];
    const int e   = mp >> 16;
    const int m0  = (mp & 0xffff) << 7;
    const int cnt = g_acc.counts[e];
    const int n0   = blockIdx.x * 128;
    const int base = g_base[e];

    extern __shared__ char smc[];
    int*   sslot = (int*)smc;            /* 128 */
    int*   stokT = (int*)(smc + 512);    /* 128 */
    float* sgate = (float*)(smc + 1024); /* 128 */

    const int tid = threadIdx.x;
    if (tid < 128) {
        const int r = m0 + tid;
        const int rc = (r < cnt) ? r : (cnt - 1);
        sslot[tid] = base + rc;
        stokT[tid] = g_tok[e * NTOK + rc] >> 1;
        sgate[tid] = (r < cnt) ? g_gate[e * NTOK + r] : 0.f;
    }
    __syncthreads();

    const __half* W2e = g_w2h + (size_t)e * TD * TH;

    const int warp = tid >> 5, lane = tid & 31;
    const int warp_m = warp >> 2;    /* *64 */
    const int warp_n = warp & 3;     /* *32 */
    const int lg = lane >> 2, lt = lane & 3;

    const uint32_t a_off = (uint32_t)(warp_m * 64 + (lane & 15)) * ROWB + (lane >> 4) * 16;
    const uint32_t b_row = (uint32_t)(warp_n * 32 + (lane & 7) + ((lane >> 4) << 3));
    const uint32_t b_off = b_row * ROWB + ((lane >> 3) & 1) * 16;

    auto issue = [&](int it, int stg) {
        const int k0 = it * 64;
        char* S = smc + HDR2 + stg * STG2;
        #pragma unroll
        for (int j = 0; j < 4; ++j) {
            const int q = tid + 256 * j;
            const int row = q >> 3, c = q & 7;
            CP16(sptr(S + row * ROWB + c * 16),
                 g_H + (size_t)sslot[row] * TH + k0 + c * 8);
        }
        #pragma unroll
        for (int j = 0; j < 4; ++j) {
            const int q = tid + 256 * j;
            const int row = q >> 3, c = q & 7;
            CP16(sptr(S + 18432 + row * ROWB + c * 16),
                 W2e + (size_t)(n0 + row) * TH + k0 + c * 8);
        }
        CP_COMMIT();
    };

    float acc[4][4][4];
    #pragma unroll
    for (int i = 0; i < 4; ++i)
        #pragma unroll
        for (int j = 0; j < 4; ++j)
            #pragma unroll
            for (int k = 0; k < 4; ++k) acc[i][j][k] = 0.f;

    issue(0, 0);
    issue(1, 1);
    int sa = 0, sc = 2;
    const int NIT = TH / 64;   /* 32 */

    #pragma unroll 1
    for (int it = 0; it < NIT; ++it) {
        if (it < NIT - 1) { CP_WAIT1(); } else { CP_WAIT0(); }
        __syncthreads();

        const uint32_t Sb = sptr(smc + HDR2 + sa * STG2);
        const uint32_t Aa = Sb + a_off;
        const uint32_t Ba = Sb + 18432 + b_off;

        #pragma unroll
        for (int ks = 0; ks < 4; ++ks) {
            const uint32_t kb = ks * 32;
            unsigned a[4][4], b[4][2];
            LDSM4(a[0][0], a[0][1], a[0][2], a[0][3], Aa + kb);
            LDSM4(a[1][0], a[1][1], a[1][2], a[1][3], Aa + 16 * ROWB + kb);
            LDSM4(a[2][0], a[2][1], a[2][2], a[2][3], Aa + 32 * ROWB + kb);
            LDSM4(a[3][0], a[3][1], a[3][2], a[3][3], Aa + 48 * ROWB + kb);
            LDSM4(b[0][0], b[0][1], b[1][0], b[1][1], Ba + kb);
            LDSM4(b[2][0], b[2][1], b[3][0], b[3][1], Ba + 16 * ROWB + kb);
            #pragma unroll
            for (int mi = 0; mi < 4; ++mi)
                #pragma unroll
                for (int ni = 0; ni < 4; ++ni)
                    mma_f16(acc[mi][ni][0], acc[mi][ni][1], acc[mi][ni][2], acc[mi][ni][3],
                            a[mi][0], a[mi][1], a[mi][2], a[mi][3], b[ni][0], b[ni][1]);
        }

        if (it + 2 < NIT) issue(it + 2, sc);
        if (++sa == 3) sa = 0;
        if (++sc == 3) sc = 0;
    }

    #pragma unroll
    for (int mi = 0; mi < 4; ++mi) {
        #pragma unroll
        for (int half = 0; half < 2; ++half) {
            const int rl = warp_m * 64 + mi * 16 + half * 8 + lg;
            if (m0 + rl < cnt) {
                const int t = stokT[rl];
                const float g = sgate[rl];
                float* yr = y + (size_t)t * TD + n0 + warp_n * 32;
                #pragma unroll
                for (int ni = 0; ni < 4; ++ni) {
                    const int col = ni * 8 + 2 * lt;
                    atomicAdd(&yr[col],     g * acc[mi][ni][half * 2 + 0]);
                    atomicAdd(&yr[col + 1], g * acc[mi][ni][half * 2 + 1]);
                }
            }
        }
    }
}

/* ---------------- launch ---------------- */
extern "C" void kernel_launch(void* const* d_in, const int* in_sizes, int n_in,
                              void* d_out, int out_size)
{
    const float* x  = (const float*)d_in[0];
    const int*   pid= (const int*)  d_in[1];
    const float* Wr = (const float*)d_in[2];
    const float* Wp = (const float*)d_in[3];
    const float* W1 = (const float*)d_in[4];
    const float* W2 = (const float*)d_in[5];
    const float* W3 = (const float*)d_in[6];
    float* out = (float*)d_out;

    static void* accAddr = nullptr;
    static int attr_done = 0;
    if (!attr_done) {
        cudaFuncSetAttribute(ffn1_kernel, cudaFuncAttributeMaxDynamicSharedMemorySize, FFN1_SMEM);
        cudaFuncSetAttribute(ffn2_kernel, cudaFuncAttributeMaxDynamicSharedMemorySize, FFN2_SMEM);
        cudaGetSymbolAddress(&accAddr, g_acc);
        attr_done = 1;
    }

    cudaMemsetAsync(d_out, 0, (size_t)out_size * sizeof(float));
    cudaMemsetAsync(accAddr, 0, sizeof(Acc));

    {
        dim3 gP(64, 64, 26), bP(32, 8);
        prep_router_kernel<<<gP, bP>>>(x, W1, W2, W3, pid, Wr, Wp);
    }
    prefix_losses_kernel<<<1, 1>>>(Wp, out, out_size - 3);

    dim3 gA(520, TH / 64, 1);
    ffn1_kernel<<<gA, 256, FFN1_SMEM>>>();

    dim3 gB(TD / 128, 520, 1);
    ffn2_kernel<<<gB, 256, FFN2_SMEM>>>(out);
}